// round 4
// baseline (speedup 1.0000x reference)
#include <cuda_runtime.h>
#include <cuda_bf16.h>
#include <cuda_fp16.h>
#include <math.h>

// Problem constants (PCVRSymbiosis): B=4, S=1024, L=1024, D=1024, H=16, HD=64, HIDDEN=4096
#define Bc 4
#define Sc 1024
#define Lc 1024
#define Dc 1024
#define Hc 16
#define HDc 64
#define HIDc 4096
#define BSc (Bc*Sc)
#define BLc (Bc*Lc)

// ---------------- scratch (static device globals; no runtime alloc) ----------------
__device__ float g_x    [BSc*Dc];
__device__ float g_qkv  [BSc*3*Dc];
__device__ float g_scores[(size_t)Bc*Hc*Sc*Sc];
__device__ float g_ctx  [BSc*Dc];
__device__ float g_t2   [BSc*Dc];
__device__ float g_qn   [BSc*Dc];
__device__ float g_sn   [BLc*Dc];
__device__ float g_cq   [BSc*Dc];
__device__ float g_ckv  [BLc*2*Dc];
__device__ float g_upd  [BSc*Dc];
__device__ float g_gacc [BSc*Dc];
__device__ float g_t3   [BSc*Dc];
__device__ float g_gu   [(size_t)BSc*2*HIDc];
__device__ float g_act  [(size_t)BSc*HIDc];
__device__ float g_ss   [Bc*2*Dc];
__device__ int   g_valid [BSc];
__device__ int   g_svalid[BLc];
__device__ float g_vrow  [Bc];
__device__ int   g_layout[2];

// ---------------- reductions ----------------
__device__ __forceinline__ float warp_sum(float v){
    #pragma unroll
    for (int o=16;o>0;o>>=1) v += __shfl_xor_sync(0xffffffffu, v, o);
    return v;
}
__device__ __forceinline__ float warp_max(float v){
    #pragma unroll
    for (int o=16;o>0;o>>=1) v = fmaxf(v, __shfl_xor_sync(0xffffffffu, v, o));
    return v;
}
__device__ float block_sum(float v){
    __shared__ float red[33];
    __syncthreads();
    int lane = threadIdx.x & 31, wid = threadIdx.x >> 5;
    v = warp_sum(v);
    if (lane==0) red[wid] = v;
    __syncthreads();
    int nw = blockDim.x >> 5;
    float r = (threadIdx.x < nw) ? red[threadIdx.x] : 0.f;
    if (wid==0){ r = warp_sum(r); if (lane==0) red[32] = r; }
    __syncthreads();
    return red[32];
}
__device__ float block_max(float v){
    __shared__ float red[33];
    __syncthreads();
    int lane = threadIdx.x & 31, wid = threadIdx.x >> 5;
    v = warp_max(v);
    if (lane==0) red[wid] = v;
    __syncthreads();
    int nw = blockDim.x >> 5;
    float r = (threadIdx.x < nw) ? red[threadIdx.x] : -3.4e38f;
    if (wid==0){ r = warp_max(r); if (lane==0) red[32] = r; }
    __syncthreads();
    return red[32];
}

// ---------------- mask layout detection + decode ----------------
__global__ void detect_mask_layout(const unsigned char* __restrict__ p, int n, int slot){
    int i = blockIdx.x*blockDim.x + threadIdx.x;
    if (i >= n) return;
    unsigned char v = p[i];
    if (v != 0 && v != 1) atomicOr(&g_layout[slot], 2);
    else if (v == 1 && (i & 3) != 0) atomicOr(&g_layout[slot], 1);
}
__global__ void decode_mask(const void* __restrict__ p, int cols, int slot,
                            int* __restrict__ valid, float* __restrict__ vrow){
    int b = blockIdx.x;
    int layout = g_layout[slot];
    int mode = (layout & 2) ? 2 : ((layout & 1) ? 1 : 0);
    __shared__ int s_anyzero;
    if (threadIdx.x==0) s_anyzero = 0;
    __syncthreads();
    int local_any = 0;
    for (int j = threadIdx.x; j < cols; j += blockDim.x){
        long idx = (long)b*cols + j;
        int m;
        if (mode==1)      m = ((const unsigned char*)p)[idx] != 0;
        else if (mode==2) m = ((const float*)p)[idx] != 0.f;
        else              m = ((const int*)p)[idx] != 0;
        valid[idx] = m;
        if (!m) local_any = 1;
    }
    if (local_any) atomicOr(&s_anyzero, 1);
    __syncthreads();
    int anyz = s_anyzero;
    for (int j = threadIdx.x; j < cols; j += blockDim.x){
        long idx = (long)b*cols + j;
        valid[idx] = anyz ? (1 - valid[idx]) : 1;
    }
    if (vrow && threadIdx.x==0) vrow[b] = anyz ? 1.f : 0.f;
}

// ---------------- mma helpers ----------------
__device__ __forceinline__ unsigned f2tf(float x){
    unsigned u; asm("cvt.rna.tf32.f32 %0, %1;" : "=r"(u) : "f"(x)); return u;
}
__device__ __forceinline__ void mma_tf32(float* c, const unsigned* a, const unsigned* b){
    asm volatile("mma.sync.aligned.m16n8k8.row.col.f32.tf32.tf32.f32 "
        "{%0,%1,%2,%3}, {%4,%5,%6,%7}, {%8,%9}, {%0,%1,%2,%3};"
        : "+f"(c[0]),"+f"(c[1]),"+f"(c[2]),"+f"(c[3])
        : "r"(a[0]),"r"(a[1]),"r"(a[2]),"r"(a[3]), "r"(b[0]),"r"(b[1]));
}
__device__ __forceinline__ void mma_f16(float* c, const unsigned* a, const unsigned* b){
    asm volatile("mma.sync.aligned.m16n8k16.row.col.f32.f16.f16.f32 "
        "{%0,%1,%2,%3}, {%4,%5,%6,%7}, {%8,%9}, {%0,%1,%2,%3};"
        : "+f"(c[0]),"+f"(c[1]),"+f"(c[2]),"+f"(c[3])
        : "r"(a[0]),"r"(a[1]),"r"(a[2]),"r"(a[3]), "r"(b[0]),"r"(b[1]));
}
__device__ __forceinline__ unsigned pack_h2(float x, float y){
    __half2 h = __floats2half2_rn(x, y);
    return *(unsigned*)&h;
}

// ---------------- fp16 tensor-core NT GEMM: C = alpha * A @ B^T + epilogue ----------------
// A [M,K] row-major, B [N,K] row-major. M%128==0, N%128==0, K%16==0 required.
template<int NWM,int NWN>
__global__ __launch_bounds__(NWM*NWN*32)
void gemm_h16(const float* __restrict__ A, const float* __restrict__ B,
              float* __restrict__ C,
              int M,int N,int K,int lda,int ldb,int ldc,
              int batH,
              long long aO,long long aI,long long bO,long long bI,
              long long cO,long long cI,
              float alpha,
              const float* __restrict__ bias,
              const float* __restrict__ residual,int ldres,
              const float* __restrict__ rowscale,int rsDiv,
              int accum)
{
    constexpr int BM = 128, BN = 128, BK = 16;
    constexpr int NT = NWM*NWN*32;         // 256
    constexpr int WM = BM/NWM, WN = BN/NWN;
    constexpr int MI = WM/16, NI = WN/8;
    constexpr int LDS_H = BK + 8;          // 24 halves per row -> conflict-free frag loads

    __shared__ __align__(16) __half As[BM*LDS_H];
    __shared__ __align__(16) __half Bs[BN*LDS_H];

    const int tid = threadIdx.x, lane = tid & 31, warp = tid >> 5;
    const int z = blockIdx.z;
    const float* Ab = A + (long long)(z/batH)*aO + (long long)(z%batH)*aI;
    const float* Bb = B + (long long)(z/batH)*bO + (long long)(z%batH)*bI;
    float*       Cb = C + (long long)(z/batH)*cO + (long long)(z%batH)*cI;

    const int m0 = blockIdx.y*BM, n0 = blockIdx.x*BN;
    const int wm0 = (warp/NWN)*WM, wn0 = (warp%NWN)*WN;
    const int qr = lane >> 2, qc = lane & 3;

    float acc[MI][NI][4];
    #pragma unroll
    for (int i=0;i<MI;i++)
        #pragma unroll
        for (int j=0;j<NI;j++)
            #pragma unroll
            for (int r=0;r<4;r++) acc[i][j][r]=0.f;

    constexpr int AF4 = (BM*BK)/(4*NT);    // 2
    constexpr int BF4 = (BN*BK)/(4*NT);    // 2
    float4 ra[AF4], rb[BF4];

    const int nk = K/BK;
    const int sm = tid>>2, skq = tid&3;    // staging coords: row = tid/4, k-quad = tid%4

    // prologue loads
    #pragma unroll
    for (int it=0; it<AF4; ++it)
        ra[it] = *(const float4*)(Ab + (long long)(m0+sm+it*(NT/4))*lda + skq*4);
    #pragma unroll
    for (int it=0; it<BF4; ++it)
        rb[it] = *(const float4*)(Bb + (long long)(n0+sm+it*(NT/4))*ldb + skq*4);

    for (int kt=0; kt<nk; ++kt){
        __syncthreads();
        #pragma unroll
        for (int it=0; it<AF4; ++it){
            int m = sm + it*(NT/4);
            *(uint2*)&As[m*LDS_H + skq*4] =
                make_uint2(pack_h2(ra[it].x, ra[it].y), pack_h2(ra[it].z, ra[it].w));
        }
        #pragma unroll
        for (int it=0; it<BF4; ++it){
            int n = sm + it*(NT/4);
            *(uint2*)&Bs[n*LDS_H + skq*4] =
                make_uint2(pack_h2(rb[it].x, rb[it].y), pack_h2(rb[it].z, rb[it].w));
        }
        __syncthreads();
        if (kt+1 < nk){
            int k0 = (kt+1)*BK;
            #pragma unroll
            for (int it=0; it<AF4; ++it)
                ra[it] = *(const float4*)(Ab + (long long)(m0+sm+it*(NT/4))*lda + k0 + skq*4);
            #pragma unroll
            for (int it=0; it<BF4; ++it)
                rb[it] = *(const float4*)(Bb + (long long)(n0+sm+it*(NT/4))*ldb + k0 + skq*4);
        }
        // one m16n8k16 step covers the whole BK=16 tile
        unsigned af[MI][4], bf[NI][2];
        #pragma unroll
        for (int mi=0; mi<MI; ++mi){
            int mr = wm0 + mi*16 + qr;
            af[mi][0] = *(const unsigned*)&As[ mr   *LDS_H + 2*qc    ];
            af[mi][1] = *(const unsigned*)&As[(mr+8)*LDS_H + 2*qc    ];
            af[mi][2] = *(const unsigned*)&As[ mr   *LDS_H + 2*qc + 8];
            af[mi][3] = *(const unsigned*)&As[(mr+8)*LDS_H + 2*qc + 8];
        }
        #pragma unroll
        for (int ni=0; ni<NI; ++ni){
            int nc = wn0 + ni*8 + qr;
            bf[ni][0] = *(const unsigned*)&Bs[nc*LDS_H + 2*qc    ];
            bf[ni][1] = *(const unsigned*)&Bs[nc*LDS_H + 2*qc + 8];
        }
        #pragma unroll
        for (int mi=0; mi<MI; ++mi)
            #pragma unroll
            for (int ni=0; ni<NI; ++ni)
                mma_f16(acc[mi][ni], af[mi], bf[ni]);
    }

    // epilogue
    #pragma unroll
    for (int mi=0; mi<MI; ++mi){
        #pragma unroll
        for (int half=0; half<2; ++half){
            int gm = m0 + wm0 + mi*16 + qr + half*8;
            float rs = rowscale ? rowscale[gm/rsDiv] : 1.f;
            #pragma unroll
            for (int ni=0; ni<NI; ++ni){
                int gn = n0 + wn0 + ni*8 + qc*2;
                float v0 = alpha*acc[mi][ni][half*2+0];
                float v1 = alpha*acc[mi][ni][half*2+1];
                if (bias){ v0 += bias[gn]; v1 += bias[gn+1]; }
                v0 *= rs; v1 *= rs;
                if (residual){
                    float2 r = *(const float2*)(residual + (long long)gm*ldres + gn);
                    v0 += r.x; v1 += r.y;
                }
                long long off = (long long)gm*ldc + gn;
                if (accum){ float2 c0 = *(float2*)(Cb+off); v0 += c0.x; v1 += c0.y; }
                *(float2*)(Cb+off) = make_float2(v0, v1);
            }
        }
    }
}

// ---------------- tf32 NN GEMM (PV only): C = A @ B ----------------
template<int BM,int BN,int NWM,int NWN>
__global__ __launch_bounds__(NWM*NWN*32)
void gemm_tc_nn(const float* __restrict__ A, const float* __restrict__ B,
                float* __restrict__ C,
                int M,int N,int K,int lda,int ldb,int ldc,
                int batH,
                long long aO,long long aI,long long bO,long long bI,
                long long cO,long long cI)
{
    constexpr int BK = 16;
    constexpr int NT = NWM*NWN*32;
    constexpr int WM = BM/NWM, WN = BN/NWN;
    constexpr int MI = WM/16, NI = WN/8;
    constexpr int LDA_S = BK+4;
    constexpr int LDB_S = BN+8;

    __shared__ unsigned As[BM*LDA_S];
    __shared__ unsigned Bs[BK*LDB_S];

    const int tid = threadIdx.x, lane = tid & 31, warp = tid >> 5;
    const int z = blockIdx.z;
    const float* Ab = A + (long long)(z/batH)*aO + (long long)(z%batH)*aI;
    const float* Bb = B + (long long)(z/batH)*bO + (long long)(z%batH)*bI;
    float*       Cb = C + (long long)(z/batH)*cO + (long long)(z%batH)*cI;

    const int m0 = blockIdx.y*BM, n0 = blockIdx.x*BN;
    const int wm0 = (warp/NWN)*WM, wn0 = (warp%NWN)*WN;
    const int qr = lane >> 2, qc = lane & 3;

    float acc[MI][NI][4];
    #pragma unroll
    for (int i=0;i<MI;i++)
        #pragma unroll
        for (int j=0;j<NI;j++)
            #pragma unroll
            for (int r=0;r<4;r++) acc[i][j][r]=0.f;

    constexpr int AF4 = (BM*BK)/(4*NT);
    constexpr int BF4 = (BN*BK)/(4*NT);
    float4 ra[AF4], rb[BF4];

    const int nk = K/BK;

    #pragma unroll
    for (int it=0; it<AF4; ++it){
        int idx = tid + it*NT; int m = idx>>2, kq = idx&3;
        ra[it] = *(const float4*)(Ab + (long long)(m0+m)*lda + kq*4);
    }
    #pragma unroll
    for (int it=0; it<BF4; ++it){
        int idx = tid + it*NT; int kl = idx/(BN/4), nq = idx%(BN/4);
        rb[it] = *(const float4*)(Bb + (long long)kl*ldb + n0 + nq*4);
    }

    for (int kt=0; kt<nk; ++kt){
        __syncthreads();
        #pragma unroll
        for (int it=0; it<AF4; ++it){
            int idx = tid + it*NT; int m = idx>>2, kq = idx&3;
            unsigned* d = &As[m*LDA_S + kq*4];
            d[0]=f2tf(ra[it].x); d[1]=f2tf(ra[it].y); d[2]=f2tf(ra[it].z); d[3]=f2tf(ra[it].w);
        }
        #pragma unroll
        for (int it=0; it<BF4; ++it){
            int idx = tid + it*NT; int kl = idx/(BN/4), nq = idx%(BN/4);
            unsigned* d = &Bs[kl*LDB_S + nq*4];
            d[0]=f2tf(rb[it].x); d[1]=f2tf(rb[it].y); d[2]=f2tf(rb[it].z); d[3]=f2tf(rb[it].w);
        }
        __syncthreads();
        if (kt+1 < nk){
            int k0 = (kt+1)*BK;
            #pragma unroll
            for (int it=0; it<AF4; ++it){
                int idx = tid + it*NT; int m = idx>>2, kq = idx&3;
                ra[it] = *(const float4*)(Ab + (long long)(m0+m)*lda + k0 + kq*4);
            }
            #pragma unroll
            for (int it=0; it<BF4; ++it){
                int idx = tid + it*NT; int kl = idx/(BN/4), nq = idx%(BN/4);
                rb[it] = *(const float4*)(Bb + (long long)(k0+kl)*ldb + n0 + nq*4);
            }
        }
        #pragma unroll
        for (int ks=0; ks<BK; ks+=8){
            unsigned af[MI][4], bf[NI][2];
            #pragma unroll
            for (int mi=0; mi<MI; ++mi){
                int mr = wm0 + mi*16 + qr;
                af[mi][0] = As[ mr   *LDA_S + ks+qc  ];
                af[mi][1] = As[(mr+8)*LDA_S + ks+qc  ];
                af[mi][2] = As[ mr   *LDA_S + ks+qc+4];
                af[mi][3] = As[(mr+8)*LDA_S + ks+qc+4];
            }
            #pragma unroll
            for (int ni=0; ni<NI; ++ni){
                int nc = wn0 + ni*8 + qr;
                bf[ni][0] = Bs[(ks+qc  )*LDB_S + nc];
                bf[ni][1] = Bs[(ks+qc+4)*LDB_S + nc];
            }
            #pragma unroll
            for (int mi=0; mi<MI; ++mi)
                #pragma unroll
                for (int ni=0; ni<NI; ++ni)
                    mma_tf32(acc[mi][ni], af[mi], bf[ni]);
        }
    }

    #pragma unroll
    for (int mi=0; mi<MI; ++mi){
        #pragma unroll
        for (int half=0; half<2; ++half){
            int gm = m0 + wm0 + mi*16 + qr + half*8;
            #pragma unroll
            for (int ni=0; ni<NI; ++ni){
                int gn = n0 + wn0 + ni*8 + qc*2;
                long long off = (long long)gm*ldc + gn;
                *(float2*)(Cb+off) = make_float2(acc[mi][ni][half*2+0], acc[mi][ni][half*2+1]);
            }
        }
    }
}

// ---------------- small fused kernels ----------------
__global__ void film_gemv(const float* __restrict__ mod, const float* __restrict__ W,
                          const float* __restrict__ bias, float* __restrict__ out,
                          int Bn, int N2, int K){
    int warp = (blockIdx.x*blockDim.x + threadIdx.x) >> 5;
    int lane = threadIdx.x & 31;
    if (warp >= Bn*N2) return;
    int b = warp / N2, n = warp % N2;
    const float* a = mod + (long)b*K;
    const float* w = W   + (long)n*K;
    float acc=0.f;
    for (int k=lane; k<K; k+=32) acc = fmaf(a[k], w[k], acc);
    acc = warp_sum(acc);
    if (lane==0) out[warp] = acc + bias[n];
}

__global__ void rmsnorm_kernel(const float* __restrict__ x, const float* __restrict__ w,
                               float* __restrict__ y, int Dd,
                               const float* __restrict__ filmss, int S){
    long row = blockIdx.x;
    const float* xr = x + row*Dd;
    float ss = 0.f;
    for (int j = threadIdx.x; j < Dd; j += blockDim.x){ float v = xr[j]; ss = fmaf(v,v,ss); }
    ss = block_sum(ss);
    float r = rsqrtf(ss/(float)Dd + 1e-6f);
    if (filmss){
        int b = (int)(row / S);
        const float* sc = filmss + (long)b*2*Dd;
        for (int j = threadIdx.x; j < Dd; j += blockDim.x){
            float v = xr[j]*r*w[j];
            y[row*Dd + j] = v*(1.f + 0.1f*tanhf(sc[j])) + sc[Dd + j];
        }
    } else {
        for (int j = threadIdx.x; j < Dd; j += blockDim.x)
            y[row*Dd + j] = xr[j]*r*w[j];
    }
}

__global__ void rope_kernel(float* __restrict__ qkv){
    long idx = (long)blockIdx.x*blockDim.x + threadIdx.x;
    const long total = (long)BSc * Hc * (HDc/2);
    if (idx >= total) return;
    int i = idx % (HDc/2);
    int h = (idx / (HDc/2)) % Hc;
    long row = idx / ((HDc/2)*Hc);
    int s = (int)(row % Sc);
    float freq = expf(-logf(10000.f) * (float)(2*i) / (float)HDc);
    float ang = (float)s * freq;
    float c = cosf(ang), sn = sinf(ang);
    float* qb = qkv + row*(3*Dc) + h*HDc;
    float e = qb[2*i], o = qb[2*i+1];
    qb[2*i]   = e*c - o*sn;
    qb[2*i+1] = e*sn + o*c;
    float* kb = qb + Dc;
    e = kb[2*i]; o = kb[2*i+1];
    kb[2*i]   = e*c - o*sn;
    kb[2*i+1] = e*sn + o*c;
}

__global__ void softmax_mask_kernel(float* __restrict__ scores, const int* __restrict__ valid,
                                    int cols, int Hh){
    __shared__ float buf[1024];
    int z = blockIdx.z;
    int b = z / Hh;
    float* row = scores + ((long long)z*gridDim.y + blockIdx.y)*cols;
    const int* vl = valid + (long)b*cols;
    float mx = -3.4e38f;
    for (int j=threadIdx.x; j<cols; j+=blockDim.x){
        float v = vl[j] ? row[j] : -3.4e38f;
        buf[j] = v;
        mx = fmaxf(mx, v);
    }
    mx = block_max(mx);
    float sm = 0.f;
    for (int j=threadIdx.x; j<cols; j+=blockDim.x){
        float e = expf(buf[j]-mx);
        buf[j] = e; sm += e;
    }
    sm = block_sum(sm);
    float inv = 1.f/sm;
    for (int j=threadIdx.x; j<cols; j+=blockDim.x) row[j] = buf[j]*inv;
}

__global__ void gate_fuse_kernel(const float* __restrict__ t2, const float* __restrict__ gacc,
                                 const float* __restrict__ gate_b, const float* __restrict__ upd,
                                 float* __restrict__ t3, long n, int Dd){
    long i = (long)blockIdx.x*blockDim.x + threadIdx.x;
    if (i >= n) return;
    float g = gacc[i] + gate_b[i % Dd];
    float sg = 1.f / (1.f + expf(-g));
    t3[i] = t2[i] + sg * upd[i];
}

__global__ void silu_kernel(const float* __restrict__ gu, float* __restrict__ act, long rows){
    long i = (long)blockIdx.x*blockDim.x + threadIdx.x;
    long n = rows * HIDc;
    if (i >= n) return;
    long m = i / HIDc; int j = (int)(i % HIDc);
    float g = gu[m*(2*HIDc) + j];
    float v = gu[m*(2*HIDc) + HIDc + j];
    float s = g / (1.f + expf(-g));
    act[i] = s * v;
}

// ---------------- host-side launch helpers ----------------
static inline void tc_nt(const float* A,const float* B,float* C,
    int M,int N,int K,int lda,int ldb,int ldc,
    float alpha,const float* bias,const float* res,int ldres,
    const float* rs,int rsdiv,int accum,
    int zc=1,int batH=1,
    long long aO=0,long long aI=0,long long bO=0,long long bI=0,
    long long cO=0,long long cI=0)
{
    dim3 g(N/128, M/128, zc);
    gemm_h16<2,4><<<g,256>>>(A,B,C,M,N,K,lda,ldb,ldc,batH,
        aO,aI,bO,bI,cO,cI,alpha,bias,res,ldres,rs,rsdiv,accum);
}
static inline void tc_nn_pv(const float* A,const float* B,float* C,
    int M,int N,int K,int lda,int ldb,int ldc,
    int zc,int batH,
    long long aO,long long aI,long long bO,long long bI,
    long long cO,long long cI)
{
    dim3 g(N/64, M/128, zc);
    gemm_tc_nn<128,64,4,2><<<g,256>>>(A,B,C,M,N,K,lda,ldb,ldc,batH,
        aO,aI,bO,bI,cO,cI);
}

extern "C" void kernel_launch(void* const* d_in, const int* in_sizes, int n_in,
                              void* d_out, int out_size)
{
    const float* tokens     = (const float*)d_in[0];
    const float* seq_tokens = (const float*)d_in[1];
    const float* modulation = (const float*)d_in[2];
    const float* attn_norm_w= (const float*)d_in[3];
    const float* qkv_w      = (const float*)d_in[4];
    const float* qkv_b      = (const float*)d_in[5];
    const float* out_w      = (const float*)d_in[6];
    const float* out_b      = (const float*)d_in[7];
    const float* film_w     = (const float*)d_in[8];
    const float* film_b     = (const float*)d_in[9];
    const float* sq_norm_w  = (const float*)d_in[10];
    const float* s_norm_w   = (const float*)d_in[11];
    const float* mha_in_w   = (const float*)d_in[12];
    const float* mha_in_b   = (const float*)d_in[13];
    const float* mha_out_w  = (const float*)d_in[14];
    const float* mha_out_b  = (const float*)d_in[15];
    const float* gate_w     = (const float*)d_in[16];
    const float* gate_b     = (const float*)d_in[17];
    const float* ffn_norm_w = (const float*)d_in[18];
    const float* gu_w       = (const float*)d_in[19];
    const float* gu_b       = (const float*)d_in[20];
    const float* down_w     = (const float*)d_in[21];
    const float* down_b     = (const float*)d_in[22];
    const void*  padding_mask = d_in[23];
    const void*  seq_mask     = d_in[24];
    float* out = (float*)d_out;

    float *p_x,*p_qkv,*p_scores,*p_ctx,*p_t2,*p_qn,*p_sn,*p_cq,*p_ckv,*p_upd,*p_gacc,*p_t3,*p_gu,*p_act,*p_ss,*p_vrow;
    int *p_valid,*p_svalid;
    cudaGetSymbolAddress((void**)&p_x, g_x);
    cudaGetSymbolAddress((void**)&p_qkv, g_qkv);
    cudaGetSymbolAddress((void**)&p_scores, g_scores);
    cudaGetSymbolAddress((void**)&p_ctx, g_ctx);
    cudaGetSymbolAddress((void**)&p_t2, g_t2);
    cudaGetSymbolAddress((void**)&p_qn, g_qn);
    cudaGetSymbolAddress((void**)&p_sn, g_sn);
    cudaGetSymbolAddress((void**)&p_cq, g_cq);
    cudaGetSymbolAddress((void**)&p_ckv, g_ckv);
    cudaGetSymbolAddress((void**)&p_upd, g_upd);
    cudaGetSymbolAddress((void**)&p_gacc, g_gacc);
    cudaGetSymbolAddress((void**)&p_t3, g_t3);
    cudaGetSymbolAddress((void**)&p_gu, g_gu);
    cudaGetSymbolAddress((void**)&p_act, g_act);
    cudaGetSymbolAddress((void**)&p_ss, g_ss);
    cudaGetSymbolAddress((void**)&p_vrow, g_vrow);
    cudaGetSymbolAddress((void**)&p_valid, g_valid);
    cudaGetSymbolAddress((void**)&p_svalid, g_svalid);

    const int BH = Bc*Hc;                     // 64
    const long long SS = (long long)Sc*Sc;    // 1M

    // 1) mask layout detect + decode
    detect_mask_layout<<<(Bc*Sc+255)/256,256>>>((const unsigned char*)padding_mask, Bc*Sc, 0);
    detect_mask_layout<<<(Bc*Lc+255)/256,256>>>((const unsigned char*)seq_mask,     Bc*Lc, 1);
    decode_mask<<<Bc,256>>>(padding_mask, Sc, 0, p_valid,  nullptr);
    decode_mask<<<Bc,256>>>(seq_mask,     Lc, 1, p_svalid, p_vrow);

    // 2) FiLM params: [B, 2D]
    film_gemv<<<(Bc*2*Dc*32 + 255)/256, 256>>>(modulation, film_w, film_b, p_ss, Bc, 2*Dc, Dc);

    // 3) x = FiLM(rmsnorm(tokens))
    rmsnorm_kernel<<<BSc,256>>>(tokens, attn_norm_w, p_x, Dc, p_ss, Sc);

    // 4) qkv = x @ qkv_w^T + qkv_b
    tc_nt(p_x, qkv_w, p_qkv, BSc, 3*Dc, Dc, Dc, Dc, 3*Dc,
          1.f, qkv_b, nullptr, 0, nullptr, 1, 0);

    // 5) RoPE on q,k
    rope_kernel<<<((long)BSc*Hc*(HDc/2) + 255)/256, 256>>>(p_qkv);

    // 6) self-attn scores = (q @ k^T)/8, batched over (b,h)
    tc_nt(p_qkv, p_qkv + Dc, p_scores, Sc, Sc, HDc, 3*Dc, 3*Dc, Sc,
          0.125f, nullptr, nullptr, 0, nullptr, 1, 0,
          BH, Hc,
          (long long)Sc*3*Dc, HDc, (long long)Sc*3*Dc, HDc,
          (long long)Hc*SS, SS);

    // 7) masked softmax
    { dim3 g(1, Sc, BH); softmax_mask_kernel<<<g,256>>>(p_scores, p_valid, Sc, Hc); }

    // 8) ctx = P @ V
    tc_nn_pv(p_scores, p_qkv + 2*Dc, p_ctx, Sc, HDc, Sc, Sc, 3*Dc, Dc,
             BH, Hc,
             (long long)Hc*SS, SS, (long long)Sc*3*Dc, HDc,
             (long long)Sc*Dc, HDc);

    // 9) tokens2 = tokens + ctx @ out_w^T + out_b
    tc_nt(p_ctx, out_w, p_t2, BSc, Dc, Dc, Dc, Dc, Dc,
          1.f, out_b, tokens, Dc, nullptr, 1, 0);

    // 10) query / src norms
    rmsnorm_kernel<<<BSc,256>>>(p_t2, sq_norm_w, p_qn, Dc, nullptr, Sc);
    rmsnorm_kernel<<<BLc,256>>>(seq_tokens, s_norm_w, p_sn, Dc, nullptr, Lc);

    // 11) cq = qn @ wq^T + bq ; ckv = sn @ [wk;wv]^T + [bk;bv]
    tc_nt(p_qn, mha_in_w, p_cq, BSc, Dc, Dc, Dc, Dc, Dc,
          1.f, mha_in_b, nullptr, 0, nullptr, 1, 0);
    tc_nt(p_sn, mha_in_w + (long long)Dc*Dc, p_ckv, BLc, 2*Dc, Dc, Dc, Dc, 2*Dc,
          1.f, mha_in_b + Dc, nullptr, 0, nullptr, 1, 0);

    // 12) cross scores = (cq @ ck^T)/8
    tc_nt(p_cq, p_ckv, p_scores, Sc, Lc, HDc, Dc, 2*Dc, Lc,
          0.125f, nullptr, nullptr, 0, nullptr, 1, 0,
          BH, Hc,
          (long long)Sc*Dc, HDc, (long long)Lc*2*Dc, HDc,
          (long long)Hc*SS, SS);

    // 13) masked softmax (seq mask)
    { dim3 g(1, Sc, BH); softmax_mask_kernel<<<g,256>>>(p_scores, p_svalid, Lc, Hc); }

    // 14) ctx2 = P @ cv
    tc_nn_pv(p_scores, p_ckv + Dc, p_ctx, Sc, HDc, Lc, Lc, 2*Dc, Dc,
             BH, Hc,
             (long long)Hc*SS, SS, (long long)Lc*2*Dc, HDc,
             (long long)Sc*Dc, HDc);

    // 15) update = (ctx2 @ mha_out_w^T + mha_out_b) * valid_rows[b]
    tc_nt(p_ctx, mha_out_w, p_upd, BSc, Dc, Dc, Dc, Dc, Dc,
          1.f, mha_out_b, nullptr, 0, p_vrow, Sc, 0);

    // 16) gate pre-activation: gacc = t2 @ gate_w[:, :D]^T + upd @ gate_w[:, D:]^T
    tc_nt(p_t2,  gate_w,      p_gacc, BSc, Dc, Dc, Dc, 2*Dc, Dc,
          1.f, nullptr, nullptr, 0, nullptr, 1, 0);
    tc_nt(p_upd, gate_w + Dc, p_gacc, BSc, Dc, Dc, Dc, 2*Dc, Dc,
          1.f, nullptr, nullptr, 0, nullptr, 1, 1);

    // 17) t3 = t2 + sigmoid(gacc + gate_b) * upd
    gate_fuse_kernel<<<((long)BSc*Dc + 255)/256, 256>>>(p_t2, p_gacc, gate_b, p_upd, p_t3,
                                                        (long)BSc*Dc, Dc);

    // 18) h = rmsnorm(t3, ffn_norm_w) (reuse g_x)
    rmsnorm_kernel<<<BSc,256>>>(p_t3, ffn_norm_w, p_x, Dc, nullptr, Sc);

    // 19) gu = h @ gu_w^T + gu_b
    tc_nt(p_x, gu_w, p_gu, BSc, 2*HIDc, Dc, Dc, Dc, 2*HIDc,
          1.f, gu_b, nullptr, 0, nullptr, 1, 0);

    // 20) act = silu(g) * val
    silu_kernel<<<((long)BSc*HIDc + 255)/256, 256>>>(p_gu, p_act, BSc);

    // 21) out = t3 + act @ down_w^T + down_b
    tc_nt(p_act, down_w, out, BSc, Dc, HIDc, HIDc, HIDc, Dc,
          1.f, down_b, p_t3, Dc, nullptr, 1, 0);
}

// round 5
// speedup vs baseline: 1.3748x; 1.3748x over previous
#include <cuda_runtime.h>
#include <cuda_bf16.h>
#include <cuda_fp16.h>
#include <math.h>

// Problem constants (PCVRSymbiosis): B=4, S=1024, L=1024, D=1024, H=16, HD=64, HIDDEN=4096
#define Bc 4
#define Sc 1024
#define Lc 1024
#define Dc 1024
#define Hc 16
#define HDc 64
#define HIDc 4096
#define BSc (Bc*Sc)
#define BLc (Bc*Lc)

// ---------------- scratch (static device globals; no runtime alloc) ----------------
__device__ float g_x    [BSc*Dc];
__device__ float g_qkv  [BSc*3*Dc];
__device__ float g_ctx  [BSc*Dc];
__device__ float g_t2   [BSc*Dc];
__device__ float g_qn   [BSc*Dc];
__device__ float g_sn   [BLc*Dc];
__device__ float g_cq   [BSc*Dc];
__device__ float g_ckv  [BLc*2*Dc];
__device__ float g_upd  [BSc*Dc];
__device__ float g_gacc [BSc*Dc];
__device__ float g_t3   [BSc*Dc];
__device__ float g_gu   [(size_t)BSc*2*HIDc];
__device__ float g_act  [(size_t)BSc*HIDc];
__device__ float g_ss   [Bc*2*Dc];
__device__ int   g_valid [BSc];
__device__ int   g_svalid[BLc];
__device__ float g_vrow  [Bc];
__device__ int   g_layout[2];

// ---------------- reductions ----------------
__device__ __forceinline__ float warp_sum(float v){
    #pragma unroll
    for (int o=16;o>0;o>>=1) v += __shfl_xor_sync(0xffffffffu, v, o);
    return v;
}
__device__ float block_sum(float v){
    __shared__ float red[33];
    __syncthreads();
    int lane = threadIdx.x & 31, wid = threadIdx.x >> 5;
    v = warp_sum(v);
    if (lane==0) red[wid] = v;
    __syncthreads();
    int nw = blockDim.x >> 5;
    float r = (threadIdx.x < nw) ? red[threadIdx.x] : 0.f;
    if (wid==0){ r = warp_sum(r); if (lane==0) red[32] = r; }
    __syncthreads();
    return red[32];
}

// ---------------- mask layout detection + decode ----------------
__global__ void detect_mask_layout(const unsigned char* __restrict__ p, int n, int slot){
    int i = blockIdx.x*blockDim.x + threadIdx.x;
    if (i >= n) return;
    unsigned char v = p[i];
    if (v != 0 && v != 1) atomicOr(&g_layout[slot], 2);
    else if (v == 1 && (i & 3) != 0) atomicOr(&g_layout[slot], 1);
}
__global__ void decode_mask(const void* __restrict__ p, int cols, int slot,
                            int* __restrict__ valid, float* __restrict__ vrow){
    int b = blockIdx.x;
    int layout = g_layout[slot];
    int mode = (layout & 2) ? 2 : ((layout & 1) ? 1 : 0);
    __shared__ int s_anyzero;
    if (threadIdx.x==0) s_anyzero = 0;
    __syncthreads();
    int local_any = 0;
    for (int j = threadIdx.x; j < cols; j += blockDim.x){
        long idx = (long)b*cols + j;
        int m;
        if (mode==1)      m = ((const unsigned char*)p)[idx] != 0;
        else if (mode==2) m = ((const float*)p)[idx] != 0.f;
        else              m = ((const int*)p)[idx] != 0;
        valid[idx] = m;
        if (!m) local_any = 1;
    }
    if (local_any) atomicOr(&s_anyzero, 1);
    __syncthreads();
    int anyz = s_anyzero;
    for (int j = threadIdx.x; j < cols; j += blockDim.x){
        long idx = (long)b*cols + j;
        valid[idx] = anyz ? (1 - valid[idx]) : 1;
    }
    if (vrow && threadIdx.x==0) vrow[b] = anyz ? 1.f : 0.f;
}

// ---------------- mma helpers ----------------
__device__ __forceinline__ void mma_f16(float* c, const unsigned* a, const unsigned* b){
    asm volatile("mma.sync.aligned.m16n8k16.row.col.f32.f16.f16.f32 "
        "{%0,%1,%2,%3}, {%4,%5,%6,%7}, {%8,%9}, {%0,%1,%2,%3};"
        : "+f"(c[0]),"+f"(c[1]),"+f"(c[2]),"+f"(c[3])
        : "r"(a[0]),"r"(a[1]),"r"(a[2]),"r"(a[3]), "r"(b[0]),"r"(b[1]));
}
__device__ __forceinline__ unsigned pack_h2(float x, float y){
    __half2 h = __floats2half2_rn(x, y);
    return *(unsigned*)&h;
}

// ---------------- fp16 tensor-core NT GEMM: C = alpha * A @ B^T + epilogue ----------------
template<int NWM,int NWN>
__global__ __launch_bounds__(NWM*NWN*32)
void gemm_h16(const float* __restrict__ A, const float* __restrict__ B,
              float* __restrict__ C,
              int M,int N,int K,int lda,int ldb,int ldc,
              float alpha,
              const float* __restrict__ bias,
              const float* __restrict__ residual,int ldres,
              const float* __restrict__ rowscale,int rsDiv,
              int accum)
{
    constexpr int BM = 128, BN = 128, BK = 16;
    constexpr int NT = NWM*NWN*32;         // 256
    constexpr int WM = BM/NWM, WN = BN/NWN;
    constexpr int MI = WM/16, NI = WN/8;
    constexpr int LDS_H = BK + 8;          // 24 halves per row

    __shared__ __align__(16) __half As[BM*LDS_H];
    __shared__ __align__(16) __half Bs[BN*LDS_H];

    const int tid = threadIdx.x, lane = tid & 31, warp = tid >> 5;
    const int m0 = blockIdx.y*BM, n0 = blockIdx.x*BN;
    const int wm0 = (warp/NWN)*WM, wn0 = (warp%NWN)*WN;
    const int qr = lane >> 2, qc = lane & 3;

    float acc[MI][NI][4];
    #pragma unroll
    for (int i=0;i<MI;i++)
        #pragma unroll
        for (int j=0;j<NI;j++)
            #pragma unroll
            for (int r=0;r<4;r++) acc[i][j][r]=0.f;

    constexpr int AF4 = (BM*BK)/(4*NT);    // 2
    constexpr int BF4 = (BN*BK)/(4*NT);    // 2
    float4 ra[AF4], rb[BF4];

    const int nk = K/BK;
    const int sm = tid>>2, skq = tid&3;

    #pragma unroll
    for (int it=0; it<AF4; ++it)
        ra[it] = *(const float4*)(A + (long long)(m0+sm+it*(NT/4))*lda + skq*4);
    #pragma unroll
    for (int it=0; it<BF4; ++it)
        rb[it] = *(const float4*)(B + (long long)(n0+sm+it*(NT/4))*ldb + skq*4);

    for (int kt=0; kt<nk; ++kt){
        __syncthreads();
        #pragma unroll
        for (int it=0; it<AF4; ++it){
            int m = sm + it*(NT/4);
            *(uint2*)&As[m*LDS_H + skq*4] =
                make_uint2(pack_h2(ra[it].x, ra[it].y), pack_h2(ra[it].z, ra[it].w));
        }
        #pragma unroll
        for (int it=0; it<BF4; ++it){
            int n = sm + it*(NT/4);
            *(uint2*)&Bs[n*LDS_H + skq*4] =
                make_uint2(pack_h2(rb[it].x, rb[it].y), pack_h2(rb[it].z, rb[it].w));
        }
        __syncthreads();
        if (kt+1 < nk){
            int k0 = (kt+1)*BK;
            #pragma unroll
            for (int it=0; it<AF4; ++it)
                ra[it] = *(const float4*)(A + (long long)(m0+sm+it*(NT/4))*lda + k0 + skq*4);
            #pragma unroll
            for (int it=0; it<BF4; ++it)
                rb[it] = *(const float4*)(B + (long long)(n0+sm+it*(NT/4))*ldb + k0 + skq*4);
        }
        unsigned af[MI][4], bf[NI][2];
        #pragma unroll
        for (int mi=0; mi<MI; ++mi){
            int mr = wm0 + mi*16 + qr;
            af[mi][0] = *(const unsigned*)&As[ mr   *LDS_H + 2*qc    ];
            af[mi][1] = *(const unsigned*)&As[(mr+8)*LDS_H + 2*qc    ];
            af[mi][2] = *(const unsigned*)&As[ mr   *LDS_H + 2*qc + 8];
            af[mi][3] = *(const unsigned*)&As[(mr+8)*LDS_H + 2*qc + 8];
        }
        #pragma unroll
        for (int ni=0; ni<NI; ++ni){
            int nc = wn0 + ni*8 + qr;
            bf[ni][0] = *(const unsigned*)&Bs[nc*LDS_H + 2*qc    ];
            bf[ni][1] = *(const unsigned*)&Bs[nc*LDS_H + 2*qc + 8];
        }
        #pragma unroll
        for (int mi=0; mi<MI; ++mi)
            #pragma unroll
            for (int ni=0; ni<NI; ++ni)
                mma_f16(acc[mi][ni], af[mi], bf[ni]);
    }

    #pragma unroll
    for (int mi=0; mi<MI; ++mi){
        #pragma unroll
        for (int half=0; half<2; ++half){
            int gm = m0 + wm0 + mi*16 + qr + half*8;
            float rs = rowscale ? rowscale[gm/rsDiv] : 1.f;
            #pragma unroll
            for (int ni=0; ni<NI; ++ni){
                int gn = n0 + wn0 + ni*8 + qc*2;
                float v0 = alpha*acc[mi][ni][half*2+0];
                float v1 = alpha*acc[mi][ni][half*2+1];
                if (bias){ v0 += bias[gn]; v1 += bias[gn+1]; }
                v0 *= rs; v1 *= rs;
                if (residual){
                    float2 r = *(const float2*)(residual + (long long)gm*ldres + gn);
                    v0 += r.x; v1 += r.y;
                }
                long long off = (long long)gm*ldc + gn;
                if (accum){ float2 c0 = *(float2*)(C+off); v0 += c0.x; v1 += c0.y; }
                *(float2*)(C+off) = make_float2(v0, v1);
            }
        }
    }
}

// ---------------- fused flash attention ----------------
// grid (qrows/128, B*H). block 256 (8 warps × 16 q-rows each).
// q,k,v fp32 row-major with per-row leading dims; head offset h*HD applied here.
// Masked online softmax (additive -1e30), fp16 mma, fp32 accum, scale folded into Q.
__global__ __launch_bounds__(256)
void flash_attn(const float* __restrict__ q, const float* __restrict__ k,
                const float* __restrict__ v, float* __restrict__ o,
                const int* __restrict__ valid,
                int ldq, int ldk, int ldv, int ldo,
                int qrows, int krows)
{
    constexpr int BQ = 128, BKT = 64;
    constexpr int LQ = HDc + 8;      // 72 halves
    constexpr int LV = BKT + 8;      // 72 halves
    __shared__ __half Qs[BQ*LQ];
    __shared__ __half Ks[BKT*LQ];
    __shared__ __half Vt[HDc*LV];
    __shared__ float  mk[BKT];

    const int z = blockIdx.y;
    const int b = z / Hc, h = z % Hc;
    const float* qb = q + (long long)b*qrows*ldq + h*HDc;
    const float* kb = k + (long long)b*krows*ldk + h*HDc;
    const float* vb = v + (long long)b*krows*ldv + h*HDc;
    float*       ob = o + (long long)b*qrows*ldo + h*HDc;
    const int*   vl = valid + (long)b*krows;

    const int tid = threadIdx.x, lane = tid & 31, warp = tid >> 5;
    const int qr = lane >> 2, qc = lane & 3;
    const int m0 = blockIdx.x*BQ;
    const int wm = warp*16;

    // load Q tile (scaled by 1/sqrt(HD) = 0.125)
    for (int i = tid; i < BQ*(HDc/4); i += 256){
        int r = i/(HDc/4), c4 = i%(HDc/4);
        float4 f = *(const float4*)(qb + (long long)(m0+r)*ldq + c4*4);
        *(uint2*)&Qs[r*LQ + c4*4] =
            make_uint2(pack_h2(0.125f*f.x, 0.125f*f.y), pack_h2(0.125f*f.z, 0.125f*f.w));
    }

    float mr0 = -3.4e38f, mr1 = -3.4e38f, lr0 = 0.f, lr1 = 0.f;
    float O[8][4];
    #pragma unroll
    for (int i=0;i<8;i++){ O[i][0]=0.f; O[i][1]=0.f; O[i][2]=0.f; O[i][3]=0.f; }

    const int nkt = krows / BKT;
    for (int kt=0; kt<nkt; ++kt){
        __syncthreads();
        // K tile
        for (int i = tid; i < BKT*(HDc/4); i += 256){
            int r = i/(HDc/4), c4 = i%(HDc/4);
            float4 f = *(const float4*)(kb + (long long)(kt*BKT+r)*ldk + c4*4);
            *(uint2*)&Ks[r*LQ + c4*4] =
                make_uint2(pack_h2(f.x, f.y), pack_h2(f.z, f.w));
        }
        // V tile, transposed: Vt[dim][key]
        for (int i = tid; i < BKT*(HDc/4); i += 256){
            int r = i/(HDc/4), c4 = i%(HDc/4);
            float4 f = *(const float4*)(vb + (long long)(kt*BKT+r)*ldv + c4*4);
            Vt[(c4*4+0)*LV + r] = __float2half(f.x);
            Vt[(c4*4+1)*LV + r] = __float2half(f.y);
            Vt[(c4*4+2)*LV + r] = __float2half(f.z);
            Vt[(c4*4+3)*LV + r] = __float2half(f.w);
        }
        if (tid < BKT) mk[tid] = vl[kt*BKT + tid] ? 0.f : -1e30f;
        __syncthreads();

        // S = Q K^T  (16 q-rows × 64 keys per warp)
        float S[8][4];
        #pragma unroll
        for (int i=0;i<8;i++){ S[i][0]=0.f; S[i][1]=0.f; S[i][2]=0.f; S[i][3]=0.f; }
        #pragma unroll
        for (int ks=0; ks<HDc; ks+=16){
            unsigned af[4];
            af[0] = *(const unsigned*)&Qs[(wm+qr  )*LQ + ks + 2*qc    ];
            af[1] = *(const unsigned*)&Qs[(wm+qr+8)*LQ + ks + 2*qc    ];
            af[2] = *(const unsigned*)&Qs[(wm+qr  )*LQ + ks + 2*qc + 8];
            af[3] = *(const unsigned*)&Qs[(wm+qr+8)*LQ + ks + 2*qc + 8];
            #pragma unroll
            for (int ni=0; ni<8; ++ni){
                unsigned bf[2];
                bf[0] = *(const unsigned*)&Ks[(ni*8+qr)*LQ + ks + 2*qc    ];
                bf[1] = *(const unsigned*)&Ks[(ni*8+qr)*LQ + ks + 2*qc + 8];
                mma_f16(S[ni], af, bf);
            }
        }
        // mask + row max
        float mn0 = -3.4e38f, mn1 = -3.4e38f;
        #pragma unroll
        for (int ni=0; ni<8; ++ni){
            float a0 = mk[ni*8 + 2*qc], a1 = mk[ni*8 + 2*qc + 1];
            S[ni][0] += a0; S[ni][1] += a1; S[ni][2] += a0; S[ni][3] += a1;
            mn0 = fmaxf(mn0, fmaxf(S[ni][0], S[ni][1]));
            mn1 = fmaxf(mn1, fmaxf(S[ni][2], S[ni][3]));
        }
        mn0 = fmaxf(mn0, __shfl_xor_sync(0xffffffffu, mn0, 1));
        mn0 = fmaxf(mn0, __shfl_xor_sync(0xffffffffu, mn0, 2));
        mn1 = fmaxf(mn1, __shfl_xor_sync(0xffffffffu, mn1, 1));
        mn1 = fmaxf(mn1, __shfl_xor_sync(0xffffffffu, mn1, 2));
        float mN0 = fmaxf(mr0, mn0), mN1 = fmaxf(mr1, mn1);
        float f0 = __expf(mr0 - mN0), f1 = __expf(mr1 - mN1);
        lr0 *= f0; lr1 *= f1;
        #pragma unroll
        for (int no=0; no<8; ++no){
            O[no][0]*=f0; O[no][1]*=f0; O[no][2]*=f1; O[no][3]*=f1;
        }
        mr0 = mN0; mr1 = mN1;
        // P = exp(S - m), pack to fp16 A-fragments
        unsigned ph[8][2];
        #pragma unroll
        for (int ni=0; ni<8; ++ni){
            float p0 = __expf(S[ni][0]-mr0), p1 = __expf(S[ni][1]-mr0);
            float p2 = __expf(S[ni][2]-mr1), p3 = __expf(S[ni][3]-mr1);
            lr0 += p0+p1; lr1 += p2+p3;
            ph[ni][0] = pack_h2(p0, p1);
            ph[ni][1] = pack_h2(p2, p3);
        }
        // O += P V
        #pragma unroll
        for (int st=0; st<4; ++st){
            unsigned af[4] = { ph[2*st][0], ph[2*st][1], ph[2*st+1][0], ph[2*st+1][1] };
            #pragma unroll
            for (int no=0; no<8; ++no){
                unsigned bf[2];
                bf[0] = *(const unsigned*)&Vt[(no*8+qr)*LV + st*16 + 2*qc    ];
                bf[1] = *(const unsigned*)&Vt[(no*8+qr)*LV + st*16 + 2*qc + 8];
                mma_f16(O[no], af, bf);
            }
        }
    }

    // final normalize (row sums live across the 4 qc lanes)
    lr0 += __shfl_xor_sync(0xffffffffu, lr0, 1);
    lr0 += __shfl_xor_sync(0xffffffffu, lr0, 2);
    lr1 += __shfl_xor_sync(0xffffffffu, lr1, 1);
    lr1 += __shfl_xor_sync(0xffffffffu, lr1, 2);
    float i0 = 1.f/lr0, i1 = 1.f/lr1;
    #pragma unroll
    for (int no=0; no<8; ++no){
        int gm0 = m0 + wm + qr, gn = no*8 + 2*qc;
        *(float2*)(ob + (long long)gm0*ldo + gn)     = make_float2(O[no][0]*i0, O[no][1]*i0);
        *(float2*)(ob + (long long)(gm0+8)*ldo + gn) = make_float2(O[no][2]*i1, O[no][3]*i1);
    }
}

// ---------------- small fused kernels ----------------
__global__ void film_gemv(const float* __restrict__ mod, const float* __restrict__ W,
                          const float* __restrict__ bias, float* __restrict__ out,
                          int Bn, int N2, int K){
    int warp = (blockIdx.x*blockDim.x + threadIdx.x) >> 5;
    int lane = threadIdx.x & 31;
    if (warp >= Bn*N2) return;
    int b = warp / N2, n = warp % N2;
    const float* a = mod + (long)b*K;
    const float* w = W   + (long)n*K;
    float acc=0.f;
    for (int k=lane; k<K; k+=32) acc = fmaf(a[k], w[k], acc);
    acc = warp_sum(acc);
    if (lane==0) out[warp] = acc + bias[n];
}

__global__ void rmsnorm_kernel(const float* __restrict__ x, const float* __restrict__ w,
                               float* __restrict__ y, int Dd,
                               const float* __restrict__ filmss, int S){
    long row = blockIdx.x;
    const float* xr = x + row*Dd;
    float ss = 0.f;
    for (int j = threadIdx.x; j < Dd; j += blockDim.x){ float v = xr[j]; ss = fmaf(v,v,ss); }
    ss = block_sum(ss);
    float r = rsqrtf(ss/(float)Dd + 1e-6f);
    if (filmss){
        int b = (int)(row / S);
        const float* sc = filmss + (long)b*2*Dd;
        for (int j = threadIdx.x; j < Dd; j += blockDim.x){
            float v = xr[j]*r*w[j];
            y[row*Dd + j] = v*(1.f + 0.1f*tanhf(sc[j])) + sc[Dd + j];
        }
    } else {
        for (int j = threadIdx.x; j < Dd; j += blockDim.x)
            y[row*Dd + j] = xr[j]*r*w[j];
    }
}

__global__ void rope_kernel(float* __restrict__ qkv){
    long idx = (long)blockIdx.x*blockDim.x + threadIdx.x;
    const long total = (long)BSc * Hc * (HDc/2);
    if (idx >= total) return;
    int i = idx % (HDc/2);
    int h = (idx / (HDc/2)) % Hc;
    long row = idx / ((HDc/2)*Hc);
    int s = (int)(row % Sc);
    float freq = expf(-logf(10000.f) * (float)(2*i) / (float)HDc);
    float ang = (float)s * freq;
    float c = cosf(ang), sn = sinf(ang);
    float* qb = qkv + row*(3*Dc) + h*HDc;
    float e = qb[2*i], o = qb[2*i+1];
    qb[2*i]   = e*c - o*sn;
    qb[2*i+1] = e*sn + o*c;
    float* kb = qb + Dc;
    e = kb[2*i]; o = kb[2*i+1];
    kb[2*i]   = e*c - o*sn;
    kb[2*i+1] = e*sn + o*c;
}

__global__ void gate_fuse_kernel(const float* __restrict__ t2, const float* __restrict__ gacc,
                                 const float* __restrict__ gate_b, const float* __restrict__ upd,
                                 float* __restrict__ t3, long n, int Dd){
    long i = (long)blockIdx.x*blockDim.x + threadIdx.x;
    if (i >= n) return;
    float g = gacc[i] + gate_b[i % Dd];
    float sg = 1.f / (1.f + expf(-g));
    t3[i] = t2[i] + sg * upd[i];
}

__global__ void silu_kernel(const float* __restrict__ gu, float* __restrict__ act, long rows){
    long i = (long)blockIdx.x*blockDim.x + threadIdx.x;
    long n = rows * HIDc;
    if (i >= n) return;
    long m = i / HIDc; int j = (int)(i % HIDc);
    float g = gu[m*(2*HIDc) + j];
    float v = gu[m*(2*HIDc) + HIDc + j];
    float s = g / (1.f + expf(-g));
    act[i] = s * v;
}

// ---------------- host-side launch helpers ----------------
static inline void tc_nt(const float* A,const float* B,float* C,
    int M,int N,int K,int lda,int ldb,int ldc,
    float alpha,const float* bias,const float* res,int ldres,
    const float* rs,int rsdiv,int accum)
{
    dim3 g(N/128, M/128, 1);
    gemm_h16<2,4><<<g,256>>>(A,B,C,M,N,K,lda,ldb,ldc,
        alpha,bias,res,ldres,rs,rsdiv,accum);
}

extern "C" void kernel_launch(void* const* d_in, const int* in_sizes, int n_in,
                              void* d_out, int out_size)
{
    const float* tokens     = (const float*)d_in[0];
    const float* seq_tokens = (const float*)d_in[1];
    const float* modulation = (const float*)d_in[2];
    const float* attn_norm_w= (const float*)d_in[3];
    const float* qkv_w      = (const float*)d_in[4];
    const float* qkv_b      = (const float*)d_in[5];
    const float* out_w      = (const float*)d_in[6];
    const float* out_b      = (const float*)d_in[7];
    const float* film_w     = (const float*)d_in[8];
    const float* film_b     = (const float*)d_in[9];
    const float* sq_norm_w  = (const float*)d_in[10];
    const float* s_norm_w   = (const float*)d_in[11];
    const float* mha_in_w   = (const float*)d_in[12];
    const float* mha_in_b   = (const float*)d_in[13];
    const float* mha_out_w  = (const float*)d_in[14];
    const float* mha_out_b  = (const float*)d_in[15];
    const float* gate_w     = (const float*)d_in[16];
    const float* gate_b     = (const float*)d_in[17];
    const float* ffn_norm_w = (const float*)d_in[18];
    const float* gu_w       = (const float*)d_in[19];
    const float* gu_b       = (const float*)d_in[20];
    const float* down_w     = (const float*)d_in[21];
    const float* down_b     = (const float*)d_in[22];
    const void*  padding_mask = d_in[23];
    const void*  seq_mask     = d_in[24];
    float* out = (float*)d_out;

    float *p_x,*p_qkv,*p_ctx,*p_t2,*p_qn,*p_sn,*p_cq,*p_ckv,*p_upd,*p_gacc,*p_t3,*p_gu,*p_act,*p_ss,*p_vrow;
    int *p_valid,*p_svalid;
    cudaGetSymbolAddress((void**)&p_x, g_x);
    cudaGetSymbolAddress((void**)&p_qkv, g_qkv);
    cudaGetSymbolAddress((void**)&p_ctx, g_ctx);
    cudaGetSymbolAddress((void**)&p_t2, g_t2);
    cudaGetSymbolAddress((void**)&p_qn, g_qn);
    cudaGetSymbolAddress((void**)&p_sn, g_sn);
    cudaGetSymbolAddress((void**)&p_cq, g_cq);
    cudaGetSymbolAddress((void**)&p_ckv, g_ckv);
    cudaGetSymbolAddress((void**)&p_upd, g_upd);
    cudaGetSymbolAddress((void**)&p_gacc, g_gacc);
    cudaGetSymbolAddress((void**)&p_t3, g_t3);
    cudaGetSymbolAddress((void**)&p_gu, g_gu);
    cudaGetSymbolAddress((void**)&p_act, g_act);
    cudaGetSymbolAddress((void**)&p_ss, g_ss);
    cudaGetSymbolAddress((void**)&p_vrow, g_vrow);
    cudaGetSymbolAddress((void**)&p_valid, g_valid);
    cudaGetSymbolAddress((void**)&p_svalid, g_svalid);

    // 1) mask layout detect + decode
    detect_mask_layout<<<(Bc*Sc+255)/256,256>>>((const unsigned char*)padding_mask, Bc*Sc, 0);
    detect_mask_layout<<<(Bc*Lc+255)/256,256>>>((const unsigned char*)seq_mask,     Bc*Lc, 1);
    decode_mask<<<Bc,256>>>(padding_mask, Sc, 0, p_valid,  nullptr);
    decode_mask<<<Bc,256>>>(seq_mask,     Lc, 1, p_svalid, p_vrow);

    // 2) FiLM params: [B, 2D]
    film_gemv<<<(Bc*2*Dc*32 + 255)/256, 256>>>(modulation, film_w, film_b, p_ss, Bc, 2*Dc, Dc);

    // 3) x = FiLM(rmsnorm(tokens))
    rmsnorm_kernel<<<BSc,256>>>(tokens, attn_norm_w, p_x, Dc, p_ss, Sc);

    // 4) qkv = x @ qkv_w^T + qkv_b
    tc_nt(p_x, qkv_w, p_qkv, BSc, 3*Dc, Dc, Dc, Dc, 3*Dc,
          1.f, qkv_b, nullptr, 0, nullptr, 1, 0);

    // 5) RoPE on q,k
    rope_kernel<<<((long)BSc*Hc*(HDc/2) + 255)/256, 256>>>(p_qkv);

    // 6-8) fused self-attention (scores + masked softmax + PV)
    { dim3 g(Sc/128, Bc*Hc);
      flash_attn<<<g,256>>>(p_qkv, p_qkv + Dc, p_qkv + 2*Dc, p_ctx, p_valid,
                            3*Dc, 3*Dc, 3*Dc, Dc, Sc, Sc); }

    // 9) tokens2 = tokens + ctx @ out_w^T + out_b
    tc_nt(p_ctx, out_w, p_t2, BSc, Dc, Dc, Dc, Dc, Dc,
          1.f, out_b, tokens, Dc, nullptr, 1, 0);

    // 10) query / src norms
    rmsnorm_kernel<<<BSc,256>>>(p_t2, sq_norm_w, p_qn, Dc, nullptr, Sc);
    rmsnorm_kernel<<<BLc,256>>>(seq_tokens, s_norm_w, p_sn, Dc, nullptr, Lc);

    // 11) cq = qn @ wq^T + bq ; ckv = sn @ [wk;wv]^T + [bk;bv]
    tc_nt(p_qn, mha_in_w, p_cq, BSc, Dc, Dc, Dc, Dc, Dc,
          1.f, mha_in_b, nullptr, 0, nullptr, 1, 0);
    tc_nt(p_sn, mha_in_w + (long long)Dc*Dc, p_ckv, BLc, 2*Dc, Dc, Dc, Dc, 2*Dc,
          1.f, mha_in_b + Dc, nullptr, 0, nullptr, 1, 0);

    // 12-14) fused cross-attention
    { dim3 g(Sc/128, Bc*Hc);
      flash_attn<<<g,256>>>(p_cq, p_ckv, p_ckv + Dc, p_ctx, p_svalid,
                            Dc, 2*Dc, 2*Dc, Dc, Sc, Lc); }

    // 15) update = (ctx2 @ mha_out_w^T + mha_out_b) * valid_rows[b]
    tc_nt(p_ctx, mha_out_w, p_upd, BSc, Dc, Dc, Dc, Dc, Dc,
          1.f, mha_out_b, nullptr, 0, p_vrow, Sc, 0);

    // 16) gate pre-activation
    tc_nt(p_t2,  gate_w,      p_gacc, BSc, Dc, Dc, Dc, 2*Dc, Dc,
          1.f, nullptr, nullptr, 0, nullptr, 1, 0);
    tc_nt(p_upd, gate_w + Dc, p_gacc, BSc, Dc, Dc, Dc, 2*Dc, Dc,
          1.f, nullptr, nullptr, 0, nullptr, 1, 1);

    // 17) t3 = t2 + sigmoid(gacc + gate_b) * upd
    gate_fuse_kernel<<<((long)BSc*Dc + 255)/256, 256>>>(p_t2, p_gacc, gate_b, p_upd, p_t3,
                                                        (long)BSc*Dc, Dc);

    // 18) h = rmsnorm(t3, ffn_norm_w)
    rmsnorm_kernel<<<BSc,256>>>(p_t3, ffn_norm_w, p_x, Dc, nullptr, Sc);

    // 19) gu = h @ gu_w^T + gu_b
    tc_nt(p_x, gu_w, p_gu, BSc, 2*HIDc, Dc, Dc, Dc, 2*HIDc,
          1.f, gu_b, nullptr, 0, nullptr, 1, 0);

    // 20) act = silu(g) * val
    silu_kernel<<<((long)BSc*HIDc + 255)/256, 256>>>(p_gu, p_act, BSc);

    // 21) out = t3 + act @ down_w^T + down_b
    tc_nt(p_act, down_w, out, BSc, Dc, HIDc, HIDc, HIDc, Dc,
          1.f, down_b, p_t3, Dc, nullptr, 1, 0);
}

// round 6
// speedup vs baseline: 1.3831x; 1.0060x over previous
#include <cuda_runtime.h>
#include <cuda_bf16.h>
#include <cuda_fp16.h>
#include <math.h>

// Problem constants (PCVRSymbiosis): B=4, S=1024, L=1024, D=1024, H=16, HD=64, HIDDEN=4096
#define Bc 4
#define Sc 1024
#define Lc 1024
#define Dc 1024
#define Hc 16
#define HDc 64
#define HIDc 4096
#define BSc (Bc*Sc)
#define BLc (Bc*Lc)

// ---------------- scratch (static device globals; no runtime alloc) ----------------
__device__ float g_x    [BSc*Dc];
__device__ float g_qkv  [BSc*3*Dc];
__device__ float g_ctx  [BSc*Dc];
__device__ float g_t2   [BSc*Dc];
__device__ float g_qn   [BSc*Dc];
__device__ float g_sn   [BLc*Dc];
__device__ float g_cq   [BSc*Dc];
__device__ float g_ckv  [BLc*2*Dc];
__device__ float g_upd  [BSc*Dc];
__device__ float g_gacc [BSc*Dc];
__device__ float g_t3   [BSc*Dc];
__device__ float g_gu   [(size_t)BSc*2*HIDc];
__device__ float g_act  [(size_t)BSc*HIDc];
__device__ float g_ss   [Bc*2*Dc];
__device__ int   g_valid [BSc];
__device__ int   g_svalid[BLc];
__device__ float g_vrow  [Bc];
__device__ int   g_layout[2];

// ---------------- reductions ----------------
__device__ __forceinline__ float warp_sum(float v){
    #pragma unroll
    for (int o=16;o>0;o>>=1) v += __shfl_xor_sync(0xffffffffu, v, o);
    return v;
}
__device__ float block_sum(float v){
    __shared__ float red[33];
    __syncthreads();
    int lane = threadIdx.x & 31, wid = threadIdx.x >> 5;
    v = warp_sum(v);
    if (lane==0) red[wid] = v;
    __syncthreads();
    int nw = blockDim.x >> 5;
    float r = (threadIdx.x < nw) ? red[threadIdx.x] : 0.f;
    if (wid==0){ r = warp_sum(r); if (lane==0) red[32] = r; }
    __syncthreads();
    return red[32];
}

// ---------------- mask layout detection + decode ----------------
__global__ void detect_mask_layout(const unsigned char* __restrict__ p, int n, int slot){
    int i = blockIdx.x*blockDim.x + threadIdx.x;
    if (i >= n) return;
    unsigned char v = p[i];
    if (v != 0 && v != 1) atomicOr(&g_layout[slot], 2);
    else if (v == 1 && (i & 3) != 0) atomicOr(&g_layout[slot], 1);
}
__global__ void decode_mask(const void* __restrict__ p, int cols, int slot,
                            int* __restrict__ valid, float* __restrict__ vrow){
    int b = blockIdx.x;
    int layout = g_layout[slot];
    int mode = (layout & 2) ? 2 : ((layout & 1) ? 1 : 0);
    __shared__ int s_anyzero;
    if (threadIdx.x==0) s_anyzero = 0;
    __syncthreads();
    int local_any = 0;
    for (int j = threadIdx.x; j < cols; j += blockDim.x){
        long idx = (long)b*cols + j;
        int m;
        if (mode==1)      m = ((const unsigned char*)p)[idx] != 0;
        else if (mode==2) m = ((const float*)p)[idx] != 0.f;
        else              m = ((const int*)p)[idx] != 0;
        valid[idx] = m;
        if (!m) local_any = 1;
    }
    if (local_any) atomicOr(&s_anyzero, 1);
    __syncthreads();
    int anyz = s_anyzero;
    for (int j = threadIdx.x; j < cols; j += blockDim.x){
        long idx = (long)b*cols + j;
        valid[idx] = anyz ? (1 - valid[idx]) : 1;
    }
    if (vrow && threadIdx.x==0) vrow[b] = anyz ? 1.f : 0.f;
}

// ---------------- mma helpers ----------------
__device__ __forceinline__ void mma_f16(float* c, const unsigned* a, const unsigned* b){
    asm volatile("mma.sync.aligned.m16n8k16.row.col.f32.f16.f16.f32 "
        "{%0,%1,%2,%3}, {%4,%5,%6,%7}, {%8,%9}, {%0,%1,%2,%3};"
        : "+f"(c[0]),"+f"(c[1]),"+f"(c[2]),"+f"(c[3])
        : "r"(a[0]),"r"(a[1]),"r"(a[2]),"r"(a[3]), "r"(b[0]),"r"(b[1]));
}
__device__ __forceinline__ unsigned pack_h2(float x, float y){
    __half2 h = __floats2half2_rn(x, y);
    return *(unsigned*)&h;
}

// ---------------- fp16 tensor-core NT GEMM: C = alpha * A @ B^T + epilogue ----------------
template<int NWM,int NWN>
__global__ __launch_bounds__(NWM*NWN*32)
void gemm_h16(const float* __restrict__ A, const float* __restrict__ B,
              float* __restrict__ C,
              int M,int N,int K,int lda,int ldb,int ldc,
              float alpha,
              const float* __restrict__ bias,
              const float* __restrict__ residual,int ldres,
              const float* __restrict__ rowscale,int rsDiv,
              int accum)
{
    constexpr int BM = 128, BN = 128, BK = 16;
    constexpr int NT = NWM*NWN*32;         // 256
    constexpr int WM = BM/NWM, WN = BN/NWN;
    constexpr int MI = WM/16, NI = WN/8;
    constexpr int LDS_H = BK + 8;          // 24 halves per row

    __shared__ __align__(16) __half As[BM*LDS_H];
    __shared__ __align__(16) __half Bs[BN*LDS_H];

    const int tid = threadIdx.x, lane = tid & 31, warp = tid >> 5;
    const int m0 = blockIdx.y*BM, n0 = blockIdx.x*BN;
    const int wm0 = (warp/NWN)*WM, wn0 = (warp%NWN)*WN;
    const int qr = lane >> 2, qc = lane & 3;

    float acc[MI][NI][4];
    #pragma unroll
    for (int i=0;i<MI;i++)
        #pragma unroll
        for (int j=0;j<NI;j++)
            #pragma unroll
            for (int r=0;r<4;r++) acc[i][j][r]=0.f;

    constexpr int AF4 = (BM*BK)/(4*NT);    // 2
    constexpr int BF4 = (BN*BK)/(4*NT);    // 2
    float4 ra[AF4], rb[BF4];

    const int nk = K/BK;
    const int sm = tid>>2, skq = tid&3;

    #pragma unroll
    for (int it=0; it<AF4; ++it)
        ra[it] = *(const float4*)(A + (long long)(m0+sm+it*(NT/4))*lda + skq*4);
    #pragma unroll
    for (int it=0; it<BF4; ++it)
        rb[it] = *(const float4*)(B + (long long)(n0+sm+it*(NT/4))*ldb + skq*4);

    for (int kt=0; kt<nk; ++kt){
        __syncthreads();
        #pragma unroll
        for (int it=0; it<AF4; ++it){
            int m = sm + it*(NT/4);
            *(uint2*)&As[m*LDS_H + skq*4] =
                make_uint2(pack_h2(ra[it].x, ra[it].y), pack_h2(ra[it].z, ra[it].w));
        }
        #pragma unroll
        for (int it=0; it<BF4; ++it){
            int n = sm + it*(NT/4);
            *(uint2*)&Bs[n*LDS_H + skq*4] =
                make_uint2(pack_h2(rb[it].x, rb[it].y), pack_h2(rb[it].z, rb[it].w));
        }
        __syncthreads();
        if (kt+1 < nk){
            int k0 = (kt+1)*BK;
            #pragma unroll
            for (int it=0; it<AF4; ++it)
                ra[it] = *(const float4*)(A + (long long)(m0+sm+it*(NT/4))*lda + k0 + skq*4);
            #pragma unroll
            for (int it=0; it<BF4; ++it)
                rb[it] = *(const float4*)(B + (long long)(n0+sm+it*(NT/4))*ldb + k0 + skq*4);
        }
        unsigned af[MI][4], bf[NI][2];
        #pragma unroll
        for (int mi=0; mi<MI; ++mi){
            int mr = wm0 + mi*16 + qr;
            af[mi][0] = *(const unsigned*)&As[ mr   *LDS_H + 2*qc    ];
            af[mi][1] = *(const unsigned*)&As[(mr+8)*LDS_H + 2*qc    ];
            af[mi][2] = *(const unsigned*)&As[ mr   *LDS_H + 2*qc + 8];
            af[mi][3] = *(const unsigned*)&As[(mr+8)*LDS_H + 2*qc + 8];
        }
        #pragma unroll
        for (int ni=0; ni<NI; ++ni){
            int nc = wn0 + ni*8 + qr;
            bf[ni][0] = *(const unsigned*)&Bs[nc*LDS_H + 2*qc    ];
            bf[ni][1] = *(const unsigned*)&Bs[nc*LDS_H + 2*qc + 8];
        }
        #pragma unroll
        for (int mi=0; mi<MI; ++mi)
            #pragma unroll
            for (int ni=0; ni<NI; ++ni)
                mma_f16(acc[mi][ni], af[mi], bf[ni]);
    }

    #pragma unroll
    for (int mi=0; mi<MI; ++mi){
        #pragma unroll
        for (int half=0; half<2; ++half){
            int gm = m0 + wm0 + mi*16 + qr + half*8;
            float rs = rowscale ? rowscale[gm/rsDiv] : 1.f;
            #pragma unroll
            for (int ni=0; ni<NI; ++ni){
                int gn = n0 + wn0 + ni*8 + qc*2;
                float v0 = alpha*acc[mi][ni][half*2+0];
                float v1 = alpha*acc[mi][ni][half*2+1];
                if (bias){ v0 += bias[gn]; v1 += bias[gn+1]; }
                v0 *= rs; v1 *= rs;
                if (residual){
                    float2 r = *(const float2*)(residual + (long long)gm*ldres + gn);
                    v0 += r.x; v1 += r.y;
                }
                long long off = (long long)gm*ldc + gn;
                if (accum){ float2 c0 = *(float2*)(C+off); v0 += c0.x; v1 += c0.y; }
                *(float2*)(C+off) = make_float2(v0, v1);
            }
        }
    }
}

// ---------------- fused flash attention ----------------
// grid (qrows/128, B*H). block 256 (8 warps × 16 q-rows each).
// q,k,v fp32 row-major with per-row leading dims; head offset h*HD applied here.
// Masked online softmax (additive -1e30), fp16 mma, fp32 accum, scale folded into Q.
__global__ __launch_bounds__(256)
void flash_attn(const float* __restrict__ q, const float* __restrict__ k,
                const float* __restrict__ v, float* __restrict__ o,
                const int* __restrict__ valid,
                int ldq, int ldk, int ldv, int ldo,
                int qrows, int krows)
{
    constexpr int BQ = 128, BKT = 64;
    constexpr int LQ = HDc + 8;      // 72 halves
    constexpr int LV = BKT + 8;      // 72 halves
    __shared__ __half Qs[BQ*LQ];
    __shared__ __half Ks[BKT*LQ];
    __shared__ __half Vt[HDc*LV];
    __shared__ float  mk[BKT];

    const int z = blockIdx.y;
    const int b = z / Hc, h = z % Hc;
    const float* qb = q + (long long)b*qrows*ldq + h*HDc;
    const float* kb = k + (long long)b*krows*ldk + h*HDc;
    const float* vb = v + (long long)b*krows*ldv + h*HDc;
    float*       ob = o + (long long)b*qrows*ldo + h*HDc;
    const int*   vl = valid + (long)b*krows;

    const int tid = threadIdx.x, lane = tid & 31, warp = tid >> 5;
    const int qr = lane >> 2, qc = lane & 3;
    const int m0 = blockIdx.x*BQ;
    const int wm = warp*16;

    // load Q tile (scaled by 1/sqrt(HD) = 0.125)
    for (int i = tid; i < BQ*(HDc/4); i += 256){
        int r = i/(HDc/4), c4 = i%(HDc/4);
        float4 f = *(const float4*)(qb + (long long)(m0+r)*ldq + c4*4);
        *(uint2*)&Qs[r*LQ + c4*4] =
            make_uint2(pack_h2(0.125f*f.x, 0.125f*f.y), pack_h2(0.125f*f.z, 0.125f*f.w));
    }

    float mr0 = -3.4e38f, mr1 = -3.4e38f, lr0 = 0.f, lr1 = 0.f;
    float O[8][4];
    #pragma unroll
    for (int i=0;i<8;i++){ O[i][0]=0.f; O[i][1]=0.f; O[i][2]=0.f; O[i][3]=0.f; }

    const int nkt = krows / BKT;
    for (int kt=0; kt<nkt; ++kt){
        __syncthreads();
        // K tile
        for (int i = tid; i < BKT*(HDc/4); i += 256){
            int r = i/(HDc/4), c4 = i%(HDc/4);
            float4 f = *(const float4*)(kb + (long long)(kt*BKT+r)*ldk + c4*4);
            *(uint2*)&Ks[r*LQ + c4*4] =
                make_uint2(pack_h2(f.x, f.y), pack_h2(f.z, f.w));
        }
        // V tile, transposed: Vt[dim][key]
        for (int i = tid; i < BKT*(HDc/4); i += 256){
            int r = i/(HDc/4), c4 = i%(HDc/4);
            float4 f = *(const float4*)(vb + (long long)(kt*BKT+r)*ldv + c4*4);
            Vt[(c4*4+0)*LV + r] = __float2half(f.x);
            Vt[(c4*4+1)*LV + r] = __float2half(f.y);
            Vt[(c4*4+2)*LV + r] = __float2half(f.z);
            Vt[(c4*4+3)*LV + r] = __float2half(f.w);
        }
        if (tid < BKT) mk[tid] = vl[kt*BKT + tid] ? 0.f : -1e30f;
        __syncthreads();

        // S = Q K^T  (16 q-rows × 64 keys per warp)
        float S[8][4];
        #pragma unroll
        for (int i=0;i<8;i++){ S[i][0]=0.f; S[i][1]=0.f; S[i][2]=0.f; S[i][3]=0.f; }
        #pragma unroll
        for (int ks=0; ks<HDc; ks+=16){
            unsigned af[4];
            af[0] = *(const unsigned*)&Qs[(wm+qr  )*LQ + ks + 2*qc    ];
            af[1] = *(const unsigned*)&Qs[(wm+qr+8)*LQ + ks + 2*qc    ];
            af[2] = *(const unsigned*)&Qs[(wm+qr  )*LQ + ks + 2*qc + 8];
            af[3] = *(const unsigned*)&Qs[(wm+qr+8)*LQ + ks + 2*qc + 8];
            #pragma unroll
            for (int ni=0; ni<8; ++ni){
                unsigned bf[2];
                bf[0] = *(const unsigned*)&Ks[(ni*8+qr)*LQ + ks + 2*qc    ];
                bf[1] = *(const unsigned*)&Ks[(ni*8+qr)*LQ + ks + 2*qc + 8];
                mma_f16(S[ni], af, bf);
            }
        }
        // mask + row max
        float mn0 = -3.4e38f, mn1 = -3.4e38f;
        #pragma unroll
        for (int ni=0; ni<8; ++ni){
            float a0 = mk[ni*8 + 2*qc], a1 = mk[ni*8 + 2*qc + 1];
            S[ni][0] += a0; S[ni][1] += a1; S[ni][2] += a0; S[ni][3] += a1;
            mn0 = fmaxf(mn0, fmaxf(S[ni][0], S[ni][1]));
            mn1 = fmaxf(mn1, fmaxf(S[ni][2], S[ni][3]));
        }
        mn0 = fmaxf(mn0, __shfl_xor_sync(0xffffffffu, mn0, 1));
        mn0 = fmaxf(mn0, __shfl_xor_sync(0xffffffffu, mn0, 2));
        mn1 = fmaxf(mn1, __shfl_xor_sync(0xffffffffu, mn1, 1));
        mn1 = fmaxf(mn1, __shfl_xor_sync(0xffffffffu, mn1, 2));
        float mN0 = fmaxf(mr0, mn0), mN1 = fmaxf(mr1, mn1);
        float f0 = __expf(mr0 - mN0), f1 = __expf(mr1 - mN1);
        lr0 *= f0; lr1 *= f1;
        #pragma unroll
        for (int no=0; no<8; ++no){
            O[no][0]*=f0; O[no][1]*=f0; O[no][2]*=f1; O[no][3]*=f1;
        }
        mr0 = mN0; mr1 = mN1;
        // P = exp(S - m), pack to fp16 A-fragments
        unsigned ph[8][2];
        #pragma unroll
        for (int ni=0; ni<8; ++ni){
            float p0 = __expf(S[ni][0]-mr0), p1 = __expf(S[ni][1]-mr0);
            float p2 = __expf(S[ni][2]-mr1), p3 = __expf(S[ni][3]-mr1);
            lr0 += p0+p1; lr1 += p2+p3;
            ph[ni][0] = pack_h2(p0, p1);
            ph[ni][1] = pack_h2(p2, p3);
        }
        // O += P V
        #pragma unroll
        for (int st=0; st<4; ++st){
            unsigned af[4] = { ph[2*st][0], ph[2*st][1], ph[2*st+1][0], ph[2*st+1][1] };
            #pragma unroll
            for (int no=0; no<8; ++no){
                unsigned bf[2];
                bf[0] = *(const unsigned*)&Vt[(no*8+qr)*LV + st*16 + 2*qc    ];
                bf[1] = *(const unsigned*)&Vt[(no*8+qr)*LV + st*16 + 2*qc + 8];
                mma_f16(O[no], af, bf);
            }
        }
    }

    // final normalize (row sums live across the 4 qc lanes)
    lr0 += __shfl_xor_sync(0xffffffffu, lr0, 1);
    lr0 += __shfl_xor_sync(0xffffffffu, lr0, 2);
    lr1 += __shfl_xor_sync(0xffffffffu, lr1, 1);
    lr1 += __shfl_xor_sync(0xffffffffu, lr1, 2);
    float i0 = 1.f/lr0, i1 = 1.f/lr1;
    #pragma unroll
    for (int no=0; no<8; ++no){
        int gm0 = m0 + wm + qr, gn = no*8 + 2*qc;
        *(float2*)(ob + (long long)gm0*ldo + gn)     = make_float2(O[no][0]*i0, O[no][1]*i0);
        *(float2*)(ob + (long long)(gm0+8)*ldo + gn) = make_float2(O[no][2]*i1, O[no][3]*i1);
    }
}

// ---------------- small fused kernels ----------------
__global__ void film_gemv(const float* __restrict__ mod, const float* __restrict__ W,
                          const float* __restrict__ bias, float* __restrict__ out,
                          int Bn, int N2, int K){
    int warp = (blockIdx.x*blockDim.x + threadIdx.x) >> 5;
    int lane = threadIdx.x & 31;
    if (warp >= Bn*N2) return;
    int b = warp / N2, n = warp % N2;
    const float* a = mod + (long)b*K;
    const float* w = W   + (long)n*K;
    float acc=0.f;
    for (int k=lane; k<K; k+=32) acc = fmaf(a[k], w[k], acc);
    acc = warp_sum(acc);
    if (lane==0) out[warp] = acc + bias[n];
}

__global__ void rmsnorm_kernel(const float* __restrict__ x, const float* __restrict__ w,
                               float* __restrict__ y, int Dd,
                               const float* __restrict__ filmss, int S){
    long row = blockIdx.x;
    const float* xr = x + row*Dd;
    float ss = 0.f;
    for (int j = threadIdx.x; j < Dd; j += blockDim.x){ float v = xr[j]; ss = fmaf(v,v,ss); }
    ss = block_sum(ss);
    float r = rsqrtf(ss/(float)Dd + 1e-6f);
    if (filmss){
        int b = (int)(row / S);
        const float* sc = filmss + (long)b*2*Dd;
        for (int j = threadIdx.x; j < Dd; j += blockDim.x){
            float v = xr[j]*r*w[j];
            y[row*Dd + j] = v*(1.f + 0.1f*tanhf(sc[j])) + sc[Dd + j];
        }
    } else {
        for (int j = threadIdx.x; j < Dd; j += blockDim.x)
            y[row*Dd + j] = xr[j]*r*w[j];
    }
}

__global__ void rope_kernel(float* __restrict__ qkv){
    long idx = (long)blockIdx.x*blockDim.x + threadIdx.x;
    const long total = (long)BSc * Hc * (HDc/2);
    if (idx >= total) return;
    int i = idx % (HDc/2);
    int h = (idx / (HDc/2)) % Hc;
    long row = idx / ((HDc/2)*Hc);
    int s = (int)(row % Sc);
    float freq = expf(-logf(10000.f) * (float)(2*i) / (float)HDc);
    float ang = (float)s * freq;
    float c = cosf(ang), sn = sinf(ang);
    float* qb = qkv + row*(3*Dc) + h*HDc;
    float e = qb[2*i], o = qb[2*i+1];
    qb[2*i]   = e*c - o*sn;
    qb[2*i+1] = e*sn + o*c;
    float* kb = qb + Dc;
    e = kb[2*i]; o = kb[2*i+1];
    kb[2*i]   = e*c - o*sn;
    kb[2*i+1] = e*sn + o*c;
}

__global__ void gate_fuse_kernel(const float* __restrict__ t2, const float* __restrict__ gacc,
                                 const float* __restrict__ gate_b, const float* __restrict__ upd,
                                 float* __restrict__ t3, long n, int Dd){
    long i = (long)blockIdx.x*blockDim.x + threadIdx.x;
    if (i >= n) return;
    float g = gacc[i] + gate_b[i % Dd];
    float sg = 1.f / (1.f + expf(-g));
    t3[i] = t2[i] + sg * upd[i];
}

__global__ void silu_kernel(const float* __restrict__ gu, float* __restrict__ act, long rows){
    long i = (long)blockIdx.x*blockDim.x + threadIdx.x;
    long n = rows * HIDc;
    if (i >= n) return;
    long m = i / HIDc; int j = (int)(i % HIDc);
    float g = gu[m*(2*HIDc) + j];
    float v = gu[m*(2*HIDc) + HIDc + j];
    float s = g / (1.f + expf(-g));
    act[i] = s * v;
}

// ---------------- host-side launch helpers ----------------
static inline void tc_nt(const float* A,const float* B,float* C,
    int M,int N,int K,int lda,int ldb,int ldc,
    float alpha,const float* bias,const float* res,int ldres,
    const float* rs,int rsdiv,int accum)
{
    dim3 g(N/128, M/128, 1);
    gemm_h16<2,4><<<g,256>>>(A,B,C,M,N,K,lda,ldb,ldc,
        alpha,bias,res,ldres,rs,rsdiv,accum);
}

extern "C" void kernel_launch(void* const* d_in, const int* in_sizes, int n_in,
                              void* d_out, int out_size)
{
    const float* tokens     = (const float*)d_in[0];
    const float* seq_tokens = (const float*)d_in[1];
    const float* modulation = (const float*)d_in[2];
    const float* attn_norm_w= (const float*)d_in[3];
    const float* qkv_w      = (const float*)d_in[4];
    const float* qkv_b      = (const float*)d_in[5];
    const float* out_w      = (const float*)d_in[6];
    const float* out_b      = (const float*)d_in[7];
    const float* film_w     = (const float*)d_in[8];
    const float* film_b     = (const float*)d_in[9];
    const float* sq_norm_w  = (const float*)d_in[10];
    const float* s_norm_w   = (const float*)d_in[11];
    const float* mha_in_w   = (const float*)d_in[12];
    const float* mha_in_b   = (const float*)d_in[13];
    const float* mha_out_w  = (const float*)d_in[14];
    const float* mha_out_b  = (const float*)d_in[15];
    const float* gate_w     = (const float*)d_in[16];
    const float* gate_b     = (const float*)d_in[17];
    const float* ffn_norm_w = (const float*)d_in[18];
    const float* gu_w       = (const float*)d_in[19];
    const float* gu_b       = (const float*)d_in[20];
    const float* down_w     = (const float*)d_in[21];
    const float* down_b     = (const float*)d_in[22];
    const void*  padding_mask = d_in[23];
    const void*  seq_mask     = d_in[24];
    float* out = (float*)d_out;

    float *p_x,*p_qkv,*p_ctx,*p_t2,*p_qn,*p_sn,*p_cq,*p_ckv,*p_upd,*p_gacc,*p_t3,*p_gu,*p_act,*p_ss,*p_vrow;
    int *p_valid,*p_svalid;
    cudaGetSymbolAddress((void**)&p_x, g_x);
    cudaGetSymbolAddress((void**)&p_qkv, g_qkv);
    cudaGetSymbolAddress((void**)&p_ctx, g_ctx);
    cudaGetSymbolAddress((void**)&p_t2, g_t2);
    cudaGetSymbolAddress((void**)&p_qn, g_qn);
    cudaGetSymbolAddress((void**)&p_sn, g_sn);
    cudaGetSymbolAddress((void**)&p_cq, g_cq);
    cudaGetSymbolAddress((void**)&p_ckv, g_ckv);
    cudaGetSymbolAddress((void**)&p_upd, g_upd);
    cudaGetSymbolAddress((void**)&p_gacc, g_gacc);
    cudaGetSymbolAddress((void**)&p_t3, g_t3);
    cudaGetSymbolAddress((void**)&p_gu, g_gu);
    cudaGetSymbolAddress((void**)&p_act, g_act);
    cudaGetSymbolAddress((void**)&p_ss, g_ss);
    cudaGetSymbolAddress((void**)&p_vrow, g_vrow);
    cudaGetSymbolAddress((void**)&p_valid, g_valid);
    cudaGetSymbolAddress((void**)&p_svalid, g_svalid);

    // 1) mask layout detect + decode
    detect_mask_layout<<<(Bc*Sc+255)/256,256>>>((const unsigned char*)padding_mask, Bc*Sc, 0);
    detect_mask_layout<<<(Bc*Lc+255)/256,256>>>((const unsigned char*)seq_mask,     Bc*Lc, 1);
    decode_mask<<<Bc,256>>>(padding_mask, Sc, 0, p_valid,  nullptr);
    decode_mask<<<Bc,256>>>(seq_mask,     Lc, 1, p_svalid, p_vrow);

    // 2) FiLM params: [B, 2D]
    film_gemv<<<(Bc*2*Dc*32 + 255)/256, 256>>>(modulation, film_w, film_b, p_ss, Bc, 2*Dc, Dc);

    // 3) x = FiLM(rmsnorm(tokens))
    rmsnorm_kernel<<<BSc,256>>>(tokens, attn_norm_w, p_x, Dc, p_ss, Sc);

    // 4) qkv = x @ qkv_w^T + qkv_b
    tc_nt(p_x, qkv_w, p_qkv, BSc, 3*Dc, Dc, Dc, Dc, 3*Dc,
          1.f, qkv_b, nullptr, 0, nullptr, 1, 0);

    // 5) RoPE on q,k
    rope_kernel<<<((long)BSc*Hc*(HDc/2) + 255)/256, 256>>>(p_qkv);

    // 6-8) fused self-attention (scores + masked softmax + PV)
    { dim3 g(Sc/128, Bc*Hc);
      flash_attn<<<g,256>>>(p_qkv, p_qkv + Dc, p_qkv + 2*Dc, p_ctx, p_valid,
                            3*Dc, 3*Dc, 3*Dc, Dc, Sc, Sc); }

    // 9) tokens2 = tokens + ctx @ out_w^T + out_b
    tc_nt(p_ctx, out_w, p_t2, BSc, Dc, Dc, Dc, Dc, Dc,
          1.f, out_b, tokens, Dc, nullptr, 1, 0);

    // 10) query / src norms
    rmsnorm_kernel<<<BSc,256>>>(p_t2, sq_norm_w, p_qn, Dc, nullptr, Sc);
    rmsnorm_kernel<<<BLc,256>>>(seq_tokens, s_norm_w, p_sn, Dc, nullptr, Lc);

    // 11) cq = qn @ wq^T + bq ; ckv = sn @ [wk;wv]^T + [bk;bv]
    tc_nt(p_qn, mha_in_w, p_cq, BSc, Dc, Dc, Dc, Dc, Dc,
          1.f, mha_in_b, nullptr, 0, nullptr, 1, 0);
    tc_nt(p_sn, mha_in_w + (long long)Dc*Dc, p_ckv, BLc, 2*Dc, Dc, Dc, Dc, 2*Dc,
          1.f, mha_in_b + Dc, nullptr, 0, nullptr, 1, 0);

    // 12-14) fused cross-attention
    { dim3 g(Sc/128, Bc*Hc);
      flash_attn<<<g,256>>>(p_cq, p_ckv, p_ckv + Dc, p_ctx, p_svalid,
                            Dc, 2*Dc, 2*Dc, Dc, Sc, Lc); }

    // 15) update = (ctx2 @ mha_out_w^T + mha_out_b) * valid_rows[b]
    tc_nt(p_ctx, mha_out_w, p_upd, BSc, Dc, Dc, Dc, Dc, Dc,
          1.f, mha_out_b, nullptr, 0, p_vrow, Sc, 0);

    // 16) gate pre-activation
    tc_nt(p_t2,  gate_w,      p_gacc, BSc, Dc, Dc, Dc, 2*Dc, Dc,
          1.f, nullptr, nullptr, 0, nullptr, 1, 0);
    tc_nt(p_upd, gate_w + Dc, p_gacc, BSc, Dc, Dc, Dc, 2*Dc, Dc,
          1.f, nullptr, nullptr, 0, nullptr, 1, 1);

    // 17) t3 = t2 + sigmoid(gacc + gate_b) * upd
    gate_fuse_kernel<<<((long)BSc*Dc + 255)/256, 256>>>(p_t2, p_gacc, gate_b, p_upd, p_t3,
                                                        (long)BSc*Dc, Dc);

    // 18) h = rmsnorm(t3, ffn_norm_w)
    rmsnorm_kernel<<<BSc,256>>>(p_t3, ffn_norm_w, p_x, Dc, nullptr, Sc);

    // 19) gu = h @ gu_w^T + gu_b
    tc_nt(p_x, gu_w, p_gu, BSc, 2*HIDc, Dc, Dc, Dc, 2*HIDc,
          1.f, gu_b, nullptr, 0, nullptr, 1, 0);

    // 20) act = silu(g) * val
    silu_kernel<<<((long)BSc*HIDc + 255)/256, 256>>>(p_gu, p_act, BSc);

    // 21) out = t3 + act @ down_w^T + down_b
    tc_nt(p_act, down_w, out, BSc, Dc, HIDc, HIDc, HIDc, Dc,
          1.f, down_b, p_t3, Dc, nullptr, 1, 0);
}

// round 7
// speedup vs baseline: 1.8442x; 1.3334x over previous
#include <cuda_runtime.h>
#include <cuda_bf16.h>
#include <cuda_fp16.h>
#include <math.h>

// Problem constants: B=4, S=1024, L=1024, D=1024, H=16, HD=64, HIDDEN=4096
#define Bc 4
#define Sc 1024
#define Lc 1024
#define Dc 1024
#define Hc 16
#define HDc 64
#define HIDc 4096
#define BSc (Bc*Sc)
#define BLc (Bc*Lc)

// ---------------- scratch (static device globals) ----------------
// fp32
__device__ float g_t2 [BSc*Dc];
__device__ float g_upd[BSc*Dc];
__device__ float g_t3 [BSc*Dc];
__device__ float g_ss [Bc*2*Dc];
__device__ int   g_valid [BSc];
__device__ int   g_svalid[BLc];
__device__ float g_vrow  [Bc];
__device__ int   g_layout[2];
// fp16 activations
__device__ __half h_x   [BSc*Dc];
__device__ __half h_qkv [BSc*3*Dc];
__device__ __half h_ctx [BSc*Dc];
__device__ __half h_qn  [BSc*Dc];
__device__ __half h_sn  [BLc*Dc];
__device__ __half h_cq  [BSc*Dc];
__device__ __half h_ckv [BLc*2*Dc];
__device__ __half h_gcat[BSc*2*Dc];
__device__ __half h_h   [BSc*Dc];
__device__ __half h_g   [(size_t)BSc*HIDc];
__device__ __half h_act [(size_t)BSc*HIDc];
// fp16 weights
__device__ __half h_qkvw  [3*Dc*Dc];
__device__ __half h_outw  [Dc*Dc];
__device__ __half h_mhainw[3*Dc*Dc];
__device__ __half h_mhaoutw[Dc*Dc];
__device__ __half h_gatew [Dc*2*Dc];
__device__ __half h_guw   [2*HIDc*Dc];
__device__ __half h_downw [Dc*HIDc];

// ---------------- reductions ----------------
__device__ __forceinline__ float warp_sum(float v){
    #pragma unroll
    for (int o=16;o>0;o>>=1) v += __shfl_xor_sync(0xffffffffu, v, o);
    return v;
}
__device__ float block_sum(float v){
    __shared__ float red[33];
    __syncthreads();
    int lane = threadIdx.x & 31, wid = threadIdx.x >> 5;
    v = warp_sum(v);
    if (lane==0) red[wid] = v;
    __syncthreads();
    int nw = blockDim.x >> 5;
    float r = (threadIdx.x < nw) ? red[threadIdx.x] : 0.f;
    if (wid==0){ r = warp_sum(r); if (lane==0) red[32] = r; }
    __syncthreads();
    return red[32];
}

// ---------------- mask layout detection + decode ----------------
__global__ void detect_mask_layout(const unsigned char* __restrict__ p, int n, int slot){
    int i = blockIdx.x*blockDim.x + threadIdx.x;
    if (i >= n) return;
    unsigned char v = p[i];
    if (v != 0 && v != 1) atomicOr(&g_layout[slot], 2);
    else if (v == 1 && (i & 3) != 0) atomicOr(&g_layout[slot], 1);
}
__global__ void decode_mask(const void* __restrict__ p, int cols, int slot,
                            int* __restrict__ valid, float* __restrict__ vrow){
    int b = blockIdx.x;
    int layout = g_layout[slot];
    int mode = (layout & 2) ? 2 : ((layout & 1) ? 1 : 0);
    __shared__ int s_anyzero;
    if (threadIdx.x==0) s_anyzero = 0;
    __syncthreads();
    int local_any = 0;
    for (int j = threadIdx.x; j < cols; j += blockDim.x){
        long idx = (long)b*cols + j;
        int m;
        if (mode==1)      m = ((const unsigned char*)p)[idx] != 0;
        else if (mode==2) m = ((const float*)p)[idx] != 0.f;
        else              m = ((const int*)p)[idx] != 0;
        valid[idx] = m;
        if (!m) local_any = 1;
    }
    if (local_any) atomicOr(&s_anyzero, 1);
    __syncthreads();
    int anyz = s_anyzero;
    for (int j = threadIdx.x; j < cols; j += blockDim.x){
        long idx = (long)b*cols + j;
        valid[idx] = anyz ? (1 - valid[idx]) : 1;
    }
    if (vrow && threadIdx.x==0) vrow[b] = anyz ? 1.f : 0.f;
}

// ---------------- helpers ----------------
__device__ __forceinline__ void mma_f16(float* c, const unsigned* a, const unsigned* b){
    asm volatile("mma.sync.aligned.m16n8k16.row.col.f32.f16.f16.f32 "
        "{%0,%1,%2,%3}, {%4,%5,%6,%7}, {%8,%9}, {%0,%1,%2,%3};"
        : "+f"(c[0]),"+f"(c[1]),"+f"(c[2]),"+f"(c[3])
        : "r"(a[0]),"r"(a[1]),"r"(a[2]),"r"(a[3]), "r"(b[0]),"r"(b[1]));
}
__device__ __forceinline__ unsigned pack_h2(float x, float y){
    __half2 h = __floats2half2_rn(x, y);
    return *(unsigned*)&h;
}
__device__ __forceinline__ unsigned smem_u32(const void* p){
    return (unsigned)__cvta_generic_to_shared(p);
}
__device__ __forceinline__ void cp16(unsigned dst, const void* src){
    asm volatile("cp.async.cg.shared.global [%0], [%1], 16;" :: "r"(dst), "l"(src) : "memory");
}

// ---------------- fp16 cp.async double-buffered NT GEMM ----------------
// A [M,K] fp16 row-major, B [N,K] fp16 row-major. M%128==0, N%128==0, K%32==0.
// epi=0: v=alpha*acc(+bias)(*rowscale)(+residual); store C32/C16
// epi=1 (gate): v=acc+bias; out = residual + sigmoid(v)*aux32   -> t3
// epi=2 (silu): v=acc+bias; g=aux16; out = silu(g)*v
template<int NWM,int NWN>
__global__ __launch_bounds__(256)
void gemm_h16p(const __half* __restrict__ A, const __half* __restrict__ B,
               float* __restrict__ C32, __half* __restrict__ C16,
               int M,int N,int K,int lda,int ldb,int ldc32,int ldc16,
               float alpha,
               const float* __restrict__ bias,
               const float* __restrict__ residual,int ldres,
               const float* __restrict__ rowscale,int rsDiv,
               int epi, const void* __restrict__ aux, int ldaux)
{
    constexpr int BM=128, BN=128, BK=32, STAGES=2;
    constexpr int WM=BM/NWM, WN=BN/NWN;
    constexpr int MI=WM/16, NI=WN/8;
    constexpr int LDS=BK+8;   // 40 halves per row (80B: conflict-free frag LDS)

    __shared__ __align__(16) __half As[STAGES][BM*LDS];
    __shared__ __align__(16) __half Bs[STAGES][BN*LDS];

    const int tid=threadIdx.x, lane=tid&31, warp=tid>>5;
    const int m0=blockIdx.y*BM, n0=blockIdx.x*BN;
    const int wm0=(warp/NWN)*WM, wn0=(warp%NWN)*WN;
    const int qr=lane>>2, qc=lane&3;

    float acc[MI][NI][4];
    #pragma unroll
    for (int i=0;i<MI;i++)
        #pragma unroll
        for (int j=0;j<NI;j++)
            #pragma unroll
            for (int r=0;r<4;r++) acc[i][j][r]=0.f;

    const int nk = K/BK;

    auto issue = [&](int s, int kt){
        int k0 = kt*BK;
        #pragma unroll
        for (int h2=0; h2<2; ++h2){
            int c = tid + h2*256;
            int r = c>>2, col = c&3;
            cp16(smem_u32(&As[s][r*LDS + col*8]),
                 A + (long long)(m0+r)*lda + k0 + col*8);
            cp16(smem_u32(&Bs[s][r*LDS + col*8]),
                 B + (long long)(n0+r)*ldb + k0 + col*8);
        }
    };

    issue(0, 0);
    asm volatile("cp.async.commit_group;" ::: "memory");

    for (int kt=0; kt<nk; ++kt){
        asm volatile("cp.async.wait_group 0;" ::: "memory");
        __syncthreads();
        if (kt+1 < nk) issue((kt+1)&1, kt+1);
        asm volatile("cp.async.commit_group;" ::: "memory");

        const __half* as = As[kt&1];
        const __half* bs = Bs[kt&1];
        #pragma unroll
        for (int ks=0; ks<BK; ks+=16){
            unsigned af[MI][4], bf[NI][2];
            #pragma unroll
            for (int mi=0; mi<MI; ++mi){
                int mr = wm0 + mi*16 + qr;
                af[mi][0] = *(const unsigned*)&as[ mr   *LDS + ks + 2*qc    ];
                af[mi][1] = *(const unsigned*)&as[(mr+8)*LDS + ks + 2*qc    ];
                af[mi][2] = *(const unsigned*)&as[ mr   *LDS + ks + 2*qc + 8];
                af[mi][3] = *(const unsigned*)&as[(mr+8)*LDS + ks + 2*qc + 8];
            }
            #pragma unroll
            for (int ni=0; ni<NI; ++ni){
                int nc = wn0 + ni*8 + qr;
                bf[ni][0] = *(const unsigned*)&bs[nc*LDS + ks + 2*qc    ];
                bf[ni][1] = *(const unsigned*)&bs[nc*LDS + ks + 2*qc + 8];
            }
            #pragma unroll
            for (int mi=0; mi<MI; ++mi)
                #pragma unroll
                for (int ni=0; ni<NI; ++ni)
                    mma_f16(acc[mi][ni], af[mi], bf[ni]);
        }
        __syncthreads();
    }

    // epilogue
    #pragma unroll
    for (int mi=0; mi<MI; ++mi){
        #pragma unroll
        for (int hf=0; hf<2; ++hf){
            int gm = m0 + wm0 + mi*16 + qr + hf*8;
            float rs = rowscale ? rowscale[gm/rsDiv] : 1.f;
            #pragma unroll
            for (int ni=0; ni<NI; ++ni){
                int gn = n0 + wn0 + ni*8 + qc*2;
                float v0 = alpha*acc[mi][ni][hf*2+0];
                float v1 = alpha*acc[mi][ni][hf*2+1];
                if (bias){ v0 += bias[gn]; v1 += bias[gn+1]; }
                if (epi==1){
                    const float* upd = (const float*)aux;
                    float2 r = *(const float2*)(residual + (long long)gm*ldres + gn);
                    float2 u = *(const float2*)(upd + (long long)gm*ldaux + gn);
                    v0 = r.x + u.x/(1.f+__expf(-v0));
                    v1 = r.y + u.y/(1.f+__expf(-v1));
                } else if (epi==2){
                    const __half* gh = (const __half*)aux;
                    __half2 gg = *(const __half2*)(gh + (long long)gm*ldaux + gn);
                    float g0 = __low2float(gg), g1 = __high2float(gg);
                    v0 *= g0/(1.f+__expf(-g0));
                    v1 *= g1/(1.f+__expf(-g1));
                } else {
                    v0 *= rs; v1 *= rs;
                    if (residual){
                        float2 r = *(const float2*)(residual + (long long)gm*ldres + gn);
                        v0 += r.x; v1 += r.y;
                    }
                }
                if (C32)
                    *(float2*)(C32 + (long long)gm*ldc32 + gn) = make_float2(v0, v1);
                if (C16)
                    *(__half2*)(C16 + (long long)gm*ldc16 + gn) = __floats2half2_rn(v0, v1);
            }
        }
    }
}

// ---------------- fused flash attention (fp16 in / fp16 out) ----------------
__global__ __launch_bounds__(256)
void flash_attn(const __half* __restrict__ q, const __half* __restrict__ k,
                const __half* __restrict__ v, __half* __restrict__ o,
                const int* __restrict__ valid,
                int ldq, int ldk, int ldv, int ldo,
                int qrows, int krows)
{
    constexpr int BQ = 128, BKT = 64;
    constexpr int LQ = HDc + 8;      // 72 halves
    constexpr int LV = BKT + 8;      // 72 halves
    __shared__ __align__(16) __half Qs[BQ*LQ];
    __shared__ __align__(16) __half Ks[BKT*LQ];
    __shared__ __align__(16) __half Vt[HDc*LV];
    __shared__ float  mk[BKT];

    const int z = blockIdx.y;
    const int b = z / Hc, h = z % Hc;
    const __half* qb = q + (long long)b*qrows*ldq + h*HDc;
    const __half* kb = k + (long long)b*krows*ldk + h*HDc;
    const __half* vb = v + (long long)b*krows*ldv + h*HDc;
    __half*       ob = o + (long long)b*qrows*ldo + h*HDc;
    const int*    vl = valid + (long)b*krows;

    const int tid = threadIdx.x, lane = tid & 31, warp = tid >> 5;
    const int qr = lane >> 2, qc = lane & 3;
    const int m0 = blockIdx.x*BQ;
    const int wm = warp*16;
    const __half2 sc2 = __float2half2_rn(0.125f);

    // Q tile, scaled by 1/8
    for (int i = tid; i < BQ*(HDc/8); i += 256){
        int r = i>>3, c8 = i&7;
        uint4 u = *(const uint4*)(qb + (long long)(m0+r)*ldq + c8*8);
        __half2* hp = (__half2*)&u;
        hp[0]=__hmul2(hp[0],sc2); hp[1]=__hmul2(hp[1],sc2);
        hp[2]=__hmul2(hp[2],sc2); hp[3]=__hmul2(hp[3],sc2);
        *(uint4*)&Qs[r*LQ + c8*8] = u;
    }

    float mr0 = -3.4e38f, mr1 = -3.4e38f, lr0 = 0.f, lr1 = 0.f;
    float O[8][4];
    #pragma unroll
    for (int i=0;i<8;i++){ O[i][0]=0.f; O[i][1]=0.f; O[i][2]=0.f; O[i][3]=0.f; }

    const int nkt = krows / BKT;
    for (int kt=0; kt<nkt; ++kt){
        __syncthreads();
        for (int i = tid; i < BKT*(HDc/8); i += 256){
            int r = i>>3, c8 = i&7;
            *(uint4*)&Ks[r*LQ + c8*8] =
                *(const uint4*)(kb + (long long)(kt*BKT+r)*ldk + c8*8);
        }
        for (int i = tid; i < BKT*(HDc/8); i += 256){
            int r = i>>3, c8 = i&7;
            uint4 u = *(const uint4*)(vb + (long long)(kt*BKT+r)*ldv + c8*8);
            const __half* hv = (const __half*)&u;
            #pragma unroll
            for (int j=0;j<8;j++) Vt[(c8*8+j)*LV + r] = hv[j];
        }
        if (tid < BKT) mk[tid] = vl[kt*BKT + tid] ? 0.f : -1e30f;
        __syncthreads();

        // S = Q K^T
        float S[8][4];
        #pragma unroll
        for (int i=0;i<8;i++){ S[i][0]=0.f; S[i][1]=0.f; S[i][2]=0.f; S[i][3]=0.f; }
        #pragma unroll
        for (int ks=0; ks<HDc; ks+=16){
            unsigned af[4];
            af[0] = *(const unsigned*)&Qs[(wm+qr  )*LQ + ks + 2*qc    ];
            af[1] = *(const unsigned*)&Qs[(wm+qr+8)*LQ + ks + 2*qc    ];
            af[2] = *(const unsigned*)&Qs[(wm+qr  )*LQ + ks + 2*qc + 8];
            af[3] = *(const unsigned*)&Qs[(wm+qr+8)*LQ + ks + 2*qc + 8];
            #pragma unroll
            for (int ni=0; ni<8; ++ni){
                unsigned bf[2];
                bf[0] = *(const unsigned*)&Ks[(ni*8+qr)*LQ + ks + 2*qc    ];
                bf[1] = *(const unsigned*)&Ks[(ni*8+qr)*LQ + ks + 2*qc + 8];
                mma_f16(S[ni], af, bf);
            }
        }
        // mask + online softmax
        float mn0 = -3.4e38f, mn1 = -3.4e38f;
        #pragma unroll
        for (int ni=0; ni<8; ++ni){
            float a0 = mk[ni*8 + 2*qc], a1 = mk[ni*8 + 2*qc + 1];
            S[ni][0] += a0; S[ni][1] += a1; S[ni][2] += a0; S[ni][3] += a1;
            mn0 = fmaxf(mn0, fmaxf(S[ni][0], S[ni][1]));
            mn1 = fmaxf(mn1, fmaxf(S[ni][2], S[ni][3]));
        }
        mn0 = fmaxf(mn0, __shfl_xor_sync(0xffffffffu, mn0, 1));
        mn0 = fmaxf(mn0, __shfl_xor_sync(0xffffffffu, mn0, 2));
        mn1 = fmaxf(mn1, __shfl_xor_sync(0xffffffffu, mn1, 1));
        mn1 = fmaxf(mn1, __shfl_xor_sync(0xffffffffu, mn1, 2));
        float mN0 = fmaxf(mr0, mn0), mN1 = fmaxf(mr1, mn1);
        float f0 = __expf(mr0 - mN0), f1 = __expf(mr1 - mN1);
        lr0 *= f0; lr1 *= f1;
        #pragma unroll
        for (int no=0; no<8; ++no){
            O[no][0]*=f0; O[no][1]*=f0; O[no][2]*=f1; O[no][3]*=f1;
        }
        mr0 = mN0; mr1 = mN1;
        unsigned ph[8][2];
        #pragma unroll
        for (int ni=0; ni<8; ++ni){
            float p0 = __expf(S[ni][0]-mr0), p1 = __expf(S[ni][1]-mr0);
            float p2 = __expf(S[ni][2]-mr1), p3 = __expf(S[ni][3]-mr1);
            lr0 += p0+p1; lr1 += p2+p3;
            ph[ni][0] = pack_h2(p0, p1);
            ph[ni][1] = pack_h2(p2, p3);
        }
        #pragma unroll
        for (int st=0; st<4; ++st){
            unsigned af[4] = { ph[2*st][0], ph[2*st][1], ph[2*st+1][0], ph[2*st+1][1] };
            #pragma unroll
            for (int no=0; no<8; ++no){
                unsigned bf[2];
                bf[0] = *(const unsigned*)&Vt[(no*8+qr)*LV + st*16 + 2*qc    ];
                bf[1] = *(const unsigned*)&Vt[(no*8+qr)*LV + st*16 + 2*qc + 8];
                mma_f16(O[no], af, bf);
            }
        }
    }

    lr0 += __shfl_xor_sync(0xffffffffu, lr0, 1);
    lr0 += __shfl_xor_sync(0xffffffffu, lr0, 2);
    lr1 += __shfl_xor_sync(0xffffffffu, lr1, 1);
    lr1 += __shfl_xor_sync(0xffffffffu, lr1, 2);
    float i0 = 1.f/lr0, i1 = 1.f/lr1;
    #pragma unroll
    for (int no=0; no<8; ++no){
        int gm0 = m0 + wm + qr, gn = no*8 + 2*qc;
        *(__half2*)(ob + (long long)gm0*ldo + gn)     = __floats2half2_rn(O[no][0]*i0, O[no][1]*i0);
        *(__half2*)(ob + (long long)(gm0+8)*ldo + gn) = __floats2half2_rn(O[no][2]*i1, O[no][3]*i1);
    }
}

// ---------------- small kernels ----------------
__global__ void cvt_f2h(const float* __restrict__ x, __half* __restrict__ y, long n){
    long i = ((long)blockIdx.x*blockDim.x + threadIdx.x)*4;
    if (i >= n) return;
    float4 f = *(const float4*)(x + i);
    *(__half2*)(y+i)   = __floats2half2_rn(f.x, f.y);
    *(__half2*)(y+i+2) = __floats2half2_rn(f.z, f.w);
}

__global__ void film_gemv(const float* __restrict__ mod, const float* __restrict__ W,
                          const float* __restrict__ bias, float* __restrict__ out,
                          int Bn, int N2, int K){
    int warp = (blockIdx.x*blockDim.x + threadIdx.x) >> 5;
    int lane = threadIdx.x & 31;
    if (warp >= Bn*N2) return;
    int b = warp / N2, n = warp % N2;
    const float* a = mod + (long)b*K;
    const float* w = W   + (long)n*K;
    float acc=0.f;
    for (int k=lane; k<K; k+=32) acc = fmaf(a[k], w[k], acc);
    acc = warp_sum(acc);
    if (lane==0) out[warp] = acc + bias[n];
}

// rmsnorm with fp16 output (+ optional FiLM)
__global__ void rmsnorm_h(const float* __restrict__ x, const float* __restrict__ w,
                          __half* __restrict__ y, int Dd,
                          const float* __restrict__ filmss, int S){
    long row = blockIdx.x;
    const float* xr = x + row*Dd;
    float ss = 0.f;
    for (int j = threadIdx.x; j < Dd; j += blockDim.x){ float v = xr[j]; ss = fmaf(v,v,ss); }
    ss = block_sum(ss);
    float r = rsqrtf(ss/(float)Dd + 1e-6f);
    if (filmss){
        int b = (int)(row / S);
        const float* sc = filmss + (long)b*2*Dd;
        for (int j = threadIdx.x; j < Dd; j += blockDim.x){
            float v = xr[j]*r*w[j];
            y[row*Dd + j] = __float2half(v*(1.f + 0.1f*tanhf(sc[j])) + sc[Dd + j]);
        }
    } else {
        for (int j = threadIdx.x; j < Dd; j += blockDim.x)
            y[row*Dd + j] = __float2half(xr[j]*r*w[j]);
    }
}

// RoPE in place on fp16 qkv (q cols [0,D), k cols [D,2D))
__global__ void rope_h(__half* __restrict__ qkv){
    long idx = (long)blockIdx.x*blockDim.x + threadIdx.x;
    const long total = (long)BSc * Hc * (HDc/2);
    if (idx >= total) return;
    int i = idx % (HDc/2);
    int h = (idx / (HDc/2)) % Hc;
    long row = idx / ((HDc/2)*Hc);
    int s = (int)(row % Sc);
    float freq = expf(-logf(10000.f) * (float)(2*i) / (float)HDc);
    float ang = (float)s * freq;
    float c = cosf(ang), sn = sinf(ang);
    __half2* qb = (__half2*)(qkv + row*(3*Dc) + h*HDc);
    float2 qv = __half22float2(qb[i]);
    qb[i] = __floats2half2_rn(qv.x*c - qv.y*sn, qv.x*sn + qv.y*c);
    __half2* kb = qb + Dc/2;
    float2 kv = __half22float2(kb[i]);
    kb[i] = __floats2half2_rn(kv.x*c - kv.y*sn, kv.x*sn + kv.y*c);
}

// ---------------- host helper ----------------
static inline void tc(const __half* A,const __half* B,float* C32,__half* C16,
    int M,int N,int K,int lda,int ldb,int ldc32,int ldc16,
    float alpha,const float* bias,const float* res,int ldres,
    const float* rs,int rsdiv,int epi,const void* aux,int ldaux)
{
    dim3 g(N/128, M/128);
    gemm_h16p<2,4><<<g,256>>>(A,B,C32,C16,M,N,K,lda,ldb,ldc32,ldc16,
        alpha,bias,res,ldres,rs,rsdiv,epi,aux,ldaux);
}

extern "C" void kernel_launch(void* const* d_in, const int* in_sizes, int n_in,
                              void* d_out, int out_size)
{
    const float* tokens     = (const float*)d_in[0];
    const float* seq_tokens = (const float*)d_in[1];
    const float* modulation = (const float*)d_in[2];
    const float* attn_norm_w= (const float*)d_in[3];
    const float* qkv_w      = (const float*)d_in[4];
    const float* qkv_b      = (const float*)d_in[5];
    const float* out_w      = (const float*)d_in[6];
    const float* out_b      = (const float*)d_in[7];
    const float* film_w     = (const float*)d_in[8];
    const float* film_b     = (const float*)d_in[9];
    const float* sq_norm_w  = (const float*)d_in[10];
    const float* s_norm_w   = (const float*)d_in[11];
    const float* mha_in_w   = (const float*)d_in[12];
    const float* mha_in_b   = (const float*)d_in[13];
    const float* mha_out_w  = (const float*)d_in[14];
    const float* mha_out_b  = (const float*)d_in[15];
    const float* gate_w     = (const float*)d_in[16];
    const float* gate_b     = (const float*)d_in[17];
    const float* ffn_norm_w = (const float*)d_in[18];
    const float* gu_w       = (const float*)d_in[19];
    const float* gu_b       = (const float*)d_in[20];
    const float* down_w     = (const float*)d_in[21];
    const float* down_b     = (const float*)d_in[22];
    const void*  padding_mask = d_in[23];
    const void*  seq_mask     = d_in[24];
    float* out = (float*)d_out;

    float *p_t2,*p_upd,*p_t3,*p_ss,*p_vrow;
    int *p_valid,*p_svalid;
    __half *p_x,*p_qkv,*p_ctx,*p_qn,*p_sn,*p_cq,*p_ckv,*p_gcat,*p_h,*p_g,*p_act;
    __half *p_qkvw,*p_outw,*p_mhainw,*p_mhaoutw,*p_gatew,*p_guw,*p_downw;
    cudaGetSymbolAddress((void**)&p_t2, g_t2);
    cudaGetSymbolAddress((void**)&p_upd, g_upd);
    cudaGetSymbolAddress((void**)&p_t3, g_t3);
    cudaGetSymbolAddress((void**)&p_ss, g_ss);
    cudaGetSymbolAddress((void**)&p_vrow, g_vrow);
    cudaGetSymbolAddress((void**)&p_valid, g_valid);
    cudaGetSymbolAddress((void**)&p_svalid, g_svalid);
    cudaGetSymbolAddress((void**)&p_x, h_x);
    cudaGetSymbolAddress((void**)&p_qkv, h_qkv);
    cudaGetSymbolAddress((void**)&p_ctx, h_ctx);
    cudaGetSymbolAddress((void**)&p_qn, h_qn);
    cudaGetSymbolAddress((void**)&p_sn, h_sn);
    cudaGetSymbolAddress((void**)&p_cq, h_cq);
    cudaGetSymbolAddress((void**)&p_ckv, h_ckv);
    cudaGetSymbolAddress((void**)&p_gcat, h_gcat);
    cudaGetSymbolAddress((void**)&p_h, h_h);
    cudaGetSymbolAddress((void**)&p_g, h_g);
    cudaGetSymbolAddress((void**)&p_act, h_act);
    cudaGetSymbolAddress((void**)&p_qkvw, h_qkvw);
    cudaGetSymbolAddress((void**)&p_outw, h_outw);
    cudaGetSymbolAddress((void**)&p_mhainw, h_mhainw);
    cudaGetSymbolAddress((void**)&p_mhaoutw, h_mhaoutw);
    cudaGetSymbolAddress((void**)&p_gatew, h_gatew);
    cudaGetSymbolAddress((void**)&p_guw, h_guw);
    cudaGetSymbolAddress((void**)&p_downw, h_downw);

    // 1) masks
    detect_mask_layout<<<(Bc*Sc+255)/256,256>>>((const unsigned char*)padding_mask, Bc*Sc, 0);
    detect_mask_layout<<<(Bc*Lc+255)/256,256>>>((const unsigned char*)seq_mask,     Bc*Lc, 1);
    decode_mask<<<Bc,256>>>(padding_mask, Sc, 0, p_valid,  nullptr);
    decode_mask<<<Bc,256>>>(seq_mask,     Lc, 1, p_svalid, p_vrow);

    // 2) weights -> fp16 (once per launch)
    cvt_f2h<<<(3*Dc*Dc/4+255)/256,256>>>(qkv_w,     p_qkvw,    (long)3*Dc*Dc);
    cvt_f2h<<<(Dc*Dc/4+255)/256,256>>>(out_w,       p_outw,    (long)Dc*Dc);
    cvt_f2h<<<(3*Dc*Dc/4+255)/256,256>>>(mha_in_w,  p_mhainw,  (long)3*Dc*Dc);
    cvt_f2h<<<(Dc*Dc/4+255)/256,256>>>(mha_out_w,   p_mhaoutw, (long)Dc*Dc);
    cvt_f2h<<<(Dc*2*Dc/4+255)/256,256>>>(gate_w,    p_gatew,   (long)Dc*2*Dc);
    cvt_f2h<<<((long)2*HIDc*Dc/4+255)/256,256>>>(gu_w, p_guw,  (long)2*HIDc*Dc);
    cvt_f2h<<<((long)Dc*HIDc/4+255)/256,256>>>(down_w, p_downw,(long)Dc*HIDc);

    // 3) FiLM params + first norm
    film_gemv<<<(Bc*2*Dc*32 + 255)/256, 256>>>(modulation, film_w, film_b, p_ss, Bc, 2*Dc, Dc);
    rmsnorm_h<<<BSc,256>>>(tokens, attn_norm_w, p_x, Dc, p_ss, Sc);

    // 4) qkv projection -> fp16
    tc(p_x, p_qkvw, nullptr, p_qkv, BSc, 3*Dc, Dc, Dc, Dc, 0, 3*Dc,
       1.f, qkv_b, nullptr, 0, nullptr, 1, 0, nullptr, 0);

    // 5) RoPE
    rope_h<<<((long)BSc*Hc*(HDc/2) + 255)/256, 256>>>(p_qkv);

    // 6) self attention
    { dim3 g(Sc/128, Bc*Hc);
      flash_attn<<<g,256>>>(p_qkv, p_qkv + Dc, p_qkv + 2*Dc, p_ctx, p_valid,
                            3*Dc, 3*Dc, 3*Dc, Dc, Sc, Sc); }

    // 7) out-proj: t2 = tokens + ctx@out_w^T + out_b  (fp32 + fp16 into gcat[:,0:D])
    tc(p_ctx, p_outw, p_t2, p_gcat, BSc, Dc, Dc, Dc, Dc, Dc, 2*Dc,
       1.f, out_b, tokens, Dc, nullptr, 1, 0, nullptr, 0);

    // 8) norms
    rmsnorm_h<<<BSc,256>>>(p_t2, sq_norm_w, p_qn, Dc, nullptr, Sc);
    rmsnorm_h<<<BLc,256>>>(seq_tokens, s_norm_w, p_sn, Dc, nullptr, Lc);

    // 9) cross projections
    tc(p_qn, p_mhainw, nullptr, p_cq, BSc, Dc, Dc, Dc, Dc, 0, Dc,
       1.f, mha_in_b, nullptr, 0, nullptr, 1, 0, nullptr, 0);
    tc(p_sn, p_mhainw + (long long)Dc*Dc, nullptr, p_ckv, BLc, 2*Dc, Dc, Dc, Dc, 0, 2*Dc,
       1.f, mha_in_b + Dc, nullptr, 0, nullptr, 1, 0, nullptr, 0);

    // 10) cross attention
    { dim3 g(Sc/128, Bc*Hc);
      flash_attn<<<g,256>>>(p_cq, p_ckv, p_ckv + Dc, p_ctx, p_svalid,
                            Dc, 2*Dc, 2*Dc, Dc, Sc, Lc); }

    // 11) mha-out: upd = (ctx2@W^T + b) * vrow  (fp32 + fp16 into gcat[:,D:2D])
    tc(p_ctx, p_mhaoutw, p_upd, p_gcat + Dc, BSc, Dc, Dc, Dc, Dc, Dc, 2*Dc,
       1.f, mha_out_b, nullptr, 0, p_vrow, Sc, 0, nullptr, 0);

    // 12) fused gate: t3 = t2 + sigmoid([t2|upd]@gate_w^T + gate_b) * upd
    tc(p_gcat, p_gatew, p_t3, nullptr, BSc, Dc, 2*Dc, 2*Dc, 2*Dc, Dc, 0,
       1.f, gate_b, p_t2, Dc, nullptr, 1, 1, p_upd, Dc);

    // 13) ffn norm
    rmsnorm_h<<<BSc,256>>>(p_t3, ffn_norm_w, p_h, Dc, nullptr, Sc);

    // 14) g = h@gu_w[0:HID]^T + b ; act = silu(g) * (h@gu_w[HID:]^T + b)
    tc(p_h, p_guw, nullptr, p_g, BSc, HIDc, Dc, Dc, Dc, 0, HIDc,
       1.f, gu_b, nullptr, 0, nullptr, 1, 0, nullptr, 0);
    tc(p_h, p_guw + (long long)HIDc*Dc, nullptr, p_act, BSc, HIDc, Dc, Dc, Dc, 0, HIDc,
       1.f, gu_b + HIDc, nullptr, 0, nullptr, 1, 2, p_g, HIDc);

    // 15) out = t3 + act@down_w^T + down_b
    tc(p_act, p_downw, out, nullptr, BSc, Dc, HIDc, HIDc, HIDc, Dc, 0,
       1.f, down_b, p_t3, Dc, nullptr, 1, 0, nullptr, 0);
}

// round 8
// speedup vs baseline: 1.8501x; 1.0032x over previous
#include <cuda_runtime.h>
#include <cuda_bf16.h>
#include <cuda_fp16.h>
#include <math.h>

// Problem constants: B=4, S=1024, L=1024, D=1024, H=16, HD=64, HIDDEN=4096
#define Bc 4
#define Sc 1024
#define Lc 1024
#define Dc 1024
#define Hc 16
#define HDc 64
#define HIDc 4096
#define BSc (Bc*Sc)
#define BLc (Bc*Lc)

// ---------------- scratch (static device globals) ----------------
__device__ float g_t2 [BSc*Dc];
__device__ float g_upd[BSc*Dc];
__device__ float g_t3 [BSc*Dc];
__device__ float g_ss [Bc*2*Dc];
__device__ int   g_valid [BSc];
__device__ int   g_svalid[BLc];
__device__ float g_vrow  [Bc];
__device__ int   g_layout[2];
__device__ __half h_x   [BSc*Dc];
__device__ __half h_qkv [BSc*3*Dc];
__device__ __half h_ctx [BSc*Dc];
__device__ __half h_qn  [BSc*Dc];
__device__ __half h_sn  [BLc*Dc];
__device__ __half h_cq  [BSc*Dc];
__device__ __half h_ckv [BLc*2*Dc];
__device__ __half h_gcat[BSc*2*Dc];
__device__ __half h_h   [BSc*Dc];
__device__ __half h_g   [(size_t)BSc*HIDc];
__device__ __half h_act [(size_t)BSc*HIDc];
__device__ __half h_qkvw  [3*Dc*Dc];
__device__ __half h_outw  [Dc*Dc];
__device__ __half h_mhainw[3*Dc*Dc];
__device__ __half h_mhaoutw[Dc*Dc];
__device__ __half h_gatew [Dc*2*Dc];
__device__ __half h_guw   [2*HIDc*Dc];
__device__ __half h_downw [Dc*HIDc];

// ---------------- reductions ----------------
__device__ __forceinline__ float warp_sum(float v){
    #pragma unroll
    for (int o=16;o>0;o>>=1) v += __shfl_xor_sync(0xffffffffu, v, o);
    return v;
}
__device__ float block_sum(float v){
    __shared__ float red[33];
    __syncthreads();
    int lane = threadIdx.x & 31, wid = threadIdx.x >> 5;
    v = warp_sum(v);
    if (lane==0) red[wid] = v;
    __syncthreads();
    int nw = blockDim.x >> 5;
    float r = (threadIdx.x < nw) ? red[threadIdx.x] : 0.f;
    if (wid==0){ r = warp_sum(r); if (lane==0) red[32] = r; }
    __syncthreads();
    return red[32];
}

// ---------------- mask layout detection + decode ----------------
__global__ void detect_mask_layout(const unsigned char* __restrict__ p, int n, int slot){
    int i = blockIdx.x*blockDim.x + threadIdx.x;
    if (i >= n) return;
    unsigned char v = p[i];
    if (v != 0 && v != 1) atomicOr(&g_layout[slot], 2);
    else if (v == 1 && (i & 3) != 0) atomicOr(&g_layout[slot], 1);
}
__global__ void decode_mask(const void* __restrict__ p, int cols, int slot,
                            int* __restrict__ valid, float* __restrict__ vrow){
    int b = blockIdx.x;
    int layout = g_layout[slot];
    int mode = (layout & 2) ? 2 : ((layout & 1) ? 1 : 0);
    __shared__ int s_anyzero;
    if (threadIdx.x==0) s_anyzero = 0;
    __syncthreads();
    int local_any = 0;
    for (int j = threadIdx.x; j < cols; j += blockDim.x){
        long idx = (long)b*cols + j;
        int m;
        if (mode==1)      m = ((const unsigned char*)p)[idx] != 0;
        else if (mode==2) m = ((const float*)p)[idx] != 0.f;
        else              m = ((const int*)p)[idx] != 0;
        valid[idx] = m;
        if (!m) local_any = 1;
    }
    if (local_any) atomicOr(&s_anyzero, 1);
    __syncthreads();
    int anyz = s_anyzero;
    for (int j = threadIdx.x; j < cols; j += blockDim.x){
        long idx = (long)b*cols + j;
        valid[idx] = anyz ? (1 - valid[idx]) : 1;
    }
    if (vrow && threadIdx.x==0) vrow[b] = anyz ? 1.f : 0.f;
}

// ---------------- helpers ----------------
__device__ __forceinline__ void mma_f16(float* c, const unsigned* a, const unsigned* b){
    asm volatile("mma.sync.aligned.m16n8k16.row.col.f32.f16.f16.f32 "
        "{%0,%1,%2,%3}, {%4,%5,%6,%7}, {%8,%9}, {%0,%1,%2,%3};"
        : "+f"(c[0]),"+f"(c[1]),"+f"(c[2]),"+f"(c[3])
        : "r"(a[0]),"r"(a[1]),"r"(a[2]),"r"(a[3]), "r"(b[0]),"r"(b[1]));
}
__device__ __forceinline__ unsigned pack_h2(float x, float y){
    __half2 h = __floats2half2_rn(x, y);
    return *(unsigned*)&h;
}
__device__ __forceinline__ unsigned smem_u32(const void* p){
    return (unsigned)__cvta_generic_to_shared(p);
}
__device__ __forceinline__ void cp16(unsigned dst, const void* src){
    asm volatile("cp.async.cg.shared.global [%0], [%1], 16;" :: "r"(dst), "l"(src) : "memory");
}
__device__ __forceinline__ void ldsm4(unsigned* r, unsigned addr){
    asm volatile("ldmatrix.sync.aligned.m8n8.x4.shared.b16 {%0,%1,%2,%3}, [%4];"
        : "=r"(r[0]),"=r"(r[1]),"=r"(r[2]),"=r"(r[3]) : "r"(addr));
}

// ---------------- fp16 cp.async double-buffered NT GEMM (ldmatrix mainloop) ----------------
// A [M,K] fp16 row-major, B [N,K] fp16 row-major. M%128==0, N%128==0, K%32==0.
// epi=0: v=alpha*acc(+bias)(*rowscale)(+residual); store C32/C16
// epi=1 (gate): v=acc+bias; out = residual + sigmoid(v)*aux32
// epi=2 (silu): v=acc+bias; g=aux16; out = silu(g)*v
template<int NWM,int NWN>
__global__ __launch_bounds__(256)
void gemm_h16p(const __half* __restrict__ A, const __half* __restrict__ B,
               float* __restrict__ C32, __half* __restrict__ C16,
               int M,int N,int K,int lda,int ldb,int ldc32,int ldc16,
               float alpha,
               const float* __restrict__ bias,
               const float* __restrict__ residual,int ldres,
               const float* __restrict__ rowscale,int rsDiv,
               int epi, const void* __restrict__ aux, int ldaux)
{
    constexpr int BM=128, BN=128, BK=32, STAGES=2;
    constexpr int WM=BM/NWM, WN=BN/NWN;
    constexpr int MI=WM/16, NI=WN/8;
    constexpr int LDS=BK+8;   // 40 halves per row (80B stride: conflict-free ldmatrix)

    __shared__ __align__(16) __half As[STAGES][BM*LDS];
    __shared__ __align__(16) __half Bs[STAGES][BN*LDS];

    const int tid=threadIdx.x, lane=tid&31, warp=tid>>5;
    const int m0=blockIdx.y*BM, n0=blockIdx.x*BN;
    const int wm0=(warp/NWN)*WM, wn0=(warp%NWN)*WN;
    const int qr=lane>>2, qc=lane&3;
    const int lr=lane&15, koff=(lane>>4)<<3;   // ldmatrix lane addressing

    float acc[MI][NI][4];
    #pragma unroll
    for (int i=0;i<MI;i++)
        #pragma unroll
        for (int j=0;j<NI;j++)
            #pragma unroll
            for (int r=0;r<4;r++) acc[i][j][r]=0.f;

    const int nk = K/BK;

    auto issue = [&](int s, int kt){
        int k0 = kt*BK;
        #pragma unroll
        for (int h2=0; h2<2; ++h2){
            int c = tid + h2*256;
            int r = c>>2, col = c&3;
            cp16(smem_u32(&As[s][r*LDS + col*8]),
                 A + (long long)(m0+r)*lda + k0 + col*8);
            cp16(smem_u32(&Bs[s][r*LDS + col*8]),
                 B + (long long)(n0+r)*ldb + k0 + col*8);
        }
    };

    issue(0, 0);
    asm volatile("cp.async.commit_group;" ::: "memory");

    for (int kt=0; kt<nk; ++kt){
        asm volatile("cp.async.wait_group 0;" ::: "memory");
        __syncthreads();
        if (kt+1 < nk) issue((kt+1)&1, kt+1);
        asm volatile("cp.async.commit_group;" ::: "memory");

        const __half* as = As[kt&1];
        const __half* bs = Bs[kt&1];
        #pragma unroll
        for (int ks=0; ks<BK; ks+=16){
            unsigned af[MI][4], bf[NI][2];
            #pragma unroll
            for (int mi=0; mi<MI; ++mi)
                ldsm4(af[mi], smem_u32(&as[(wm0+mi*16+lr)*LDS + ks + koff]));
            #pragma unroll
            for (int nj=0; nj<NI/2; ++nj){
                unsigned r[4];
                ldsm4(r, smem_u32(&bs[(wn0+nj*16+lr)*LDS + ks + koff]));
                bf[2*nj][0]=r[0]; bf[2*nj+1][0]=r[1];
                bf[2*nj][1]=r[2]; bf[2*nj+1][1]=r[3];
            }
            #pragma unroll
            for (int mi=0; mi<MI; ++mi)
                #pragma unroll
                for (int ni=0; ni<NI; ++ni)
                    mma_f16(acc[mi][ni], af[mi], bf[ni]);
        }
        __syncthreads();
    }

    // epilogue
    #pragma unroll
    for (int mi=0; mi<MI; ++mi){
        #pragma unroll
        for (int hf=0; hf<2; ++hf){
            int gm = m0 + wm0 + mi*16 + qr + hf*8;
            float rs = rowscale ? rowscale[gm/rsDiv] : 1.f;
            #pragma unroll
            for (int ni=0; ni<NI; ++ni){
                int gn = n0 + wn0 + ni*8 + qc*2;
                float v0 = alpha*acc[mi][ni][hf*2+0];
                float v1 = alpha*acc[mi][ni][hf*2+1];
                if (bias){ v0 += bias[gn]; v1 += bias[gn+1]; }
                if (epi==1){
                    const float* upd = (const float*)aux;
                    float2 r = *(const float2*)(residual + (long long)gm*ldres + gn);
                    float2 u = *(const float2*)(upd + (long long)gm*ldaux + gn);
                    v0 = r.x + u.x/(1.f+__expf(-v0));
                    v1 = r.y + u.y/(1.f+__expf(-v1));
                } else if (epi==2){
                    const __half* gh = (const __half*)aux;
                    __half2 gg = *(const __half2*)(gh + (long long)gm*ldaux + gn);
                    float g0 = __low2float(gg), g1 = __high2float(gg);
                    v0 *= g0/(1.f+__expf(-g0));
                    v1 *= g1/(1.f+__expf(-g1));
                } else {
                    v0 *= rs; v1 *= rs;
                    if (residual){
                        float2 r = *(const float2*)(residual + (long long)gm*ldres + gn);
                        v0 += r.x; v1 += r.y;
                    }
                }
                if (C32)
                    *(float2*)(C32 + (long long)gm*ldc32 + gn) = make_float2(v0, v1);
                if (C16)
                    *(__half2*)(C16 + (long long)gm*ldc16 + gn) = __floats2half2_rn(v0, v1);
            }
        }
    }
}

// ---------------- fused flash attention (fp16 in/out, ldmatrix + hoisted Q frags) ----------------
__global__ __launch_bounds__(256)
void flash_attn(const __half* __restrict__ q, const __half* __restrict__ k,
                const __half* __restrict__ v, __half* __restrict__ o,
                const int* __restrict__ valid,
                int ldq, int ldk, int ldv, int ldo,
                int qrows, int krows)
{
    constexpr int BQ = 128, BKT = 64;
    constexpr int LQ = HDc + 8;      // 72 halves (144B stride: conflict-free ldmatrix)
    constexpr int LV = BKT + 8;
    __shared__ __align__(16) __half Qs[BQ*LQ];
    __shared__ __align__(16) __half Ks[BKT*LQ];
    __shared__ __align__(16) __half Vt[HDc*LV];
    __shared__ float  mk[BKT];

    const int z = blockIdx.y;
    const int b = z / Hc, h = z % Hc;
    const __half* qb = q + (long long)b*qrows*ldq + h*HDc;
    const __half* kb = k + (long long)b*krows*ldk + h*HDc;
    const __half* vb = v + (long long)b*krows*ldv + h*HDc;
    __half*       ob = o + (long long)b*qrows*ldo + h*HDc;
    const int*    vl = valid + (long)b*krows;

    const int tid = threadIdx.x, lane = tid & 31, warp = tid >> 5;
    const int qr = lane >> 2, qc = lane & 3;
    const int lr = lane & 15, koff = (lane>>4)<<3;
    const int m0 = blockIdx.x*BQ;
    const int wm = warp*16;
    const __half2 sc2 = __float2half2_rn(0.125f);

    // Q tile, scaled by 1/8
    for (int i = tid; i < BQ*(HDc/8); i += 256){
        int r = i>>3, c8 = i&7;
        uint4 u = *(const uint4*)(qb + (long long)(m0+r)*ldq + c8*8);
        __half2* hp = (__half2*)&u;
        hp[0]=__hmul2(hp[0],sc2); hp[1]=__hmul2(hp[1],sc2);
        hp[2]=__hmul2(hp[2],sc2); hp[3]=__hmul2(hp[3],sc2);
        *(uint4*)&Qs[r*LQ + c8*8] = u;
    }
    __syncthreads();
    // hoist Q fragments (loop-invariant)
    unsigned qf[4][4];
    #pragma unroll
    for (int ks4=0; ks4<4; ++ks4)
        ldsm4(qf[ks4], smem_u32(&Qs[(wm+lr)*LQ + ks4*16 + koff]));

    float mr0 = -3.4e38f, mr1 = -3.4e38f, lr0 = 0.f, lr1 = 0.f;
    float O[8][4];
    #pragma unroll
    for (int i=0;i<8;i++){ O[i][0]=0.f; O[i][1]=0.f; O[i][2]=0.f; O[i][3]=0.f; }

    const int nkt = krows / BKT;
    for (int kt=0; kt<nkt; ++kt){
        __syncthreads();
        for (int i = tid; i < BKT*(HDc/8); i += 256){
            int r = i>>3, c8 = i&7;
            *(uint4*)&Ks[r*LQ + c8*8] =
                *(const uint4*)(kb + (long long)(kt*BKT+r)*ldk + c8*8);
        }
        for (int i = tid; i < BKT*(HDc/8); i += 256){
            int r = i>>3, c8 = i&7;
            uint4 u = *(const uint4*)(vb + (long long)(kt*BKT+r)*ldv + c8*8);
            const __half* hv = (const __half*)&u;
            #pragma unroll
            for (int j=0;j<8;j++) Vt[(c8*8+j)*LV + r] = hv[j];
        }
        if (tid < BKT) mk[tid] = vl[kt*BKT + tid] ? 0.f : -1e30f;
        __syncthreads();

        // S = Q K^T via ldmatrix
        float S[8][4];
        #pragma unroll
        for (int i=0;i<8;i++){ S[i][0]=0.f; S[i][1]=0.f; S[i][2]=0.f; S[i][3]=0.f; }
        #pragma unroll
        for (int ks4=0; ks4<4; ++ks4){
            unsigned kf[8][2];
            #pragma unroll
            for (int nj=0; nj<4; ++nj){
                unsigned r[4];
                ldsm4(r, smem_u32(&Ks[(nj*16+lr)*LQ + ks4*16 + koff]));
                kf[2*nj][0]=r[0]; kf[2*nj+1][0]=r[1];
                kf[2*nj][1]=r[2]; kf[2*nj+1][1]=r[3];
            }
            #pragma unroll
            for (int ni=0; ni<8; ++ni)
                mma_f16(S[ni], qf[ks4], kf[ni]);
        }
        // mask + online softmax
        float mn0 = -3.4e38f, mn1 = -3.4e38f;
        #pragma unroll
        for (int ni=0; ni<8; ++ni){
            float a0 = mk[ni*8 + 2*qc], a1 = mk[ni*8 + 2*qc + 1];
            S[ni][0] += a0; S[ni][1] += a1; S[ni][2] += a0; S[ni][3] += a1;
            mn0 = fmaxf(mn0, fmaxf(S[ni][0], S[ni][1]));
            mn1 = fmaxf(mn1, fmaxf(S[ni][2], S[ni][3]));
        }
        mn0 = fmaxf(mn0, __shfl_xor_sync(0xffffffffu, mn0, 1));
        mn0 = fmaxf(mn0, __shfl_xor_sync(0xffffffffu, mn0, 2));
        mn1 = fmaxf(mn1, __shfl_xor_sync(0xffffffffu, mn1, 1));
        mn1 = fmaxf(mn1, __shfl_xor_sync(0xffffffffu, mn1, 2));
        float mN0 = fmaxf(mr0, mn0), mN1 = fmaxf(mr1, mn1);
        float f0 = __expf(mr0 - mN0), f1 = __expf(mr1 - mN1);
        lr0 *= f0; lr1 *= f1;
        #pragma unroll
        for (int no=0; no<8; ++no){
            O[no][0]*=f0; O[no][1]*=f0; O[no][2]*=f1; O[no][3]*=f1;
        }
        mr0 = mN0; mr1 = mN1;
        unsigned ph[8][2];
        #pragma unroll
        for (int ni=0; ni<8; ++ni){
            float p0 = __expf(S[ni][0]-mr0), p1 = __expf(S[ni][1]-mr0);
            float p2 = __expf(S[ni][2]-mr1), p3 = __expf(S[ni][3]-mr1);
            lr0 += p0+p1; lr1 += p2+p3;
            ph[ni][0] = pack_h2(p0, p1);
            ph[ni][1] = pack_h2(p2, p3);
        }
        // O += P V via ldmatrix on Vt
        #pragma unroll
        for (int st=0; st<4; ++st){
            unsigned af[4] = { ph[2*st][0], ph[2*st][1], ph[2*st+1][0], ph[2*st+1][1] };
            unsigned vf[8][2];
            #pragma unroll
            for (int nj=0; nj<4; ++nj){
                unsigned r[4];
                ldsm4(r, smem_u32(&Vt[(nj*16+lr)*LV + st*16 + koff]));
                vf[2*nj][0]=r[0]; vf[2*nj+1][0]=r[1];
                vf[2*nj][1]=r[2]; vf[2*nj+1][1]=r[3];
            }
            #pragma unroll
            for (int no=0; no<8; ++no)
                mma_f16(O[no], af, vf[no]);
        }
    }

    lr0 += __shfl_xor_sync(0xffffffffu, lr0, 1);
    lr0 += __shfl_xor_sync(0xffffffffu, lr0, 2);
    lr1 += __shfl_xor_sync(0xffffffffu, lr1, 1);
    lr1 += __shfl_xor_sync(0xffffffffu, lr1, 2);
    float i0 = 1.f/lr0, i1 = 1.f/lr1;
    #pragma unroll
    for (int no=0; no<8; ++no){
        int gm0 = m0 + wm + qr, gn = no*8 + 2*qc;
        *(__half2*)(ob + (long long)gm0*ldo + gn)     = __floats2half2_rn(O[no][0]*i0, O[no][1]*i0);
        *(__half2*)(ob + (long long)(gm0+8)*ldo + gn) = __floats2half2_rn(O[no][2]*i1, O[no][3]*i1);
    }
}

// ---------------- small kernels ----------------
__global__ void cvt_f2h(const float* __restrict__ x, __half* __restrict__ y, long n){
    long i = ((long)blockIdx.x*blockDim.x + threadIdx.x)*4;
    if (i >= n) return;
    float4 f = *(const float4*)(x + i);
    *(__half2*)(y+i)   = __floats2half2_rn(f.x, f.y);
    *(__half2*)(y+i+2) = __floats2half2_rn(f.z, f.w);
}

__global__ void film_gemv(const float* __restrict__ mod, const float* __restrict__ W,
                          const float* __restrict__ bias, float* __restrict__ out,
                          int Bn, int N2, int K){
    int warp = (blockIdx.x*blockDim.x + threadIdx.x) >> 5;
    int lane = threadIdx.x & 31;
    if (warp >= Bn*N2) return;
    int b = warp / N2, n = warp % N2;
    const float* a = mod + (long)b*K;
    const float* w = W   + (long)n*K;
    float acc=0.f;
    for (int k=lane; k<K; k+=32) acc = fmaf(a[k], w[k], acc);
    acc = warp_sum(acc);
    if (lane==0) out[warp] = acc + bias[n];
}

__global__ void rmsnorm_h(const float* __restrict__ x, const float* __restrict__ w,
                          __half* __restrict__ y, int Dd,
                          const float* __restrict__ filmss, int S){
    long row = blockIdx.x;
    const float* xr = x + row*Dd;
    float ss = 0.f;
    for (int j = threadIdx.x; j < Dd; j += blockDim.x){ float v = xr[j]; ss = fmaf(v,v,ss); }
    ss = block_sum(ss);
    float r = rsqrtf(ss/(float)Dd + 1e-6f);
    if (filmss){
        int b = (int)(row / S);
        const float* sc = filmss + (long)b*2*Dd;
        for (int j = threadIdx.x; j < Dd; j += blockDim.x){
            float v = xr[j]*r*w[j];
            y[row*Dd + j] = __float2half(v*(1.f + 0.1f*tanhf(sc[j])) + sc[Dd + j]);
        }
    } else {
        for (int j = threadIdx.x; j < Dd; j += blockDim.x)
            y[row*Dd + j] = __float2half(xr[j]*r*w[j]);
    }
}

__global__ void rope_h(__half* __restrict__ qkv){
    long idx = (long)blockIdx.x*blockDim.x + threadIdx.x;
    const long total = (long)BSc * Hc * (HDc/2);
    if (idx >= total) return;
    int i = idx % (HDc/2);
    int h = (idx / (HDc/2)) % Hc;
    long row = idx / ((HDc/2)*Hc);
    int s = (int)(row % Sc);
    float freq = expf(-logf(10000.f) * (float)(2*i) / (float)HDc);
    float ang = (float)s * freq;
    float c = cosf(ang), sn = sinf(ang);
    __half2* qb = (__half2*)(qkv + row*(3*Dc) + h*HDc);
    float2 qv = __half22float2(qb[i]);
    qb[i] = __floats2half2_rn(qv.x*c - qv.y*sn, qv.x*sn + qv.y*c);
    __half2* kb = qb + Dc/2;
    float2 kv = __half22float2(kb[i]);
    kb[i] = __floats2half2_rn(kv.x*c - kv.y*sn, kv.x*sn + kv.y*c);
}

// ---------------- host helper ----------------
static inline void tc(const __half* A,const __half* B,float* C32,__half* C16,
    int M,int N,int K,int lda,int ldb,int ldc32,int ldc16,
    float alpha,const float* bias,const float* res,int ldres,
    const float* rs,int rsdiv,int epi,const void* aux,int ldaux)
{
    dim3 g(N/128, M/128);
    gemm_h16p<2,4><<<g,256>>>(A,B,C32,C16,M,N,K,lda,ldb,ldc32,ldc16,
        alpha,bias,res,ldres,rs,rsdiv,epi,aux,ldaux);
}

extern "C" void kernel_launch(void* const* d_in, const int* in_sizes, int n_in,
                              void* d_out, int out_size)
{
    const float* tokens     = (const float*)d_in[0];
    const float* seq_tokens = (const float*)d_in[1];
    const float* modulation = (const float*)d_in[2];
    const float* attn_norm_w= (const float*)d_in[3];
    const float* qkv_w      = (const float*)d_in[4];
    const float* qkv_b      = (const float*)d_in[5];
    const float* out_w      = (const float*)d_in[6];
    const float* out_b      = (const float*)d_in[7];
    const float* film_w     = (const float*)d_in[8];
    const float* film_b     = (const float*)d_in[9];
    const float* sq_norm_w  = (const float*)d_in[10];
    const float* s_norm_w   = (const float*)d_in[11];
    const float* mha_in_w   = (const float*)d_in[12];
    const float* mha_in_b   = (const float*)d_in[13];
    const float* mha_out_w  = (const float*)d_in[14];
    const float* mha_out_b  = (const float*)d_in[15];
    const float* gate_w     = (const float*)d_in[16];
    const float* gate_b     = (const float*)d_in[17];
    const float* ffn_norm_w = (const float*)d_in[18];
    const float* gu_w       = (const float*)d_in[19];
    const float* gu_b       = (const float*)d_in[20];
    const float* down_w     = (const float*)d_in[21];
    const float* down_b     = (const float*)d_in[22];
    const void*  padding_mask = d_in[23];
    const void*  seq_mask     = d_in[24];
    float* out = (float*)d_out;

    float *p_t2,*p_upd,*p_t3,*p_ss,*p_vrow;
    int *p_valid,*p_svalid;
    __half *p_x,*p_qkv,*p_ctx,*p_qn,*p_sn,*p_cq,*p_ckv,*p_gcat,*p_h,*p_g,*p_act;
    __half *p_qkvw,*p_outw,*p_mhainw,*p_mhaoutw,*p_gatew,*p_guw,*p_downw;
    cudaGetSymbolAddress((void**)&p_t2, g_t2);
    cudaGetSymbolAddress((void**)&p_upd, g_upd);
    cudaGetSymbolAddress((void**)&p_t3, g_t3);
    cudaGetSymbolAddress((void**)&p_ss, g_ss);
    cudaGetSymbolAddress((void**)&p_vrow, g_vrow);
    cudaGetSymbolAddress((void**)&p_valid, g_valid);
    cudaGetSymbolAddress((void**)&p_svalid, g_svalid);
    cudaGetSymbolAddress((void**)&p_x, h_x);
    cudaGetSymbolAddress((void**)&p_qkv, h_qkv);
    cudaGetSymbolAddress((void**)&p_ctx, h_ctx);
    cudaGetSymbolAddress((void**)&p_qn, h_qn);
    cudaGetSymbolAddress((void**)&p_sn, h_sn);
    cudaGetSymbolAddress((void**)&p_cq, h_cq);
    cudaGetSymbolAddress((void**)&p_ckv, h_ckv);
    cudaGetSymbolAddress((void**)&p_gcat, h_gcat);
    cudaGetSymbolAddress((void**)&p_h, h_h);
    cudaGetSymbolAddress((void**)&p_g, h_g);
    cudaGetSymbolAddress((void**)&p_act, h_act);
    cudaGetSymbolAddress((void**)&p_qkvw, h_qkvw);
    cudaGetSymbolAddress((void**)&p_outw, h_outw);
    cudaGetSymbolAddress((void**)&p_mhainw, h_mhainw);
    cudaGetSymbolAddress((void**)&p_mhaoutw, h_mhaoutw);
    cudaGetSymbolAddress((void**)&p_gatew, h_gatew);
    cudaGetSymbolAddress((void**)&p_guw, h_guw);
    cudaGetSymbolAddress((void**)&p_downw, h_downw);

    // 1) masks
    detect_mask_layout<<<(Bc*Sc+255)/256,256>>>((const unsigned char*)padding_mask, Bc*Sc, 0);
    detect_mask_layout<<<(Bc*Lc+255)/256,256>>>((const unsigned char*)seq_mask,     Bc*Lc, 1);
    decode_mask<<<Bc,256>>>(padding_mask, Sc, 0, p_valid,  nullptr);
    decode_mask<<<Bc,256>>>(seq_mask,     Lc, 1, p_svalid, p_vrow);

    // 2) weights -> fp16
    cvt_f2h<<<(3*Dc*Dc/4+255)/256,256>>>(qkv_w,     p_qkvw,    (long)3*Dc*Dc);
    cvt_f2h<<<(Dc*Dc/4+255)/256,256>>>(out_w,       p_outw,    (long)Dc*Dc);
    cvt_f2h<<<(3*Dc*Dc/4+255)/256,256>>>(mha_in_w,  p_mhainw,  (long)3*Dc*Dc);
    cvt_f2h<<<(Dc*Dc/4+255)/256,256>>>(mha_out_w,   p_mhaoutw, (long)Dc*Dc);
    cvt_f2h<<<(Dc*2*Dc/4+255)/256,256>>>(gate_w,    p_gatew,   (long)Dc*2*Dc);
    cvt_f2h<<<((long)2*HIDc*Dc/4+255)/256,256>>>(gu_w, p_guw,  (long)2*HIDc*Dc);
    cvt_f2h<<<((long)Dc*HIDc/4+255)/256,256>>>(down_w, p_downw,(long)Dc*HIDc);

    // 3) FiLM + first norm
    film_gemv<<<(Bc*2*Dc*32 + 255)/256, 256>>>(modulation, film_w, film_b, p_ss, Bc, 2*Dc, Dc);
    rmsnorm_h<<<BSc,256>>>(tokens, attn_norm_w, p_x, Dc, p_ss, Sc);

    // 4) qkv projection
    tc(p_x, p_qkvw, nullptr, p_qkv, BSc, 3*Dc, Dc, Dc, Dc, 0, 3*Dc,
       1.f, qkv_b, nullptr, 0, nullptr, 1, 0, nullptr, 0);

    // 5) RoPE
    rope_h<<<((long)BSc*Hc*(HDc/2) + 255)/256, 256>>>(p_qkv);

    // 6) self attention
    { dim3 g(Sc/128, Bc*Hc);
      flash_attn<<<g,256>>>(p_qkv, p_qkv + Dc, p_qkv + 2*Dc, p_ctx, p_valid,
                            3*Dc, 3*Dc, 3*Dc, Dc, Sc, Sc); }

    // 7) out-proj: t2 (fp32 + fp16 into gcat[:,0:D])
    tc(p_ctx, p_outw, p_t2, p_gcat, BSc, Dc, Dc, Dc, Dc, Dc, 2*Dc,
       1.f, out_b, tokens, Dc, nullptr, 1, 0, nullptr, 0);

    // 8) norms
    rmsnorm_h<<<BSc,256>>>(p_t2, sq_norm_w, p_qn, Dc, nullptr, Sc);
    rmsnorm_h<<<BLc,256>>>(seq_tokens, s_norm_w, p_sn, Dc, nullptr, Lc);

    // 9) cross projections
    tc(p_qn, p_mhainw, nullptr, p_cq, BSc, Dc, Dc, Dc, Dc, 0, Dc,
       1.f, mha_in_b, nullptr, 0, nullptr, 1, 0, nullptr, 0);
    tc(p_sn, p_mhainw + (long long)Dc*Dc, nullptr, p_ckv, BLc, 2*Dc, Dc, Dc, Dc, 0, 2*Dc,
       1.f, mha_in_b + Dc, nullptr, 0, nullptr, 1, 0, nullptr, 0);

    // 10) cross attention
    { dim3 g(Sc/128, Bc*Hc);
      flash_attn<<<g,256>>>(p_cq, p_ckv, p_ckv + Dc, p_ctx, p_svalid,
                            Dc, 2*Dc, 2*Dc, Dc, Sc, Lc); }

    // 11) mha-out: upd (fp32 + fp16 into gcat[:,D:2D])
    tc(p_ctx, p_mhaoutw, p_upd, p_gcat + Dc, BSc, Dc, Dc, Dc, Dc, Dc, 2*Dc,
       1.f, mha_out_b, nullptr, 0, p_vrow, Sc, 0, nullptr, 0);

    // 12) fused gate: t3 = t2 + sigmoid([t2|upd]@gate_w^T + gate_b) * upd
    tc(p_gcat, p_gatew, p_t3, nullptr, BSc, Dc, 2*Dc, 2*Dc, 2*Dc, Dc, 0,
       1.f, gate_b, p_t2, Dc, nullptr, 1, 1, p_upd, Dc);

    // 13) ffn norm
    rmsnorm_h<<<BSc,256>>>(p_t3, ffn_norm_w, p_h, Dc, nullptr, Sc);

    // 14) g = h@gu_w[0:HID]^T + b ; act = silu(g) * (h@gu_w[HID:]^T + b)
    tc(p_h, p_guw, nullptr, p_g, BSc, HIDc, Dc, Dc, Dc, 0, HIDc,
       1.f, gu_b, nullptr, 0, nullptr, 1, 0, nullptr, 0);
    tc(p_h, p_guw + (long long)HIDc*Dc, nullptr, p_act, BSc, HIDc, Dc, Dc, Dc, 0, HIDc,
       1.f, gu_b + HIDc, nullptr, 0, nullptr, 1, 2, p_g, HIDc);

    // 15) out = t3 + act@down_w^T + down_b
    tc(p_act, p_downw, out, nullptr, BSc, Dc, HIDc, HIDc, HIDc, Dc, 0,
       1.f, down_b, p_t3, Dc, nullptr, 1, 0, nullptr, 0);
}

// round 9
// speedup vs baseline: 1.8517x; 1.0009x over previous
#include <cuda_runtime.h>
#include <cuda_bf16.h>
#include <cuda_fp16.h>
#include <math.h>

// Problem constants: B=4, S=1024, L=1024, D=1024, H=16, HD=64, HIDDEN=4096
#define Bc 4
#define Sc 1024
#define Lc 1024
#define Dc 1024
#define Hc 16
#define HDc 64
#define HIDc 4096
#define BSc (Bc*Sc)
#define BLc (Bc*Lc)

// ---------------- scratch (static device globals) ----------------
__device__ float g_t2 [BSc*Dc];
__device__ float g_upd[BSc*Dc];
__device__ float g_t3 [BSc*Dc];
__device__ float g_ss [Bc*2*Dc];
__device__ int   g_valid [BSc];
__device__ int   g_svalid[BLc];
__device__ float g_vrow  [Bc];
__device__ int   g_layout[2];
__device__ __half h_x   [BSc*Dc];
__device__ __half h_qkv [BSc*3*Dc];
__device__ __half h_ctx [BSc*Dc];
__device__ __half h_qn  [BSc*Dc];
__device__ __half h_sn  [BLc*Dc];
__device__ __half h_cq  [BSc*Dc];
__device__ __half h_ckv [BLc*2*Dc];
__device__ __half h_gcat[BSc*2*Dc];
__device__ __half h_h   [BSc*Dc];
__device__ __half h_g   [(size_t)BSc*HIDc];
__device__ __half h_act [(size_t)BSc*HIDc];
__device__ __half h_qkvw  [3*Dc*Dc];
__device__ __half h_outw  [Dc*Dc];
__device__ __half h_mhainw[3*Dc*Dc];
__device__ __half h_mhaoutw[Dc*Dc];
__device__ __half h_gatew [Dc*2*Dc];
__device__ __half h_guw   [2*HIDc*Dc];
__device__ __half h_downw [Dc*HIDc];

// ---------------- reductions ----------------
__device__ __forceinline__ float warp_sum(float v){
    #pragma unroll
    for (int o=16;o>0;o>>=1) v += __shfl_xor_sync(0xffffffffu, v, o);
    return v;
}
__device__ float block_sum(float v){
    __shared__ float red[33];
    __syncthreads();
    int lane = threadIdx.x & 31, wid = threadIdx.x >> 5;
    v = warp_sum(v);
    if (lane==0) red[wid] = v;
    __syncthreads();
    int nw = blockDim.x >> 5;
    float r = (threadIdx.x < nw) ? red[threadIdx.x] : 0.f;
    if (wid==0){ r = warp_sum(r); if (lane==0) red[32] = r; }
    __syncthreads();
    return red[32];
}

// ---------------- mask layout detection + decode ----------------
__global__ void detect_mask_layout(const unsigned char* __restrict__ p, int n, int slot){
    int i = blockIdx.x*blockDim.x + threadIdx.x;
    if (i >= n) return;
    unsigned char v = p[i];
    if (v != 0 && v != 1) atomicOr(&g_layout[slot], 2);
    else if (v == 1 && (i & 3) != 0) atomicOr(&g_layout[slot], 1);
}
__global__ void decode_mask(const void* __restrict__ p, int cols, int slot,
                            int* __restrict__ valid, float* __restrict__ vrow){
    int b = blockIdx.x;
    int layout = g_layout[slot];
    int mode = (layout & 2) ? 2 : ((layout & 1) ? 1 : 0);
    __shared__ int s_anyzero;
    if (threadIdx.x==0) s_anyzero = 0;
    __syncthreads();
    int local_any = 0;
    for (int j = threadIdx.x; j < cols; j += blockDim.x){
        long idx = (long)b*cols + j;
        int m;
        if (mode==1)      m = ((const unsigned char*)p)[idx] != 0;
        else if (mode==2) m = ((const float*)p)[idx] != 0.f;
        else              m = ((const int*)p)[idx] != 0;
        valid[idx] = m;
        if (!m) local_any = 1;
    }
    if (local_any) atomicOr(&s_anyzero, 1);
    __syncthreads();
    int anyz = s_anyzero;
    for (int j = threadIdx.x; j < cols; j += blockDim.x){
        long idx = (long)b*cols + j;
        valid[idx] = anyz ? (1 - valid[idx]) : 1;
    }
    if (vrow && threadIdx.x==0) vrow[b] = anyz ? 1.f : 0.f;
}

// ---------------- helpers ----------------
__device__ __forceinline__ void mma_f16(float* c, const unsigned* a, const unsigned* b){
    asm volatile("mma.sync.aligned.m16n8k16.row.col.f32.f16.f16.f32 "
        "{%0,%1,%2,%3}, {%4,%5,%6,%7}, {%8,%9}, {%0,%1,%2,%3};"
        : "+f"(c[0]),"+f"(c[1]),"+f"(c[2]),"+f"(c[3])
        : "r"(a[0]),"r"(a[1]),"r"(a[2]),"r"(a[3]), "r"(b[0]),"r"(b[1]));
}
__device__ __forceinline__ unsigned pack_h2(float x, float y){
    __half2 h = __floats2half2_rn(x, y);
    return *(unsigned*)&h;
}
__device__ __forceinline__ unsigned smem_u32(const void* p){
    return (unsigned)__cvta_generic_to_shared(p);
}
__device__ __forceinline__ void cp16(unsigned dst, const void* src){
    asm volatile("cp.async.cg.shared.global [%0], [%1], 16;" :: "r"(dst), "l"(src) : "memory");
}
__device__ __forceinline__ void ldsm4(unsigned* r, unsigned addr){
    asm volatile("ldmatrix.sync.aligned.m8n8.x4.shared.b16 {%0,%1,%2,%3}, [%4];"
        : "=r"(r[0]),"=r"(r[1]),"=r"(r[2]),"=r"(r[3]) : "r"(addr));
}

// ---------------- fp16 cp.async double-buffered NT GEMM (ldmatrix mainloop) ----------------
// A [M,K] fp16 row-major, B [N,K] fp16 row-major. M%128==0, N%128==0, K%32==0.
// epi=0: v=alpha*acc(+bias)(*rowscale)(+residual); store C32/C16
// epi=1 (gate): v=acc+bias; out = residual + sigmoid(v)*aux32
// epi=2 (silu): v=acc+bias; g=aux16; out = silu(g)*v
template<int NWM,int NWN>
__global__ __launch_bounds__(256)
void gemm_h16p(const __half* __restrict__ A, const __half* __restrict__ B,
               float* __restrict__ C32, __half* __restrict__ C16,
               int M,int N,int K,int lda,int ldb,int ldc32,int ldc16,
               float alpha,
               const float* __restrict__ bias,
               const float* __restrict__ residual,int ldres,
               const float* __restrict__ rowscale,int rsDiv,
               int epi, const void* __restrict__ aux, int ldaux)
{
    constexpr int BM=128, BN=128, BK=32, STAGES=2;
    constexpr int WM=BM/NWM, WN=BN/NWN;
    constexpr int MI=WM/16, NI=WN/8;
    constexpr int LDS=BK+8;   // 40 halves per row (80B stride: conflict-free ldmatrix)

    __shared__ __align__(16) __half As[STAGES][BM*LDS];
    __shared__ __align__(16) __half Bs[STAGES][BN*LDS];

    const int tid=threadIdx.x, lane=tid&31, warp=tid>>5;
    const int m0=blockIdx.y*BM, n0=blockIdx.x*BN;
    const int wm0=(warp/NWN)*WM, wn0=(warp%NWN)*WN;
    const int qr=lane>>2, qc=lane&3;
    const int lr=lane&15, koff=(lane>>4)<<3;   // ldmatrix lane addressing

    float acc[MI][NI][4];
    #pragma unroll
    for (int i=0;i<MI;i++)
        #pragma unroll
        for (int j=0;j<NI;j++)
            #pragma unroll
            for (int r=0;r<4;r++) acc[i][j][r]=0.f;

    const int nk = K/BK;

    auto issue = [&](int s, int kt){
        int k0 = kt*BK;
        #pragma unroll
        for (int h2=0; h2<2; ++h2){
            int c = tid + h2*256;
            int r = c>>2, col = c&3;
            cp16(smem_u32(&As[s][r*LDS + col*8]),
                 A + (long long)(m0+r)*lda + k0 + col*8);
            cp16(smem_u32(&Bs[s][r*LDS + col*8]),
                 B + (long long)(n0+r)*ldb + k0 + col*8);
        }
    };

    issue(0, 0);
    asm volatile("cp.async.commit_group;" ::: "memory");

    for (int kt=0; kt<nk; ++kt){
        asm volatile("cp.async.wait_group 0;" ::: "memory");
        __syncthreads();
        if (kt+1 < nk) issue((kt+1)&1, kt+1);
        asm volatile("cp.async.commit_group;" ::: "memory");

        const __half* as = As[kt&1];
        const __half* bs = Bs[kt&1];
        #pragma unroll
        for (int ks=0; ks<BK; ks+=16){
            unsigned af[MI][4], bf[NI][2];
            #pragma unroll
            for (int mi=0; mi<MI; ++mi)
                ldsm4(af[mi], smem_u32(&as[(wm0+mi*16+lr)*LDS + ks + koff]));
            #pragma unroll
            for (int nj=0; nj<NI/2; ++nj){
                unsigned r[4];
                ldsm4(r, smem_u32(&bs[(wn0+nj*16+lr)*LDS + ks + koff]));
                bf[2*nj][0]=r[0]; bf[2*nj+1][0]=r[1];
                bf[2*nj][1]=r[2]; bf[2*nj+1][1]=r[3];
            }
            #pragma unroll
            for (int mi=0; mi<MI; ++mi)
                #pragma unroll
                for (int ni=0; ni<NI; ++ni)
                    mma_f16(acc[mi][ni], af[mi], bf[ni]);
        }
        __syncthreads();
    }

    // epilogue
    #pragma unroll
    for (int mi=0; mi<MI; ++mi){
        #pragma unroll
        for (int hf=0; hf<2; ++hf){
            int gm = m0 + wm0 + mi*16 + qr + hf*8;
            float rs = rowscale ? rowscale[gm/rsDiv] : 1.f;
            #pragma unroll
            for (int ni=0; ni<NI; ++ni){
                int gn = n0 + wn0 + ni*8 + qc*2;
                float v0 = alpha*acc[mi][ni][hf*2+0];
                float v1 = alpha*acc[mi][ni][hf*2+1];
                if (bias){ v0 += bias[gn]; v1 += bias[gn+1]; }
                if (epi==1){
                    const float* upd = (const float*)aux;
                    float2 r = *(const float2*)(residual + (long long)gm*ldres + gn);
                    float2 u = *(const float2*)(upd + (long long)gm*ldaux + gn);
                    v0 = r.x + u.x/(1.f+__expf(-v0));
                    v1 = r.y + u.y/(1.f+__expf(-v1));
                } else if (epi==2){
                    const __half* gh = (const __half*)aux;
                    __half2 gg = *(const __half2*)(gh + (long long)gm*ldaux + gn);
                    float g0 = __low2float(gg), g1 = __high2float(gg);
                    v0 *= g0/(1.f+__expf(-g0));
                    v1 *= g1/(1.f+__expf(-g1));
                } else {
                    v0 *= rs; v1 *= rs;
                    if (residual){
                        float2 r = *(const float2*)(residual + (long long)gm*ldres + gn);
                        v0 += r.x; v1 += r.y;
                    }
                }
                if (C32)
                    *(float2*)(C32 + (long long)gm*ldc32 + gn) = make_float2(v0, v1);
                if (C16)
                    *(__half2*)(C16 + (long long)gm*ldc16 + gn) = __floats2half2_rn(v0, v1);
            }
        }
    }
}

// ---------------- fused flash attention (fp16 in/out, ldmatrix + hoisted Q frags) ----------------
__global__ __launch_bounds__(256)
void flash_attn(const __half* __restrict__ q, const __half* __restrict__ k,
                const __half* __restrict__ v, __half* __restrict__ o,
                const int* __restrict__ valid,
                int ldq, int ldk, int ldv, int ldo,
                int qrows, int krows)
{
    constexpr int BQ = 128, BKT = 64;
    constexpr int LQ = HDc + 8;      // 72 halves (144B stride: conflict-free ldmatrix)
    constexpr int LV = BKT + 8;
    __shared__ __align__(16) __half Qs[BQ*LQ];
    __shared__ __align__(16) __half Ks[BKT*LQ];
    __shared__ __align__(16) __half Vt[HDc*LV];
    __shared__ float  mk[BKT];

    const int z = blockIdx.y;
    const int b = z / Hc, h = z % Hc;
    const __half* qb = q + (long long)b*qrows*ldq + h*HDc;
    const __half* kb = k + (long long)b*krows*ldk + h*HDc;
    const __half* vb = v + (long long)b*krows*ldv + h*HDc;
    __half*       ob = o + (long long)b*qrows*ldo + h*HDc;
    const int*    vl = valid + (long)b*krows;

    const int tid = threadIdx.x, lane = tid & 31, warp = tid >> 5;
    const int qr = lane >> 2, qc = lane & 3;
    const int lr = lane & 15, koff = (lane>>4)<<3;
    const int m0 = blockIdx.x*BQ;
    const int wm = warp*16;
    const __half2 sc2 = __float2half2_rn(0.125f);

    // Q tile, scaled by 1/8
    for (int i = tid; i < BQ*(HDc/8); i += 256){
        int r = i>>3, c8 = i&7;
        uint4 u = *(const uint4*)(qb + (long long)(m0+r)*ldq + c8*8);
        __half2* hp = (__half2*)&u;
        hp[0]=__hmul2(hp[0],sc2); hp[1]=__hmul2(hp[1],sc2);
        hp[2]=__hmul2(hp[2],sc2); hp[3]=__hmul2(hp[3],sc2);
        *(uint4*)&Qs[r*LQ + c8*8] = u;
    }
    __syncthreads();
    // hoist Q fragments (loop-invariant)
    unsigned qf[4][4];
    #pragma unroll
    for (int ks4=0; ks4<4; ++ks4)
        ldsm4(qf[ks4], smem_u32(&Qs[(wm+lr)*LQ + ks4*16 + koff]));

    float mr0 = -3.4e38f, mr1 = -3.4e38f, lr0 = 0.f, lr1 = 0.f;
    float O[8][4];
    #pragma unroll
    for (int i=0;i<8;i++){ O[i][0]=0.f; O[i][1]=0.f; O[i][2]=0.f; O[i][3]=0.f; }

    const int nkt = krows / BKT;
    for (int kt=0; kt<nkt; ++kt){
        __syncthreads();
        for (int i = tid; i < BKT*(HDc/8); i += 256){
            int r = i>>3, c8 = i&7;
            *(uint4*)&Ks[r*LQ + c8*8] =
                *(const uint4*)(kb + (long long)(kt*BKT+r)*ldk + c8*8);
        }
        for (int i = tid; i < BKT*(HDc/8); i += 256){
            int r = i>>3, c8 = i&7;
            uint4 u = *(const uint4*)(vb + (long long)(kt*BKT+r)*ldv + c8*8);
            const __half* hv = (const __half*)&u;
            #pragma unroll
            for (int j=0;j<8;j++) Vt[(c8*8+j)*LV + r] = hv[j];
        }
        if (tid < BKT) mk[tid] = vl[kt*BKT + tid] ? 0.f : -1e30f;
        __syncthreads();

        // S = Q K^T via ldmatrix
        float S[8][4];
        #pragma unroll
        for (int i=0;i<8;i++){ S[i][0]=0.f; S[i][1]=0.f; S[i][2]=0.f; S[i][3]=0.f; }
        #pragma unroll
        for (int ks4=0; ks4<4; ++ks4){
            unsigned kf[8][2];
            #pragma unroll
            for (int nj=0; nj<4; ++nj){
                unsigned r[4];
                ldsm4(r, smem_u32(&Ks[(nj*16+lr)*LQ + ks4*16 + koff]));
                kf[2*nj][0]=r[0]; kf[2*nj+1][0]=r[1];
                kf[2*nj][1]=r[2]; kf[2*nj+1][1]=r[3];
            }
            #pragma unroll
            for (int ni=0; ni<8; ++ni)
                mma_f16(S[ni], qf[ks4], kf[ni]);
        }
        // mask + online softmax
        float mn0 = -3.4e38f, mn1 = -3.4e38f;
        #pragma unroll
        for (int ni=0; ni<8; ++ni){
            float a0 = mk[ni*8 + 2*qc], a1 = mk[ni*8 + 2*qc + 1];
            S[ni][0] += a0; S[ni][1] += a1; S[ni][2] += a0; S[ni][3] += a1;
            mn0 = fmaxf(mn0, fmaxf(S[ni][0], S[ni][1]));
            mn1 = fmaxf(mn1, fmaxf(S[ni][2], S[ni][3]));
        }
        mn0 = fmaxf(mn0, __shfl_xor_sync(0xffffffffu, mn0, 1));
        mn0 = fmaxf(mn0, __shfl_xor_sync(0xffffffffu, mn0, 2));
        mn1 = fmaxf(mn1, __shfl_xor_sync(0xffffffffu, mn1, 1));
        mn1 = fmaxf(mn1, __shfl_xor_sync(0xffffffffu, mn1, 2));
        float mN0 = fmaxf(mr0, mn0), mN1 = fmaxf(mr1, mn1);
        float f0 = __expf(mr0 - mN0), f1 = __expf(mr1 - mN1);
        lr0 *= f0; lr1 *= f1;
        #pragma unroll
        for (int no=0; no<8; ++no){
            O[no][0]*=f0; O[no][1]*=f0; O[no][2]*=f1; O[no][3]*=f1;
        }
        mr0 = mN0; mr1 = mN1;
        unsigned ph[8][2];
        #pragma unroll
        for (int ni=0; ni<8; ++ni){
            float p0 = __expf(S[ni][0]-mr0), p1 = __expf(S[ni][1]-mr0);
            float p2 = __expf(S[ni][2]-mr1), p3 = __expf(S[ni][3]-mr1);
            lr0 += p0+p1; lr1 += p2+p3;
            ph[ni][0] = pack_h2(p0, p1);
            ph[ni][1] = pack_h2(p2, p3);
        }
        // O += P V via ldmatrix on Vt
        #pragma unroll
        for (int st=0; st<4; ++st){
            unsigned af[4] = { ph[2*st][0], ph[2*st][1], ph[2*st+1][0], ph[2*st+1][1] };
            unsigned vf[8][2];
            #pragma unroll
            for (int nj=0; nj<4; ++nj){
                unsigned r[4];
                ldsm4(r, smem_u32(&Vt[(nj*16+lr)*LV + st*16 + koff]));
                vf[2*nj][0]=r[0]; vf[2*nj+1][0]=r[1];
                vf[2*nj][1]=r[2]; vf[2*nj+1][1]=r[3];
            }
            #pragma unroll
            for (int no=0; no<8; ++no)
                mma_f16(O[no], af, vf[no]);
        }
    }

    lr0 += __shfl_xor_sync(0xffffffffu, lr0, 1);
    lr0 += __shfl_xor_sync(0xffffffffu, lr0, 2);
    lr1 += __shfl_xor_sync(0xffffffffu, lr1, 1);
    lr1 += __shfl_xor_sync(0xffffffffu, lr1, 2);
    float i0 = 1.f/lr0, i1 = 1.f/lr1;
    #pragma unroll
    for (int no=0; no<8; ++no){
        int gm0 = m0 + wm + qr, gn = no*8 + 2*qc;
        *(__half2*)(ob + (long long)gm0*ldo + gn)     = __floats2half2_rn(O[no][0]*i0, O[no][1]*i0);
        *(__half2*)(ob + (long long)(gm0+8)*ldo + gn) = __floats2half2_rn(O[no][2]*i1, O[no][3]*i1);
    }
}

// ---------------- small kernels ----------------
__global__ void cvt_f2h(const float* __restrict__ x, __half* __restrict__ y, long n){
    long i = ((long)blockIdx.x*blockDim.x + threadIdx.x)*4;
    if (i >= n) return;
    float4 f = *(const float4*)(x + i);
    *(__half2*)(y+i)   = __floats2half2_rn(f.x, f.y);
    *(__half2*)(y+i+2) = __floats2half2_rn(f.z, f.w);
}

__global__ void film_gemv(const float* __restrict__ mod, const float* __restrict__ W,
                          const float* __restrict__ bias, float* __restrict__ out,
                          int Bn, int N2, int K){
    int warp = (blockIdx.x*blockDim.x + threadIdx.x) >> 5;
    int lane = threadIdx.x & 31;
    if (warp >= Bn*N2) return;
    int b = warp / N2, n = warp % N2;
    const float* a = mod + (long)b*K;
    const float* w = W   + (long)n*K;
    float acc=0.f;
    for (int k=lane; k<K; k+=32) acc = fmaf(a[k], w[k], acc);
    acc = warp_sum(acc);
    if (lane==0) out[warp] = acc + bias[n];
}

__global__ void rmsnorm_h(const float* __restrict__ x, const float* __restrict__ w,
                          __half* __restrict__ y, int Dd,
                          const float* __restrict__ filmss, int S){
    long row = blockIdx.x;
    const float* xr = x + row*Dd;
    float ss = 0.f;
    for (int j = threadIdx.x; j < Dd; j += blockDim.x){ float v = xr[j]; ss = fmaf(v,v,ss); }
    ss = block_sum(ss);
    float r = rsqrtf(ss/(float)Dd + 1e-6f);
    if (filmss){
        int b = (int)(row / S);
        const float* sc = filmss + (long)b*2*Dd;
        for (int j = threadIdx.x; j < Dd; j += blockDim.x){
            float v = xr[j]*r*w[j];
            y[row*Dd + j] = __float2half(v*(1.f + 0.1f*tanhf(sc[j])) + sc[Dd + j]);
        }
    } else {
        for (int j = threadIdx.x; j < Dd; j += blockDim.x)
            y[row*Dd + j] = __float2half(xr[j]*r*w[j]);
    }
}

__global__ void rope_h(__half* __restrict__ qkv){
    long idx = (long)blockIdx.x*blockDim.x + threadIdx.x;
    const long total = (long)BSc * Hc * (HDc/2);
    if (idx >= total) return;
    int i = idx % (HDc/2);
    int h = (idx / (HDc/2)) % Hc;
    long row = idx / ((HDc/2)*Hc);
    int s = (int)(row % Sc);
    float freq = expf(-logf(10000.f) * (float)(2*i) / (float)HDc);
    float ang = (float)s * freq;
    float c = cosf(ang), sn = sinf(ang);
    __half2* qb = (__half2*)(qkv + row*(3*Dc) + h*HDc);
    float2 qv = __half22float2(qb[i]);
    qb[i] = __floats2half2_rn(qv.x*c - qv.y*sn, qv.x*sn + qv.y*c);
    __half2* kb = qb + Dc/2;
    float2 kv = __half22float2(kb[i]);
    kb[i] = __floats2half2_rn(kv.x*c - kv.y*sn, kv.x*sn + kv.y*c);
}

// ---------------- host helper ----------------
static inline void tc(const __half* A,const __half* B,float* C32,__half* C16,
    int M,int N,int K,int lda,int ldb,int ldc32,int ldc16,
    float alpha,const float* bias,const float* res,int ldres,
    const float* rs,int rsdiv,int epi,const void* aux,int ldaux)
{
    dim3 g(N/128, M/128);
    gemm_h16p<2,4><<<g,256>>>(A,B,C32,C16,M,N,K,lda,ldb,ldc32,ldc16,
        alpha,bias,res,ldres,rs,rsdiv,epi,aux,ldaux);
}

extern "C" void kernel_launch(void* const* d_in, const int* in_sizes, int n_in,
                              void* d_out, int out_size)
{
    const float* tokens     = (const float*)d_in[0];
    const float* seq_tokens = (const float*)d_in[1];
    const float* modulation = (const float*)d_in[2];
    const float* attn_norm_w= (const float*)d_in[3];
    const float* qkv_w      = (const float*)d_in[4];
    const float* qkv_b      = (const float*)d_in[5];
    const float* out_w      = (const float*)d_in[6];
    const float* out_b      = (const float*)d_in[7];
    const float* film_w     = (const float*)d_in[8];
    const float* film_b     = (const float*)d_in[9];
    const float* sq_norm_w  = (const float*)d_in[10];
    const float* s_norm_w   = (const float*)d_in[11];
    const float* mha_in_w   = (const float*)d_in[12];
    const float* mha_in_b   = (const float*)d_in[13];
    const float* mha_out_w  = (const float*)d_in[14];
    const float* mha_out_b  = (const float*)d_in[15];
    const float* gate_w     = (const float*)d_in[16];
    const float* gate_b     = (const float*)d_in[17];
    const float* ffn_norm_w = (const float*)d_in[18];
    const float* gu_w       = (const float*)d_in[19];
    const float* gu_b       = (const float*)d_in[20];
    const float* down_w     = (const float*)d_in[21];
    const float* down_b     = (const float*)d_in[22];
    const void*  padding_mask = d_in[23];
    const void*  seq_mask     = d_in[24];
    float* out = (float*)d_out;

    float *p_t2,*p_upd,*p_t3,*p_ss,*p_vrow;
    int *p_valid,*p_svalid;
    __half *p_x,*p_qkv,*p_ctx,*p_qn,*p_sn,*p_cq,*p_ckv,*p_gcat,*p_h,*p_g,*p_act;
    __half *p_qkvw,*p_outw,*p_mhainw,*p_mhaoutw,*p_gatew,*p_guw,*p_downw;
    cudaGetSymbolAddress((void**)&p_t2, g_t2);
    cudaGetSymbolAddress((void**)&p_upd, g_upd);
    cudaGetSymbolAddress((void**)&p_t3, g_t3);
    cudaGetSymbolAddress((void**)&p_ss, g_ss);
    cudaGetSymbolAddress((void**)&p_vrow, g_vrow);
    cudaGetSymbolAddress((void**)&p_valid, g_valid);
    cudaGetSymbolAddress((void**)&p_svalid, g_svalid);
    cudaGetSymbolAddress((void**)&p_x, h_x);
    cudaGetSymbolAddress((void**)&p_qkv, h_qkv);
    cudaGetSymbolAddress((void**)&p_ctx, h_ctx);
    cudaGetSymbolAddress((void**)&p_qn, h_qn);
    cudaGetSymbolAddress((void**)&p_sn, h_sn);
    cudaGetSymbolAddress((void**)&p_cq, h_cq);
    cudaGetSymbolAddress((void**)&p_ckv, h_ckv);
    cudaGetSymbolAddress((void**)&p_gcat, h_gcat);
    cudaGetSymbolAddress((void**)&p_h, h_h);
    cudaGetSymbolAddress((void**)&p_g, h_g);
    cudaGetSymbolAddress((void**)&p_act, h_act);
    cudaGetSymbolAddress((void**)&p_qkvw, h_qkvw);
    cudaGetSymbolAddress((void**)&p_outw, h_outw);
    cudaGetSymbolAddress((void**)&p_mhainw, h_mhainw);
    cudaGetSymbolAddress((void**)&p_mhaoutw, h_mhaoutw);
    cudaGetSymbolAddress((void**)&p_gatew, h_gatew);
    cudaGetSymbolAddress((void**)&p_guw, h_guw);
    cudaGetSymbolAddress((void**)&p_downw, h_downw);

    // 1) masks
    detect_mask_layout<<<(Bc*Sc+255)/256,256>>>((const unsigned char*)padding_mask, Bc*Sc, 0);
    detect_mask_layout<<<(Bc*Lc+255)/256,256>>>((const unsigned char*)seq_mask,     Bc*Lc, 1);
    decode_mask<<<Bc,256>>>(padding_mask, Sc, 0, p_valid,  nullptr);
    decode_mask<<<Bc,256>>>(seq_mask,     Lc, 1, p_svalid, p_vrow);

    // 2) weights -> fp16
    cvt_f2h<<<(3*Dc*Dc/4+255)/256,256>>>(qkv_w,     p_qkvw,    (long)3*Dc*Dc);
    cvt_f2h<<<(Dc*Dc/4+255)/256,256>>>(out_w,       p_outw,    (long)Dc*Dc);
    cvt_f2h<<<(3*Dc*Dc/4+255)/256,256>>>(mha_in_w,  p_mhainw,  (long)3*Dc*Dc);
    cvt_f2h<<<(Dc*Dc/4+255)/256,256>>>(mha_out_w,   p_mhaoutw, (long)Dc*Dc);
    cvt_f2h<<<(Dc*2*Dc/4+255)/256,256>>>(gate_w,    p_gatew,   (long)Dc*2*Dc);
    cvt_f2h<<<((long)2*HIDc*Dc/4+255)/256,256>>>(gu_w, p_guw,  (long)2*HIDc*Dc);
    cvt_f2h<<<((long)Dc*HIDc/4+255)/256,256>>>(down_w, p_downw,(long)Dc*HIDc);

    // 3) FiLM + first norm
    film_gemv<<<(Bc*2*Dc*32 + 255)/256, 256>>>(modulation, film_w, film_b, p_ss, Bc, 2*Dc, Dc);
    rmsnorm_h<<<BSc,256>>>(tokens, attn_norm_w, p_x, Dc, p_ss, Sc);

    // 4) qkv projection
    tc(p_x, p_qkvw, nullptr, p_qkv, BSc, 3*Dc, Dc, Dc, Dc, 0, 3*Dc,
       1.f, qkv_b, nullptr, 0, nullptr, 1, 0, nullptr, 0);

    // 5) RoPE
    rope_h<<<((long)BSc*Hc*(HDc/2) + 255)/256, 256>>>(p_qkv);

    // 6) self attention
    { dim3 g(Sc/128, Bc*Hc);
      flash_attn<<<g,256>>>(p_qkv, p_qkv + Dc, p_qkv + 2*Dc, p_ctx, p_valid,
                            3*Dc, 3*Dc, 3*Dc, Dc, Sc, Sc); }

    // 7) out-proj: t2 (fp32 + fp16 into gcat[:,0:D])
    tc(p_ctx, p_outw, p_t2, p_gcat, BSc, Dc, Dc, Dc, Dc, Dc, 2*Dc,
       1.f, out_b, tokens, Dc, nullptr, 1, 0, nullptr, 0);

    // 8) norms
    rmsnorm_h<<<BSc,256>>>(p_t2, sq_norm_w, p_qn, Dc, nullptr, Sc);
    rmsnorm_h<<<BLc,256>>>(seq_tokens, s_norm_w, p_sn, Dc, nullptr, Lc);

    // 9) cross projections
    tc(p_qn, p_mhainw, nullptr, p_cq, BSc, Dc, Dc, Dc, Dc, 0, Dc,
       1.f, mha_in_b, nullptr, 0, nullptr, 1, 0, nullptr, 0);
    tc(p_sn, p_mhainw + (long long)Dc*Dc, nullptr, p_ckv, BLc, 2*Dc, Dc, Dc, Dc, 0, 2*Dc,
       1.f, mha_in_b + Dc, nullptr, 0, nullptr, 1, 0, nullptr, 0);

    // 10) cross attention
    { dim3 g(Sc/128, Bc*Hc);
      flash_attn<<<g,256>>>(p_cq, p_ckv, p_ckv + Dc, p_ctx, p_svalid,
                            Dc, 2*Dc, 2*Dc, Dc, Sc, Lc); }

    // 11) mha-out: upd (fp32 + fp16 into gcat[:,D:2D])
    tc(p_ctx, p_mhaoutw, p_upd, p_gcat + Dc, BSc, Dc, Dc, Dc, Dc, Dc, 2*Dc,
       1.f, mha_out_b, nullptr, 0, p_vrow, Sc, 0, nullptr, 0);

    // 12) fused gate: t3 = t2 + sigmoid([t2|upd]@gate_w^T + gate_b) * upd
    tc(p_gcat, p_gatew, p_t3, nullptr, BSc, Dc, 2*Dc, 2*Dc, 2*Dc, Dc, 0,
       1.f, gate_b, p_t2, Dc, nullptr, 1, 1, p_upd, Dc);

    // 13) ffn norm
    rmsnorm_h<<<BSc,256>>>(p_t3, ffn_norm_w, p_h, Dc, nullptr, Sc);

    // 14) g = h@gu_w[0:HID]^T + b ; act = silu(g) * (h@gu_w[HID:]^T + b)
    tc(p_h, p_guw, nullptr, p_g, BSc, HIDc, Dc, Dc, Dc, 0, HIDc,
       1.f, gu_b, nullptr, 0, nullptr, 1, 0, nullptr, 0);
    tc(p_h, p_guw + (long long)HIDc*Dc, nullptr, p_act, BSc, HIDc, Dc, Dc, Dc, 0, HIDc,
       1.f, gu_b + HIDc, nullptr, 0, nullptr, 1, 2, p_g, HIDc);

    // 15) out = t3 + act@down_w^T + down_b
    tc(p_act, p_downw, out, nullptr, BSc, Dc, HIDc, HIDc, HIDc, Dc, 0,
       1.f, down_b, p_t3, Dc, nullptr, 1, 0, nullptr, 0);
}

// round 10
// speedup vs baseline: 1.8550x; 1.0017x over previous
#include <cuda_runtime.h>
#include <cuda_bf16.h>
#include <cuda_fp16.h>
#include <math.h>

// Problem constants: B=4, S=1024, L=1024, D=1024, H=16, HD=64, HIDDEN=4096
#define Bc 4
#define Sc 1024
#define Lc 1024
#define Dc 1024
#define Hc 16
#define HDc 64
#define HIDc 4096
#define BSc (Bc*Sc)
#define BLc (Bc*Lc)

// ---------------- scratch (static device globals) ----------------
__device__ float g_t2 [BSc*Dc];
__device__ float g_upd[BSc*Dc];
__device__ float g_t3 [BSc*Dc];
__device__ float g_ss [Bc*2*Dc];
__device__ int   g_valid [BSc];
__device__ int   g_svalid[BLc];
__device__ float g_vrow  [Bc];
__device__ int   g_layout[2];
__device__ __half h_x   [BSc*Dc];
__device__ __half h_qkv [BSc*3*Dc];
__device__ __half h_ctx [BSc*Dc];
__device__ __half h_qn  [BSc*Dc];
__device__ __half h_sn  [BLc*Dc];
__device__ __half h_cq  [BSc*Dc];
__device__ __half h_ckv [BLc*2*Dc];
__device__ __half h_gcat[BSc*2*Dc];
__device__ __half h_h   [BSc*Dc];
__device__ __half h_g   [(size_t)BSc*HIDc];
__device__ __half h_act [(size_t)BSc*HIDc];
__device__ __half h_qkvw  [3*Dc*Dc];
__device__ __half h_outw  [Dc*Dc];
__device__ __half h_mhainw[3*Dc*Dc];
__device__ __half h_mhaoutw[Dc*Dc];
__device__ __half h_gatew [Dc*2*Dc];
__device__ __half h_guw   [2*HIDc*Dc];
__device__ __half h_downw [Dc*HIDc];

// ---------------- reductions ----------------
__device__ __forceinline__ float warp_sum(float v){
    #pragma unroll
    for (int o=16;o>0;o>>=1) v += __shfl_xor_sync(0xffffffffu, v, o);
    return v;
}
__device__ float block_sum(float v){
    __shared__ float red[33];
    __syncthreads();
    int lane = threadIdx.x & 31, wid = threadIdx.x >> 5;
    v = warp_sum(v);
    if (lane==0) red[wid] = v;
    __syncthreads();
    int nw = blockDim.x >> 5;
    float r = (threadIdx.x < nw) ? red[threadIdx.x] : 0.f;
    if (wid==0){ r = warp_sum(r); if (lane==0) red[32] = r; }
    __syncthreads();
    return red[32];
}

// ---------------- mask layout detection + decode ----------------
__global__ void detect_mask_layout(const unsigned char* __restrict__ p, int n, int slot){
    int i = blockIdx.x*blockDim.x + threadIdx.x;
    if (i >= n) return;
    unsigned char v = p[i];
    if (v != 0 && v != 1) atomicOr(&g_layout[slot], 2);
    else if (v == 1 && (i & 3) != 0) atomicOr(&g_layout[slot], 1);
}
__global__ void decode_mask(const void* __restrict__ p, int cols, int slot,
                            int* __restrict__ valid, float* __restrict__ vrow){
    int b = blockIdx.x;
    int layout = g_layout[slot];
    int mode = (layout & 2) ? 2 : ((layout & 1) ? 1 : 0);
    __shared__ int s_anyzero;
    if (threadIdx.x==0) s_anyzero = 0;
    __syncthreads();
    int local_any = 0;
    for (int j = threadIdx.x; j < cols; j += blockDim.x){
        long idx = (long)b*cols + j;
        int m;
        if (mode==1)      m = ((const unsigned char*)p)[idx] != 0;
        else if (mode==2) m = ((const float*)p)[idx] != 0.f;
        else              m = ((const int*)p)[idx] != 0;
        valid[idx] = m;
        if (!m) local_any = 1;
    }
    if (local_any) atomicOr(&s_anyzero, 1);
    __syncthreads();
    int anyz = s_anyzero;
    for (int j = threadIdx.x; j < cols; j += blockDim.x){
        long idx = (long)b*cols + j;
        valid[idx] = anyz ? (1 - valid[idx]) : 1;
    }
    if (vrow && threadIdx.x==0) vrow[b] = anyz ? 1.f : 0.f;
}

// ---------------- helpers ----------------
__device__ __forceinline__ void mma_f16(float* c, const unsigned* a, const unsigned* b){
    asm volatile("mma.sync.aligned.m16n8k16.row.col.f32.f16.f16.f32 "
        "{%0,%1,%2,%3}, {%4,%5,%6,%7}, {%8,%9}, {%0,%1,%2,%3};"
        : "+f"(c[0]),"+f"(c[1]),"+f"(c[2]),"+f"(c[3])
        : "r"(a[0]),"r"(a[1]),"r"(a[2]),"r"(a[3]), "r"(b[0]),"r"(b[1]));
}
__device__ __forceinline__ unsigned pack_h2(float x, float y){
    __half2 h = __floats2half2_rn(x, y);
    return *(unsigned*)&h;
}
__device__ __forceinline__ unsigned smem_u32(const void* p){
    return (unsigned)__cvta_generic_to_shared(p);
}
__device__ __forceinline__ void cp16(unsigned dst, const void* src){
    asm volatile("cp.async.cg.shared.global [%0], [%1], 16;" :: "r"(dst), "l"(src) : "memory");
}
__device__ __forceinline__ void ldsm4(unsigned* r, unsigned addr){
    asm volatile("ldmatrix.sync.aligned.m8n8.x4.shared.b16 {%0,%1,%2,%3}, [%4];"
        : "=r"(r[0]),"=r"(r[1]),"=r"(r[2]),"=r"(r[3]) : "r"(addr));
}

// ---------------- fp16 cp.async double-buffered NT GEMM (ldmatrix mainloop) ----------------
// A [M,K] fp16 row-major, B [N,K] fp16 row-major. M%128==0, N%128==0, K%32==0.
// epi=0: v=alpha*acc(+bias)(*rowscale)(+residual); store C32/C16
// epi=1 (gate): v=acc+bias; out = residual + sigmoid(v)*aux32
// epi=2 (silu): v=acc+bias; g=aux16; out = silu(g)*v
template<int NWM,int NWN>
__global__ __launch_bounds__(256)
void gemm_h16p(const __half* __restrict__ A, const __half* __restrict__ B,
               float* __restrict__ C32, __half* __restrict__ C16,
               int M,int N,int K,int lda,int ldb,int ldc32,int ldc16,
               float alpha,
               const float* __restrict__ bias,
               const float* __restrict__ residual,int ldres,
               const float* __restrict__ rowscale,int rsDiv,
               int epi, const void* __restrict__ aux, int ldaux)
{
    constexpr int BM=128, BN=128, BK=32, STAGES=2;
    constexpr int WM=BM/NWM, WN=BN/NWN;
    constexpr int MI=WM/16, NI=WN/8;
    constexpr int LDS=BK+8;   // 40 halves per row (80B stride: conflict-free ldmatrix)

    __shared__ __align__(16) __half As[STAGES][BM*LDS];
    __shared__ __align__(16) __half Bs[STAGES][BN*LDS];

    const int tid=threadIdx.x, lane=tid&31, warp=tid>>5;
    const int m0=blockIdx.y*BM, n0=blockIdx.x*BN;
    const int wm0=(warp/NWN)*WM, wn0=(warp%NWN)*WN;
    const int qr=lane>>2, qc=lane&3;
    const int lr=lane&15, koff=(lane>>4)<<3;   // ldmatrix lane addressing

    float acc[MI][NI][4];
    #pragma unroll
    for (int i=0;i<MI;i++)
        #pragma unroll
        for (int j=0;j<NI;j++)
            #pragma unroll
            for (int r=0;r<4;r++) acc[i][j][r]=0.f;

    const int nk = K/BK;

    auto issue = [&](int s, int kt){
        int k0 = kt*BK;
        #pragma unroll
        for (int h2=0; h2<2; ++h2){
            int c = tid + h2*256;
            int r = c>>2, col = c&3;
            cp16(smem_u32(&As[s][r*LDS + col*8]),
                 A + (long long)(m0+r)*lda + k0 + col*8);
            cp16(smem_u32(&Bs[s][r*LDS + col*8]),
                 B + (long long)(n0+r)*ldb + k0 + col*8);
        }
    };

    issue(0, 0);
    asm volatile("cp.async.commit_group;" ::: "memory");

    for (int kt=0; kt<nk; ++kt){
        asm volatile("cp.async.wait_group 0;" ::: "memory");
        __syncthreads();
        if (kt+1 < nk) issue((kt+1)&1, kt+1);
        asm volatile("cp.async.commit_group;" ::: "memory");

        const __half* as = As[kt&1];
        const __half* bs = Bs[kt&1];
        #pragma unroll
        for (int ks=0; ks<BK; ks+=16){
            unsigned af[MI][4], bf[NI][2];
            #pragma unroll
            for (int mi=0; mi<MI; ++mi)
                ldsm4(af[mi], smem_u32(&as[(wm0+mi*16+lr)*LDS + ks + koff]));
            #pragma unroll
            for (int nj=0; nj<NI/2; ++nj){
                unsigned r[4];
                ldsm4(r, smem_u32(&bs[(wn0+nj*16+lr)*LDS + ks + koff]));
                bf[2*nj][0]=r[0]; bf[2*nj+1][0]=r[1];
                bf[2*nj][1]=r[2]; bf[2*nj+1][1]=r[3];
            }
            #pragma unroll
            for (int mi=0; mi<MI; ++mi)
                #pragma unroll
                for (int ni=0; ni<NI; ++ni)
                    mma_f16(acc[mi][ni], af[mi], bf[ni]);
        }
        __syncthreads();
    }

    // epilogue
    #pragma unroll
    for (int mi=0; mi<MI; ++mi){
        #pragma unroll
        for (int hf=0; hf<2; ++hf){
            int gm = m0 + wm0 + mi*16 + qr + hf*8;
            float rs = rowscale ? rowscale[gm/rsDiv] : 1.f;
            #pragma unroll
            for (int ni=0; ni<NI; ++ni){
                int gn = n0 + wn0 + ni*8 + qc*2;
                float v0 = alpha*acc[mi][ni][hf*2+0];
                float v1 = alpha*acc[mi][ni][hf*2+1];
                if (bias){ v0 += bias[gn]; v1 += bias[gn+1]; }
                if (epi==1){
                    const float* upd = (const float*)aux;
                    float2 r = *(const float2*)(residual + (long long)gm*ldres + gn);
                    float2 u = *(const float2*)(upd + (long long)gm*ldaux + gn);
                    v0 = r.x + u.x/(1.f+__expf(-v0));
                    v1 = r.y + u.y/(1.f+__expf(-v1));
                } else if (epi==2){
                    const __half* gh = (const __half*)aux;
                    __half2 gg = *(const __half2*)(gh + (long long)gm*ldaux + gn);
                    float g0 = __low2float(gg), g1 = __high2float(gg);
                    v0 *= g0/(1.f+__expf(-g0));
                    v1 *= g1/(1.f+__expf(-g1));
                } else {
                    v0 *= rs; v1 *= rs;
                    if (residual){
                        float2 r = *(const float2*)(residual + (long long)gm*ldres + gn);
                        v0 += r.x; v1 += r.y;
                    }
                }
                if (C32)
                    *(float2*)(C32 + (long long)gm*ldc32 + gn) = make_float2(v0, v1);
                if (C16)
                    *(__half2*)(C16 + (long long)gm*ldc16 + gn) = __floats2half2_rn(v0, v1);
            }
        }
    }
}

// ---------------- fused flash attention (fp16 in/out, ldmatrix + hoisted Q frags) ----------------
__global__ __launch_bounds__(256)
void flash_attn(const __half* __restrict__ q, const __half* __restrict__ k,
                const __half* __restrict__ v, __half* __restrict__ o,
                const int* __restrict__ valid,
                int ldq, int ldk, int ldv, int ldo,
                int qrows, int krows)
{
    constexpr int BQ = 128, BKT = 64;
    constexpr int LQ = HDc + 8;      // 72 halves (144B stride: conflict-free ldmatrix)
    constexpr int LV = BKT + 8;
    __shared__ __align__(16) __half Qs[BQ*LQ];
    __shared__ __align__(16) __half Ks[BKT*LQ];
    __shared__ __align__(16) __half Vt[HDc*LV];
    __shared__ float  mk[BKT];

    const int z = blockIdx.y;
    const int b = z / Hc, h = z % Hc;
    const __half* qb = q + (long long)b*qrows*ldq + h*HDc;
    const __half* kb = k + (long long)b*krows*ldk + h*HDc;
    const __half* vb = v + (long long)b*krows*ldv + h*HDc;
    __half*       ob = o + (long long)b*qrows*ldo + h*HDc;
    const int*    vl = valid + (long)b*krows;

    const int tid = threadIdx.x, lane = tid & 31, warp = tid >> 5;
    const int qr = lane >> 2, qc = lane & 3;
    const int lr = lane & 15, koff = (lane>>4)<<3;
    const int m0 = blockIdx.x*BQ;
    const int wm = warp*16;
    const __half2 sc2 = __float2half2_rn(0.125f);

    // Q tile, scaled by 1/8
    for (int i = tid; i < BQ*(HDc/8); i += 256){
        int r = i>>3, c8 = i&7;
        uint4 u = *(const uint4*)(qb + (long long)(m0+r)*ldq + c8*8);
        __half2* hp = (__half2*)&u;
        hp[0]=__hmul2(hp[0],sc2); hp[1]=__hmul2(hp[1],sc2);
        hp[2]=__hmul2(hp[2],sc2); hp[3]=__hmul2(hp[3],sc2);
        *(uint4*)&Qs[r*LQ + c8*8] = u;
    }
    __syncthreads();
    // hoist Q fragments (loop-invariant)
    unsigned qf[4][4];
    #pragma unroll
    for (int ks4=0; ks4<4; ++ks4)
        ldsm4(qf[ks4], smem_u32(&Qs[(wm+lr)*LQ + ks4*16 + koff]));

    float mr0 = -3.4e38f, mr1 = -3.4e38f, lr0 = 0.f, lr1 = 0.f;
    float O[8][4];
    #pragma unroll
    for (int i=0;i<8;i++){ O[i][0]=0.f; O[i][1]=0.f; O[i][2]=0.f; O[i][3]=0.f; }

    const int nkt = krows / BKT;
    for (int kt=0; kt<nkt; ++kt){
        __syncthreads();
        for (int i = tid; i < BKT*(HDc/8); i += 256){
            int r = i>>3, c8 = i&7;
            *(uint4*)&Ks[r*LQ + c8*8] =
                *(const uint4*)(kb + (long long)(kt*BKT+r)*ldk + c8*8);
        }
        for (int i = tid; i < BKT*(HDc/8); i += 256){
            int r = i>>3, c8 = i&7;
            uint4 u = *(const uint4*)(vb + (long long)(kt*BKT+r)*ldv + c8*8);
            const __half* hv = (const __half*)&u;
            #pragma unroll
            for (int j=0;j<8;j++) Vt[(c8*8+j)*LV + r] = hv[j];
        }
        if (tid < BKT) mk[tid] = vl[kt*BKT + tid] ? 0.f : -1e30f;
        __syncthreads();

        // S = Q K^T via ldmatrix
        float S[8][4];
        #pragma unroll
        for (int i=0;i<8;i++){ S[i][0]=0.f; S[i][1]=0.f; S[i][2]=0.f; S[i][3]=0.f; }
        #pragma unroll
        for (int ks4=0; ks4<4; ++ks4){
            unsigned kf[8][2];
            #pragma unroll
            for (int nj=0; nj<4; ++nj){
                unsigned r[4];
                ldsm4(r, smem_u32(&Ks[(nj*16+lr)*LQ + ks4*16 + koff]));
                kf[2*nj][0]=r[0]; kf[2*nj+1][0]=r[1];
                kf[2*nj][1]=r[2]; kf[2*nj+1][1]=r[3];
            }
            #pragma unroll
            for (int ni=0; ni<8; ++ni)
                mma_f16(S[ni], qf[ks4], kf[ni]);
        }
        // mask + online softmax
        float mn0 = -3.4e38f, mn1 = -3.4e38f;
        #pragma unroll
        for (int ni=0; ni<8; ++ni){
            float a0 = mk[ni*8 + 2*qc], a1 = mk[ni*8 + 2*qc + 1];
            S[ni][0] += a0; S[ni][1] += a1; S[ni][2] += a0; S[ni][3] += a1;
            mn0 = fmaxf(mn0, fmaxf(S[ni][0], S[ni][1]));
            mn1 = fmaxf(mn1, fmaxf(S[ni][2], S[ni][3]));
        }
        mn0 = fmaxf(mn0, __shfl_xor_sync(0xffffffffu, mn0, 1));
        mn0 = fmaxf(mn0, __shfl_xor_sync(0xffffffffu, mn0, 2));
        mn1 = fmaxf(mn1, __shfl_xor_sync(0xffffffffu, mn1, 1));
        mn1 = fmaxf(mn1, __shfl_xor_sync(0xffffffffu, mn1, 2));
        float mN0 = fmaxf(mr0, mn0), mN1 = fmaxf(mr1, mn1);
        float f0 = __expf(mr0 - mN0), f1 = __expf(mr1 - mN1);
        lr0 *= f0; lr1 *= f1;
        #pragma unroll
        for (int no=0; no<8; ++no){
            O[no][0]*=f0; O[no][1]*=f0; O[no][2]*=f1; O[no][3]*=f1;
        }
        mr0 = mN0; mr1 = mN1;
        unsigned ph[8][2];
        #pragma unroll
        for (int ni=0; ni<8; ++ni){
            float p0 = __expf(S[ni][0]-mr0), p1 = __expf(S[ni][1]-mr0);
            float p2 = __expf(S[ni][2]-mr1), p3 = __expf(S[ni][3]-mr1);
            lr0 += p0+p1; lr1 += p2+p3;
            ph[ni][0] = pack_h2(p0, p1);
            ph[ni][1] = pack_h2(p2, p3);
        }
        // O += P V via ldmatrix on Vt
        #pragma unroll
        for (int st=0; st<4; ++st){
            unsigned af[4] = { ph[2*st][0], ph[2*st][1], ph[2*st+1][0], ph[2*st+1][1] };
            unsigned vf[8][2];
            #pragma unroll
            for (int nj=0; nj<4; ++nj){
                unsigned r[4];
                ldsm4(r, smem_u32(&Vt[(nj*16+lr)*LV + st*16 + koff]));
                vf[2*nj][0]=r[0]; vf[2*nj+1][0]=r[1];
                vf[2*nj][1]=r[2]; vf[2*nj+1][1]=r[3];
            }
            #pragma unroll
            for (int no=0; no<8; ++no)
                mma_f16(O[no], af, vf[no]);
        }
    }

    lr0 += __shfl_xor_sync(0xffffffffu, lr0, 1);
    lr0 += __shfl_xor_sync(0xffffffffu, lr0, 2);
    lr1 += __shfl_xor_sync(0xffffffffu, lr1, 1);
    lr1 += __shfl_xor_sync(0xffffffffu, lr1, 2);
    float i0 = 1.f/lr0, i1 = 1.f/lr1;
    #pragma unroll
    for (int no=0; no<8; ++no){
        int gm0 = m0 + wm + qr, gn = no*8 + 2*qc;
        *(__half2*)(ob + (long long)gm0*ldo + gn)     = __floats2half2_rn(O[no][0]*i0, O[no][1]*i0);
        *(__half2*)(ob + (long long)(gm0+8)*ldo + gn) = __floats2half2_rn(O[no][2]*i1, O[no][3]*i1);
    }
}

// ---------------- small kernels ----------------
__global__ void cvt_f2h(const float* __restrict__ x, __half* __restrict__ y, long n){
    long i = ((long)blockIdx.x*blockDim.x + threadIdx.x)*4;
    if (i >= n) return;
    float4 f = *(const float4*)(x + i);
    *(__half2*)(y+i)   = __floats2half2_rn(f.x, f.y);
    *(__half2*)(y+i+2) = __floats2half2_rn(f.z, f.w);
}

__global__ void film_gemv(const float* __restrict__ mod, const float* __restrict__ W,
                          const float* __restrict__ bias, float* __restrict__ out,
                          int Bn, int N2, int K){
    int warp = (blockIdx.x*blockDim.x + threadIdx.x) >> 5;
    int lane = threadIdx.x & 31;
    if (warp >= Bn*N2) return;
    int b = warp / N2, n = warp % N2;
    const float* a = mod + (long)b*K;
    const float* w = W   + (long)n*K;
    float acc=0.f;
    for (int k=lane; k<K; k+=32) acc = fmaf(a[k], w[k], acc);
    acc = warp_sum(acc);
    if (lane==0) out[warp] = acc + bias[n];
}

__global__ void rmsnorm_h(const float* __restrict__ x, const float* __restrict__ w,
                          __half* __restrict__ y, int Dd,
                          const float* __restrict__ filmss, int S){
    long row = blockIdx.x;
    const float* xr = x + row*Dd;
    float ss = 0.f;
    for (int j = threadIdx.x; j < Dd; j += blockDim.x){ float v = xr[j]; ss = fmaf(v,v,ss); }
    ss = block_sum(ss);
    float r = rsqrtf(ss/(float)Dd + 1e-6f);
    if (filmss){
        int b = (int)(row / S);
        const float* sc = filmss + (long)b*2*Dd;
        for (int j = threadIdx.x; j < Dd; j += blockDim.x){
            float v = xr[j]*r*w[j];
            y[row*Dd + j] = __float2half(v*(1.f + 0.1f*tanhf(sc[j])) + sc[Dd + j]);
        }
    } else {
        for (int j = threadIdx.x; j < Dd; j += blockDim.x)
            y[row*Dd + j] = __float2half(xr[j]*r*w[j]);
    }
}

__global__ void rope_h(__half* __restrict__ qkv){
    long idx = (long)blockIdx.x*blockDim.x + threadIdx.x;
    const long total = (long)BSc * Hc * (HDc/2);
    if (idx >= total) return;
    int i = idx % (HDc/2);
    int h = (idx / (HDc/2)) % Hc;
    long row = idx / ((HDc/2)*Hc);
    int s = (int)(row % Sc);
    float freq = expf(-logf(10000.f) * (float)(2*i) / (float)HDc);
    float ang = (float)s * freq;
    float c = cosf(ang), sn = sinf(ang);
    __half2* qb = (__half2*)(qkv + row*(3*Dc) + h*HDc);
    float2 qv = __half22float2(qb[i]);
    qb[i] = __floats2half2_rn(qv.x*c - qv.y*sn, qv.x*sn + qv.y*c);
    __half2* kb = qb + Dc/2;
    float2 kv = __half22float2(kb[i]);
    kb[i] = __floats2half2_rn(kv.x*c - kv.y*sn, kv.x*sn + kv.y*c);
}

// ---------------- host helper ----------------
static inline void tc(const __half* A,const __half* B,float* C32,__half* C16,
    int M,int N,int K,int lda,int ldb,int ldc32,int ldc16,
    float alpha,const float* bias,const float* res,int ldres,
    const float* rs,int rsdiv,int epi,const void* aux,int ldaux)
{
    dim3 g(N/128, M/128);
    gemm_h16p<2,4><<<g,256>>>(A,B,C32,C16,M,N,K,lda,ldb,ldc32,ldc16,
        alpha,bias,res,ldres,rs,rsdiv,epi,aux,ldaux);
}

extern "C" void kernel_launch(void* const* d_in, const int* in_sizes, int n_in,
                              void* d_out, int out_size)
{
    const float* tokens     = (const float*)d_in[0];
    const float* seq_tokens = (const float*)d_in[1];
    const float* modulation = (const float*)d_in[2];
    const float* attn_norm_w= (const float*)d_in[3];
    const float* qkv_w      = (const float*)d_in[4];
    const float* qkv_b      = (const float*)d_in[5];
    const float* out_w      = (const float*)d_in[6];
    const float* out_b      = (const float*)d_in[7];
    const float* film_w     = (const float*)d_in[8];
    const float* film_b     = (const float*)d_in[9];
    const float* sq_norm_w  = (const float*)d_in[10];
    const float* s_norm_w   = (const float*)d_in[11];
    const float* mha_in_w   = (const float*)d_in[12];
    const float* mha_in_b   = (const float*)d_in[13];
    const float* mha_out_w  = (const float*)d_in[14];
    const float* mha_out_b  = (const float*)d_in[15];
    const float* gate_w     = (const float*)d_in[16];
    const float* gate_b     = (const float*)d_in[17];
    const float* ffn_norm_w = (const float*)d_in[18];
    const float* gu_w       = (const float*)d_in[19];
    const float* gu_b       = (const float*)d_in[20];
    const float* down_w     = (const float*)d_in[21];
    const float* down_b     = (const float*)d_in[22];
    const void*  padding_mask = d_in[23];
    const void*  seq_mask     = d_in[24];
    float* out = (float*)d_out;

    float *p_t2,*p_upd,*p_t3,*p_ss,*p_vrow;
    int *p_valid,*p_svalid;
    __half *p_x,*p_qkv,*p_ctx,*p_qn,*p_sn,*p_cq,*p_ckv,*p_gcat,*p_h,*p_g,*p_act;
    __half *p_qkvw,*p_outw,*p_mhainw,*p_mhaoutw,*p_gatew,*p_guw,*p_downw;
    cudaGetSymbolAddress((void**)&p_t2, g_t2);
    cudaGetSymbolAddress((void**)&p_upd, g_upd);
    cudaGetSymbolAddress((void**)&p_t3, g_t3);
    cudaGetSymbolAddress((void**)&p_ss, g_ss);
    cudaGetSymbolAddress((void**)&p_vrow, g_vrow);
    cudaGetSymbolAddress((void**)&p_valid, g_valid);
    cudaGetSymbolAddress((void**)&p_svalid, g_svalid);
    cudaGetSymbolAddress((void**)&p_x, h_x);
    cudaGetSymbolAddress((void**)&p_qkv, h_qkv);
    cudaGetSymbolAddress((void**)&p_ctx, h_ctx);
    cudaGetSymbolAddress((void**)&p_qn, h_qn);
    cudaGetSymbolAddress((void**)&p_sn, h_sn);
    cudaGetSymbolAddress((void**)&p_cq, h_cq);
    cudaGetSymbolAddress((void**)&p_ckv, h_ckv);
    cudaGetSymbolAddress((void**)&p_gcat, h_gcat);
    cudaGetSymbolAddress((void**)&p_h, h_h);
    cudaGetSymbolAddress((void**)&p_g, h_g);
    cudaGetSymbolAddress((void**)&p_act, h_act);
    cudaGetSymbolAddress((void**)&p_qkvw, h_qkvw);
    cudaGetSymbolAddress((void**)&p_outw, h_outw);
    cudaGetSymbolAddress((void**)&p_mhainw, h_mhainw);
    cudaGetSymbolAddress((void**)&p_mhaoutw, h_mhaoutw);
    cudaGetSymbolAddress((void**)&p_gatew, h_gatew);
    cudaGetSymbolAddress((void**)&p_guw, h_guw);
    cudaGetSymbolAddress((void**)&p_downw, h_downw);

    // 1) masks
    detect_mask_layout<<<(Bc*Sc+255)/256,256>>>((const unsigned char*)padding_mask, Bc*Sc, 0);
    detect_mask_layout<<<(Bc*Lc+255)/256,256>>>((const unsigned char*)seq_mask,     Bc*Lc, 1);
    decode_mask<<<Bc,256>>>(padding_mask, Sc, 0, p_valid,  nullptr);
    decode_mask<<<Bc,256>>>(seq_mask,     Lc, 1, p_svalid, p_vrow);

    // 2) weights -> fp16
    cvt_f2h<<<(3*Dc*Dc/4+255)/256,256>>>(qkv_w,     p_qkvw,    (long)3*Dc*Dc);
    cvt_f2h<<<(Dc*Dc/4+255)/256,256>>>(out_w,       p_outw,    (long)Dc*Dc);
    cvt_f2h<<<(3*Dc*Dc/4+255)/256,256>>>(mha_in_w,  p_mhainw,  (long)3*Dc*Dc);
    cvt_f2h<<<(Dc*Dc/4+255)/256,256>>>(mha_out_w,   p_mhaoutw, (long)Dc*Dc);
    cvt_f2h<<<(Dc*2*Dc/4+255)/256,256>>>(gate_w,    p_gatew,   (long)Dc*2*Dc);
    cvt_f2h<<<((long)2*HIDc*Dc/4+255)/256,256>>>(gu_w, p_guw,  (long)2*HIDc*Dc);
    cvt_f2h<<<((long)Dc*HIDc/4+255)/256,256>>>(down_w, p_downw,(long)Dc*HIDc);

    // 3) FiLM + first norm
    film_gemv<<<(Bc*2*Dc*32 + 255)/256, 256>>>(modulation, film_w, film_b, p_ss, Bc, 2*Dc, Dc);
    rmsnorm_h<<<BSc,256>>>(tokens, attn_norm_w, p_x, Dc, p_ss, Sc);

    // 4) qkv projection
    tc(p_x, p_qkvw, nullptr, p_qkv, BSc, 3*Dc, Dc, Dc, Dc, 0, 3*Dc,
       1.f, qkv_b, nullptr, 0, nullptr, 1, 0, nullptr, 0);

    // 5) RoPE
    rope_h<<<((long)BSc*Hc*(HDc/2) + 255)/256, 256>>>(p_qkv);

    // 6) self attention
    { dim3 g(Sc/128, Bc*Hc);
      flash_attn<<<g,256>>>(p_qkv, p_qkv + Dc, p_qkv + 2*Dc, p_ctx, p_valid,
                            3*Dc, 3*Dc, 3*Dc, Dc, Sc, Sc); }

    // 7) out-proj: t2 (fp32 + fp16 into gcat[:,0:D])
    tc(p_ctx, p_outw, p_t2, p_gcat, BSc, Dc, Dc, Dc, Dc, Dc, 2*Dc,
       1.f, out_b, tokens, Dc, nullptr, 1, 0, nullptr, 0);

    // 8) norms
    rmsnorm_h<<<BSc,256>>>(p_t2, sq_norm_w, p_qn, Dc, nullptr, Sc);
    rmsnorm_h<<<BLc,256>>>(seq_tokens, s_norm_w, p_sn, Dc, nullptr, Lc);

    // 9) cross projections
    tc(p_qn, p_mhainw, nullptr, p_cq, BSc, Dc, Dc, Dc, Dc, 0, Dc,
       1.f, mha_in_b, nullptr, 0, nullptr, 1, 0, nullptr, 0);
    tc(p_sn, p_mhainw + (long long)Dc*Dc, nullptr, p_ckv, BLc, 2*Dc, Dc, Dc, Dc, 0, 2*Dc,
       1.f, mha_in_b + Dc, nullptr, 0, nullptr, 1, 0, nullptr, 0);

    // 10) cross attention
    { dim3 g(Sc/128, Bc*Hc);
      flash_attn<<<g,256>>>(p_cq, p_ckv, p_ckv + Dc, p_ctx, p_svalid,
                            Dc, 2*Dc, 2*Dc, Dc, Sc, Lc); }

    // 11) mha-out: upd (fp32 + fp16 into gcat[:,D:2D])
    tc(p_ctx, p_mhaoutw, p_upd, p_gcat + Dc, BSc, Dc, Dc, Dc, Dc, Dc, 2*Dc,
       1.f, mha_out_b, nullptr, 0, p_vrow, Sc, 0, nullptr, 0);

    // 12) fused gate: t3 = t2 + sigmoid([t2|upd]@gate_w^T + gate_b) * upd
    tc(p_gcat, p_gatew, p_t3, nullptr, BSc, Dc, 2*Dc, 2*Dc, 2*Dc, Dc, 0,
       1.f, gate_b, p_t2, Dc, nullptr, 1, 1, p_upd, Dc);

    // 13) ffn norm
    rmsnorm_h<<<BSc,256>>>(p_t3, ffn_norm_w, p_h, Dc, nullptr, Sc);

    // 14) g = h@gu_w[0:HID]^T + b ; act = silu(g) * (h@gu_w[HID:]^T + b)
    tc(p_h, p_guw, nullptr, p_g, BSc, HIDc, Dc, Dc, Dc, 0, HIDc,
       1.f, gu_b, nullptr, 0, nullptr, 1, 0, nullptr, 0);
    tc(p_h, p_guw + (long long)HIDc*Dc, nullptr, p_act, BSc, HIDc, Dc, Dc, Dc, 0, HIDc,
       1.f, gu_b + HIDc, nullptr, 0, nullptr, 1, 2, p_g, HIDc);

    // 15) out = t3 + act@down_w^T + down_b
    tc(p_act, p_downw, out, nullptr, BSc, Dc, HIDc, HIDc, HIDc, Dc, 0,
       1.f, down_b, p_t3, Dc, nullptr, 1, 0, nullptr, 0);
}

// round 11
// speedup vs baseline: 1.8552x; 1.0002x over previous
#include <cuda_runtime.h>
#include <cuda_bf16.h>
#include <cuda_fp16.h>
#include <math.h>

// Problem constants: B=4, S=1024, L=1024, D=1024, H=16, HD=64, HIDDEN=4096
#define Bc 4
#define Sc 1024
#define Lc 1024
#define Dc 1024
#define Hc 16
#define HDc 64
#define HIDc 4096
#define BSc (Bc*Sc)
#define BLc (Bc*Lc)

// ---------------- scratch (static device globals) ----------------
__device__ float g_t2 [BSc*Dc];
__device__ float g_upd[BSc*Dc];
__device__ float g_t3 [BSc*Dc];
__device__ float g_ss [Bc*2*Dc];
__device__ int   g_valid [BSc];
__device__ int   g_svalid[BLc];
__device__ float g_vrow  [Bc];
__device__ int   g_layout[2];
__device__ __half h_x   [BSc*Dc];
__device__ __half h_qkv [BSc*3*Dc];
__device__ __half h_ctx [BSc*Dc];
__device__ __half h_qn  [BSc*Dc];
__device__ __half h_sn  [BLc*Dc];
__device__ __half h_cq  [BSc*Dc];
__device__ __half h_ckv [BLc*2*Dc];
__device__ __half h_gcat[BSc*2*Dc];
__device__ __half h_h   [BSc*Dc];
__device__ __half h_g   [(size_t)BSc*HIDc];
__device__ __half h_act [(size_t)BSc*HIDc];
__device__ __half h_qkvw  [3*Dc*Dc];
__device__ __half h_outw  [Dc*Dc];
__device__ __half h_mhainw[3*Dc*Dc];
__device__ __half h_mhaoutw[Dc*Dc];
__device__ __half h_gatew [Dc*2*Dc];
__device__ __half h_guw   [2*HIDc*Dc];
__device__ __half h_downw [Dc*HIDc];

// ---------------- reductions ----------------
__device__ __forceinline__ float warp_sum(float v){
    #pragma unroll
    for (int o=16;o>0;o>>=1) v += __shfl_xor_sync(0xffffffffu, v, o);
    return v;
}
__device__ float block_sum(float v){
    __shared__ float red[33];
    __syncthreads();
    int lane = threadIdx.x & 31, wid = threadIdx.x >> 5;
    v = warp_sum(v);
    if (lane==0) red[wid] = v;
    __syncthreads();
    int nw = blockDim.x >> 5;
    float r = (threadIdx.x < nw) ? red[threadIdx.x] : 0.f;
    if (wid==0){ r = warp_sum(r); if (lane==0) red[32] = r; }
    __syncthreads();
    return red[32];
}

// ---------------- mask layout detection + decode ----------------
__global__ void detect_mask_layout(const unsigned char* __restrict__ p, int n, int slot){
    int i = blockIdx.x*blockDim.x + threadIdx.x;
    if (i >= n) return;
    unsigned char v = p[i];
    if (v != 0 && v != 1) atomicOr(&g_layout[slot], 2);
    else if (v == 1 && (i & 3) != 0) atomicOr(&g_layout[slot], 1);
}
__global__ void decode_mask(const void* __restrict__ p, int cols, int slot,
                            int* __restrict__ valid, float* __restrict__ vrow){
    int b = blockIdx.x;
    int layout = g_layout[slot];
    int mode = (layout & 2) ? 2 : ((layout & 1) ? 1 : 0);
    __shared__ int s_anyzero;
    if (threadIdx.x==0) s_anyzero = 0;
    __syncthreads();
    int local_any = 0;
    for (int j = threadIdx.x; j < cols; j += blockDim.x){
        long idx = (long)b*cols + j;
        int m;
        if (mode==1)      m = ((const unsigned char*)p)[idx] != 0;
        else if (mode==2) m = ((const float*)p)[idx] != 0.f;
        else              m = ((const int*)p)[idx] != 0;
        valid[idx] = m;
        if (!m) local_any = 1;
    }
    if (local_any) atomicOr(&s_anyzero, 1);
    __syncthreads();
    int anyz = s_anyzero;
    for (int j = threadIdx.x; j < cols; j += blockDim.x){
        long idx = (long)b*cols + j;
        valid[idx] = anyz ? (1 - valid[idx]) : 1;
    }
    if (vrow && threadIdx.x==0) vrow[b] = anyz ? 1.f : 0.f;
}

// ---------------- helpers ----------------
__device__ __forceinline__ void mma_f16(float* c, const unsigned* a, const unsigned* b){
    asm volatile("mma.sync.aligned.m16n8k16.row.col.f32.f16.f16.f32 "
        "{%0,%1,%2,%3}, {%4,%5,%6,%7}, {%8,%9}, {%0,%1,%2,%3};"
        : "+f"(c[0]),"+f"(c[1]),"+f"(c[2]),"+f"(c[3])
        : "r"(a[0]),"r"(a[1]),"r"(a[2]),"r"(a[3]), "r"(b[0]),"r"(b[1]));
}
__device__ __forceinline__ unsigned pack_h2(float x, float y){
    __half2 h = __floats2half2_rn(x, y);
    return *(unsigned*)&h;
}
__device__ __forceinline__ unsigned smem_u32(const void* p){
    return (unsigned)__cvta_generic_to_shared(p);
}
__device__ __forceinline__ void cp16(unsigned dst, const void* src){
    asm volatile("cp.async.cg.shared.global [%0], [%1], 16;" :: "r"(dst), "l"(src) : "memory");
}
__device__ __forceinline__ void ldsm4(unsigned* r, unsigned addr){
    asm volatile("ldmatrix.sync.aligned.m8n8.x4.shared.b16 {%0,%1,%2,%3}, [%4];"
        : "=r"(r[0]),"=r"(r[1]),"=r"(r[2]),"=r"(r[3]) : "r"(addr));
}

// ---------------- fp16 cp.async double-buffered NT GEMM (ldmatrix mainloop) ----------------
// A [M,K] fp16 row-major, B [N,K] fp16 row-major. M%128==0, N%128==0, K%32==0.
// epi=0: v=alpha*acc(+bias)(*rowscale)(+residual); store C32/C16
// epi=1 (gate): v=acc+bias; out = residual + sigmoid(v)*aux32
// epi=2 (silu): v=acc+bias; g=aux16; out = silu(g)*v
template<int NWM,int NWN>
__global__ __launch_bounds__(256)
void gemm_h16p(const __half* __restrict__ A, const __half* __restrict__ B,
               float* __restrict__ C32, __half* __restrict__ C16,
               int M,int N,int K,int lda,int ldb,int ldc32,int ldc16,
               float alpha,
               const float* __restrict__ bias,
               const float* __restrict__ residual,int ldres,
               const float* __restrict__ rowscale,int rsDiv,
               int epi, const void* __restrict__ aux, int ldaux)
{
    constexpr int BM=128, BN=128, BK=32, STAGES=2;
    constexpr int WM=BM/NWM, WN=BN/NWN;
    constexpr int MI=WM/16, NI=WN/8;
    constexpr int LDS=BK+8;   // 40 halves per row (80B stride: conflict-free ldmatrix)

    __shared__ __align__(16) __half As[STAGES][BM*LDS];
    __shared__ __align__(16) __half Bs[STAGES][BN*LDS];

    const int tid=threadIdx.x, lane=tid&31, warp=tid>>5;
    const int m0=blockIdx.y*BM, n0=blockIdx.x*BN;
    const int wm0=(warp/NWN)*WM, wn0=(warp%NWN)*WN;
    const int qr=lane>>2, qc=lane&3;
    const int lr=lane&15, koff=(lane>>4)<<3;   // ldmatrix lane addressing

    float acc[MI][NI][4];
    #pragma unroll
    for (int i=0;i<MI;i++)
        #pragma unroll
        for (int j=0;j<NI;j++)
            #pragma unroll
            for (int r=0;r<4;r++) acc[i][j][r]=0.f;

    const int nk = K/BK;

    auto issue = [&](int s, int kt){
        int k0 = kt*BK;
        #pragma unroll
        for (int h2=0; h2<2; ++h2){
            int c = tid + h2*256;
            int r = c>>2, col = c&3;
            cp16(smem_u32(&As[s][r*LDS + col*8]),
                 A + (long long)(m0+r)*lda + k0 + col*8);
            cp16(smem_u32(&Bs[s][r*LDS + col*8]),
                 B + (long long)(n0+r)*ldb + k0 + col*8);
        }
    };

    issue(0, 0);
    asm volatile("cp.async.commit_group;" ::: "memory");

    for (int kt=0; kt<nk; ++kt){
        asm volatile("cp.async.wait_group 0;" ::: "memory");
        __syncthreads();
        if (kt+1 < nk) issue((kt+1)&1, kt+1);
        asm volatile("cp.async.commit_group;" ::: "memory");

        const __half* as = As[kt&1];
        const __half* bs = Bs[kt&1];
        #pragma unroll
        for (int ks=0; ks<BK; ks+=16){
            unsigned af[MI][4], bf[NI][2];
            #pragma unroll
            for (int mi=0; mi<MI; ++mi)
                ldsm4(af[mi], smem_u32(&as[(wm0+mi*16+lr)*LDS + ks + koff]));
            #pragma unroll
            for (int nj=0; nj<NI/2; ++nj){
                unsigned r[4];
                ldsm4(r, smem_u32(&bs[(wn0+nj*16+lr)*LDS + ks + koff]));
                bf[2*nj][0]=r[0]; bf[2*nj+1][0]=r[1];
                bf[2*nj][1]=r[2]; bf[2*nj+1][1]=r[3];
            }
            #pragma unroll
            for (int mi=0; mi<MI; ++mi)
                #pragma unroll
                for (int ni=0; ni<NI; ++ni)
                    mma_f16(acc[mi][ni], af[mi], bf[ni]);
        }
        __syncthreads();
    }

    // epilogue
    #pragma unroll
    for (int mi=0; mi<MI; ++mi){
        #pragma unroll
        for (int hf=0; hf<2; ++hf){
            int gm = m0 + wm0 + mi*16 + qr + hf*8;
            float rs = rowscale ? rowscale[gm/rsDiv] : 1.f;
            #pragma unroll
            for (int ni=0; ni<NI; ++ni){
                int gn = n0 + wn0 + ni*8 + qc*2;
                float v0 = alpha*acc[mi][ni][hf*2+0];
                float v1 = alpha*acc[mi][ni][hf*2+1];
                if (bias){ v0 += bias[gn]; v1 += bias[gn+1]; }
                if (epi==1){
                    const float* upd = (const float*)aux;
                    float2 r = *(const float2*)(residual + (long long)gm*ldres + gn);
                    float2 u = *(const float2*)(upd + (long long)gm*ldaux + gn);
                    v0 = r.x + u.x/(1.f+__expf(-v0));
                    v1 = r.y + u.y/(1.f+__expf(-v1));
                } else if (epi==2){
                    const __half* gh = (const __half*)aux;
                    __half2 gg = *(const __half2*)(gh + (long long)gm*ldaux + gn);
                    float g0 = __low2float(gg), g1 = __high2float(gg);
                    v0 *= g0/(1.f+__expf(-g0));
                    v1 *= g1/(1.f+__expf(-g1));
                } else {
                    v0 *= rs; v1 *= rs;
                    if (residual){
                        float2 r = *(const float2*)(residual + (long long)gm*ldres + gn);
                        v0 += r.x; v1 += r.y;
                    }
                }
                if (C32)
                    *(float2*)(C32 + (long long)gm*ldc32 + gn) = make_float2(v0, v1);
                if (C16)
                    *(__half2*)(C16 + (long long)gm*ldc16 + gn) = __floats2half2_rn(v0, v1);
            }
        }
    }
}

// ---------------- fused flash attention (fp16 in/out, ldmatrix + hoisted Q frags) ----------------
__global__ __launch_bounds__(256)
void flash_attn(const __half* __restrict__ q, const __half* __restrict__ k,
                const __half* __restrict__ v, __half* __restrict__ o,
                const int* __restrict__ valid,
                int ldq, int ldk, int ldv, int ldo,
                int qrows, int krows)
{
    constexpr int BQ = 128, BKT = 64;
    constexpr int LQ = HDc + 8;      // 72 halves (144B stride: conflict-free ldmatrix)
    constexpr int LV = BKT + 8;
    __shared__ __align__(16) __half Qs[BQ*LQ];
    __shared__ __align__(16) __half Ks[BKT*LQ];
    __shared__ __align__(16) __half Vt[HDc*LV];
    __shared__ float  mk[BKT];

    const int z = blockIdx.y;
    const int b = z / Hc, h = z % Hc;
    const __half* qb = q + (long long)b*qrows*ldq + h*HDc;
    const __half* kb = k + (long long)b*krows*ldk + h*HDc;
    const __half* vb = v + (long long)b*krows*ldv + h*HDc;
    __half*       ob = o + (long long)b*qrows*ldo + h*HDc;
    const int*    vl = valid + (long)b*krows;

    const int tid = threadIdx.x, lane = tid & 31, warp = tid >> 5;
    const int qr = lane >> 2, qc = lane & 3;
    const int lr = lane & 15, koff = (lane>>4)<<3;
    const int m0 = blockIdx.x*BQ;
    const int wm = warp*16;
    const __half2 sc2 = __float2half2_rn(0.125f);

    // Q tile, scaled by 1/8
    for (int i = tid; i < BQ*(HDc/8); i += 256){
        int r = i>>3, c8 = i&7;
        uint4 u = *(const uint4*)(qb + (long long)(m0+r)*ldq + c8*8);
        __half2* hp = (__half2*)&u;
        hp[0]=__hmul2(hp[0],sc2); hp[1]=__hmul2(hp[1],sc2);
        hp[2]=__hmul2(hp[2],sc2); hp[3]=__hmul2(hp[3],sc2);
        *(uint4*)&Qs[r*LQ + c8*8] = u;
    }
    __syncthreads();
    // hoist Q fragments (loop-invariant)
    unsigned qf[4][4];
    #pragma unroll
    for (int ks4=0; ks4<4; ++ks4)
        ldsm4(qf[ks4], smem_u32(&Qs[(wm+lr)*LQ + ks4*16 + koff]));

    float mr0 = -3.4e38f, mr1 = -3.4e38f, lr0 = 0.f, lr1 = 0.f;
    float O[8][4];
    #pragma unroll
    for (int i=0;i<8;i++){ O[i][0]=0.f; O[i][1]=0.f; O[i][2]=0.f; O[i][3]=0.f; }

    const int nkt = krows / BKT;
    for (int kt=0; kt<nkt; ++kt){
        __syncthreads();
        for (int i = tid; i < BKT*(HDc/8); i += 256){
            int r = i>>3, c8 = i&7;
            *(uint4*)&Ks[r*LQ + c8*8] =
                *(const uint4*)(kb + (long long)(kt*BKT+r)*ldk + c8*8);
        }
        for (int i = tid; i < BKT*(HDc/8); i += 256){
            int r = i>>3, c8 = i&7;
            uint4 u = *(const uint4*)(vb + (long long)(kt*BKT+r)*ldv + c8*8);
            const __half* hv = (const __half*)&u;
            #pragma unroll
            for (int j=0;j<8;j++) Vt[(c8*8+j)*LV + r] = hv[j];
        }
        if (tid < BKT) mk[tid] = vl[kt*BKT + tid] ? 0.f : -1e30f;
        __syncthreads();

        // S = Q K^T via ldmatrix
        float S[8][4];
        #pragma unroll
        for (int i=0;i<8;i++){ S[i][0]=0.f; S[i][1]=0.f; S[i][2]=0.f; S[i][3]=0.f; }
        #pragma unroll
        for (int ks4=0; ks4<4; ++ks4){
            unsigned kf[8][2];
            #pragma unroll
            for (int nj=0; nj<4; ++nj){
                unsigned r[4];
                ldsm4(r, smem_u32(&Ks[(nj*16+lr)*LQ + ks4*16 + koff]));
                kf[2*nj][0]=r[0]; kf[2*nj+1][0]=r[1];
                kf[2*nj][1]=r[2]; kf[2*nj+1][1]=r[3];
            }
            #pragma unroll
            for (int ni=0; ni<8; ++ni)
                mma_f16(S[ni], qf[ks4], kf[ni]);
        }
        // mask + online softmax
        float mn0 = -3.4e38f, mn1 = -3.4e38f;
        #pragma unroll
        for (int ni=0; ni<8; ++ni){
            float a0 = mk[ni*8 + 2*qc], a1 = mk[ni*8 + 2*qc + 1];
            S[ni][0] += a0; S[ni][1] += a1; S[ni][2] += a0; S[ni][3] += a1;
            mn0 = fmaxf(mn0, fmaxf(S[ni][0], S[ni][1]));
            mn1 = fmaxf(mn1, fmaxf(S[ni][2], S[ni][3]));
        }
        mn0 = fmaxf(mn0, __shfl_xor_sync(0xffffffffu, mn0, 1));
        mn0 = fmaxf(mn0, __shfl_xor_sync(0xffffffffu, mn0, 2));
        mn1 = fmaxf(mn1, __shfl_xor_sync(0xffffffffu, mn1, 1));
        mn1 = fmaxf(mn1, __shfl_xor_sync(0xffffffffu, mn1, 2));
        float mN0 = fmaxf(mr0, mn0), mN1 = fmaxf(mr1, mn1);
        float f0 = __expf(mr0 - mN0), f1 = __expf(mr1 - mN1);
        lr0 *= f0; lr1 *= f1;
        #pragma unroll
        for (int no=0; no<8; ++no){
            O[no][0]*=f0; O[no][1]*=f0; O[no][2]*=f1; O[no][3]*=f1;
        }
        mr0 = mN0; mr1 = mN1;
        unsigned ph[8][2];
        #pragma unroll
        for (int ni=0; ni<8; ++ni){
            float p0 = __expf(S[ni][0]-mr0), p1 = __expf(S[ni][1]-mr0);
            float p2 = __expf(S[ni][2]-mr1), p3 = __expf(S[ni][3]-mr1);
            lr0 += p0+p1; lr1 += p2+p3;
            ph[ni][0] = pack_h2(p0, p1);
            ph[ni][1] = pack_h2(p2, p3);
        }
        // O += P V via ldmatrix on Vt
        #pragma unroll
        for (int st=0; st<4; ++st){
            unsigned af[4] = { ph[2*st][0], ph[2*st][1], ph[2*st+1][0], ph[2*st+1][1] };
            unsigned vf[8][2];
            #pragma unroll
            for (int nj=0; nj<4; ++nj){
                unsigned r[4];
                ldsm4(r, smem_u32(&Vt[(nj*16+lr)*LV + st*16 + koff]));
                vf[2*nj][0]=r[0]; vf[2*nj+1][0]=r[1];
                vf[2*nj][1]=r[2]; vf[2*nj+1][1]=r[3];
            }
            #pragma unroll
            for (int no=0; no<8; ++no)
                mma_f16(O[no], af, vf[no]);
        }
    }

    lr0 += __shfl_xor_sync(0xffffffffu, lr0, 1);
    lr0 += __shfl_xor_sync(0xffffffffu, lr0, 2);
    lr1 += __shfl_xor_sync(0xffffffffu, lr1, 1);
    lr1 += __shfl_xor_sync(0xffffffffu, lr1, 2);
    float i0 = 1.f/lr0, i1 = 1.f/lr1;
    #pragma unroll
    for (int no=0; no<8; ++no){
        int gm0 = m0 + wm + qr, gn = no*8 + 2*qc;
        *(__half2*)(ob + (long long)gm0*ldo + gn)     = __floats2half2_rn(O[no][0]*i0, O[no][1]*i0);
        *(__half2*)(ob + (long long)(gm0+8)*ldo + gn) = __floats2half2_rn(O[no][2]*i1, O[no][3]*i1);
    }
}

// ---------------- small kernels ----------------
__global__ void cvt_f2h(const float* __restrict__ x, __half* __restrict__ y, long n){
    long i = ((long)blockIdx.x*blockDim.x + threadIdx.x)*4;
    if (i >= n) return;
    float4 f = *(const float4*)(x + i);
    *(__half2*)(y+i)   = __floats2half2_rn(f.x, f.y);
    *(__half2*)(y+i+2) = __floats2half2_rn(f.z, f.w);
}

__global__ void film_gemv(const float* __restrict__ mod, const float* __restrict__ W,
                          const float* __restrict__ bias, float* __restrict__ out,
                          int Bn, int N2, int K){
    int warp = (blockIdx.x*blockDim.x + threadIdx.x) >> 5;
    int lane = threadIdx.x & 31;
    if (warp >= Bn*N2) return;
    int b = warp / N2, n = warp % N2;
    const float* a = mod + (long)b*K;
    const float* w = W   + (long)n*K;
    float acc=0.f;
    for (int k=lane; k<K; k+=32) acc = fmaf(a[k], w[k], acc);
    acc = warp_sum(acc);
    if (lane==0) out[warp] = acc + bias[n];
}

__global__ void rmsnorm_h(const float* __restrict__ x, const float* __restrict__ w,
                          __half* __restrict__ y, int Dd,
                          const float* __restrict__ filmss, int S){
    long row = blockIdx.x;
    const float* xr = x + row*Dd;
    float ss = 0.f;
    for (int j = threadIdx.x; j < Dd; j += blockDim.x){ float v = xr[j]; ss = fmaf(v,v,ss); }
    ss = block_sum(ss);
    float r = rsqrtf(ss/(float)Dd + 1e-6f);
    if (filmss){
        int b = (int)(row / S);
        const float* sc = filmss + (long)b*2*Dd;
        for (int j = threadIdx.x; j < Dd; j += blockDim.x){
            float v = xr[j]*r*w[j];
            y[row*Dd + j] = __float2half(v*(1.f + 0.1f*tanhf(sc[j])) + sc[Dd + j]);
        }
    } else {
        for (int j = threadIdx.x; j < Dd; j += blockDim.x)
            y[row*Dd + j] = __float2half(xr[j]*r*w[j]);
    }
}

__global__ void rope_h(__half* __restrict__ qkv){
    long idx = (long)blockIdx.x*blockDim.x + threadIdx.x;
    const long total = (long)BSc * Hc * (HDc/2);
    if (idx >= total) return;
    int i = idx % (HDc/2);
    int h = (idx / (HDc/2)) % Hc;
    long row = idx / ((HDc/2)*Hc);
    int s = (int)(row % Sc);
    float freq = expf(-logf(10000.f) * (float)(2*i) / (float)HDc);
    float ang = (float)s * freq;
    float c = cosf(ang), sn = sinf(ang);
    __half2* qb = (__half2*)(qkv + row*(3*Dc) + h*HDc);
    float2 qv = __half22float2(qb[i]);
    qb[i] = __floats2half2_rn(qv.x*c - qv.y*sn, qv.x*sn + qv.y*c);
    __half2* kb = qb + Dc/2;
    float2 kv = __half22float2(kb[i]);
    kb[i] = __floats2half2_rn(kv.x*c - kv.y*sn, kv.x*sn + kv.y*c);
}

// ---------------- host helper ----------------
static inline void tc(const __half* A,const __half* B,float* C32,__half* C16,
    int M,int N,int K,int lda,int ldb,int ldc32,int ldc16,
    float alpha,const float* bias,const float* res,int ldres,
    const float* rs,int rsdiv,int epi,const void* aux,int ldaux)
{
    dim3 g(N/128, M/128);
    gemm_h16p<2,4><<<g,256>>>(A,B,C32,C16,M,N,K,lda,ldb,ldc32,ldc16,
        alpha,bias,res,ldres,rs,rsdiv,epi,aux,ldaux);
}

extern "C" void kernel_launch(void* const* d_in, const int* in_sizes, int n_in,
                              void* d_out, int out_size)
{
    const float* tokens     = (const float*)d_in[0];
    const float* seq_tokens = (const float*)d_in[1];
    const float* modulation = (const float*)d_in[2];
    const float* attn_norm_w= (const float*)d_in[3];
    const float* qkv_w      = (const float*)d_in[4];
    const float* qkv_b      = (const float*)d_in[5];
    const float* out_w      = (const float*)d_in[6];
    const float* out_b      = (const float*)d_in[7];
    const float* film_w     = (const float*)d_in[8];
    const float* film_b     = (const float*)d_in[9];
    const float* sq_norm_w  = (const float*)d_in[10];
    const float* s_norm_w   = (const float*)d_in[11];
    const float* mha_in_w   = (const float*)d_in[12];
    const float* mha_in_b   = (const float*)d_in[13];
    const float* mha_out_w  = (const float*)d_in[14];
    const float* mha_out_b  = (const float*)d_in[15];
    const float* gate_w     = (const float*)d_in[16];
    const float* gate_b     = (const float*)d_in[17];
    const float* ffn_norm_w = (const float*)d_in[18];
    const float* gu_w       = (const float*)d_in[19];
    const float* gu_b       = (const float*)d_in[20];
    const float* down_w     = (const float*)d_in[21];
    const float* down_b     = (const float*)d_in[22];
    const void*  padding_mask = d_in[23];
    const void*  seq_mask     = d_in[24];
    float* out = (float*)d_out;

    float *p_t2,*p_upd,*p_t3,*p_ss,*p_vrow;
    int *p_valid,*p_svalid;
    __half *p_x,*p_qkv,*p_ctx,*p_qn,*p_sn,*p_cq,*p_ckv,*p_gcat,*p_h,*p_g,*p_act;
    __half *p_qkvw,*p_outw,*p_mhainw,*p_mhaoutw,*p_gatew,*p_guw,*p_downw;
    cudaGetSymbolAddress((void**)&p_t2, g_t2);
    cudaGetSymbolAddress((void**)&p_upd, g_upd);
    cudaGetSymbolAddress((void**)&p_t3, g_t3);
    cudaGetSymbolAddress((void**)&p_ss, g_ss);
    cudaGetSymbolAddress((void**)&p_vrow, g_vrow);
    cudaGetSymbolAddress((void**)&p_valid, g_valid);
    cudaGetSymbolAddress((void**)&p_svalid, g_svalid);
    cudaGetSymbolAddress((void**)&p_x, h_x);
    cudaGetSymbolAddress((void**)&p_qkv, h_qkv);
    cudaGetSymbolAddress((void**)&p_ctx, h_ctx);
    cudaGetSymbolAddress((void**)&p_qn, h_qn);
    cudaGetSymbolAddress((void**)&p_sn, h_sn);
    cudaGetSymbolAddress((void**)&p_cq, h_cq);
    cudaGetSymbolAddress((void**)&p_ckv, h_ckv);
    cudaGetSymbolAddress((void**)&p_gcat, h_gcat);
    cudaGetSymbolAddress((void**)&p_h, h_h);
    cudaGetSymbolAddress((void**)&p_g, h_g);
    cudaGetSymbolAddress((void**)&p_act, h_act);
    cudaGetSymbolAddress((void**)&p_qkvw, h_qkvw);
    cudaGetSymbolAddress((void**)&p_outw, h_outw);
    cudaGetSymbolAddress((void**)&p_mhainw, h_mhainw);
    cudaGetSymbolAddress((void**)&p_mhaoutw, h_mhaoutw);
    cudaGetSymbolAddress((void**)&p_gatew, h_gatew);
    cudaGetSymbolAddress((void**)&p_guw, h_guw);
    cudaGetSymbolAddress((void**)&p_downw, h_downw);

    // 1) masks
    detect_mask_layout<<<(Bc*Sc+255)/256,256>>>((const unsigned char*)padding_mask, Bc*Sc, 0);
    detect_mask_layout<<<(Bc*Lc+255)/256,256>>>((const unsigned char*)seq_mask,     Bc*Lc, 1);
    decode_mask<<<Bc,256>>>(padding_mask, Sc, 0, p_valid,  nullptr);
    decode_mask<<<Bc,256>>>(seq_mask,     Lc, 1, p_svalid, p_vrow);

    // 2) weights -> fp16
    cvt_f2h<<<(3*Dc*Dc/4+255)/256,256>>>(qkv_w,     p_qkvw,    (long)3*Dc*Dc);
    cvt_f2h<<<(Dc*Dc/4+255)/256,256>>>(out_w,       p_outw,    (long)Dc*Dc);
    cvt_f2h<<<(3*Dc*Dc/4+255)/256,256>>>(mha_in_w,  p_mhainw,  (long)3*Dc*Dc);
    cvt_f2h<<<(Dc*Dc/4+255)/256,256>>>(mha_out_w,   p_mhaoutw, (long)Dc*Dc);
    cvt_f2h<<<(Dc*2*Dc/4+255)/256,256>>>(gate_w,    p_gatew,   (long)Dc*2*Dc);
    cvt_f2h<<<((long)2*HIDc*Dc/4+255)/256,256>>>(gu_w, p_guw,  (long)2*HIDc*Dc);
    cvt_f2h<<<((long)Dc*HIDc/4+255)/256,256>>>(down_w, p_downw,(long)Dc*HIDc);

    // 3) FiLM + first norm
    film_gemv<<<(Bc*2*Dc*32 + 255)/256, 256>>>(modulation, film_w, film_b, p_ss, Bc, 2*Dc, Dc);
    rmsnorm_h<<<BSc,256>>>(tokens, attn_norm_w, p_x, Dc, p_ss, Sc);

    // 4) qkv projection
    tc(p_x, p_qkvw, nullptr, p_qkv, BSc, 3*Dc, Dc, Dc, Dc, 0, 3*Dc,
       1.f, qkv_b, nullptr, 0, nullptr, 1, 0, nullptr, 0);

    // 5) RoPE
    rope_h<<<((long)BSc*Hc*(HDc/2) + 255)/256, 256>>>(p_qkv);

    // 6) self attention
    { dim3 g(Sc/128, Bc*Hc);
      flash_attn<<<g,256>>>(p_qkv, p_qkv + Dc, p_qkv + 2*Dc, p_ctx, p_valid,
                            3*Dc, 3*Dc, 3*Dc, Dc, Sc, Sc); }

    // 7) out-proj: t2 (fp32 + fp16 into gcat[:,0:D])
    tc(p_ctx, p_outw, p_t2, p_gcat, BSc, Dc, Dc, Dc, Dc, Dc, 2*Dc,
       1.f, out_b, tokens, Dc, nullptr, 1, 0, nullptr, 0);

    // 8) norms
    rmsnorm_h<<<BSc,256>>>(p_t2, sq_norm_w, p_qn, Dc, nullptr, Sc);
    rmsnorm_h<<<BLc,256>>>(seq_tokens, s_norm_w, p_sn, Dc, nullptr, Lc);

    // 9) cross projections
    tc(p_qn, p_mhainw, nullptr, p_cq, BSc, Dc, Dc, Dc, Dc, 0, Dc,
       1.f, mha_in_b, nullptr, 0, nullptr, 1, 0, nullptr, 0);
    tc(p_sn, p_mhainw + (long long)Dc*Dc, nullptr, p_ckv, BLc, 2*Dc, Dc, Dc, Dc, 0, 2*Dc,
       1.f, mha_in_b + Dc, nullptr, 0, nullptr, 1, 0, nullptr, 0);

    // 10) cross attention
    { dim3 g(Sc/128, Bc*Hc);
      flash_attn<<<g,256>>>(p_cq, p_ckv, p_ckv + Dc, p_ctx, p_svalid,
                            Dc, 2*Dc, 2*Dc, Dc, Sc, Lc); }

    // 11) mha-out: upd (fp32 + fp16 into gcat[:,D:2D])
    tc(p_ctx, p_mhaoutw, p_upd, p_gcat + Dc, BSc, Dc, Dc, Dc, Dc, Dc, 2*Dc,
       1.f, mha_out_b, nullptr, 0, p_vrow, Sc, 0, nullptr, 0);

    // 12) fused gate: t3 = t2 + sigmoid([t2|upd]@gate_w^T + gate_b) * upd
    tc(p_gcat, p_gatew, p_t3, nullptr, BSc, Dc, 2*Dc, 2*Dc, 2*Dc, Dc, 0,
       1.f, gate_b, p_t2, Dc, nullptr, 1, 1, p_upd, Dc);

    // 13) ffn norm
    rmsnorm_h<<<BSc,256>>>(p_t3, ffn_norm_w, p_h, Dc, nullptr, Sc);

    // 14) g = h@gu_w[0:HID]^T + b ; act = silu(g) * (h@gu_w[HID:]^T + b)
    tc(p_h, p_guw, nullptr, p_g, BSc, HIDc, Dc, Dc, Dc, 0, HIDc,
       1.f, gu_b, nullptr, 0, nullptr, 1, 0, nullptr, 0);
    tc(p_h, p_guw + (long long)HIDc*Dc, nullptr, p_act, BSc, HIDc, Dc, Dc, Dc, 0, HIDc,
       1.f, gu_b + HIDc, nullptr, 0, nullptr, 1, 2, p_g, HIDc);

    // 15) out = t3 + act@down_w^T + down_b
    tc(p_act, p_downw, out, nullptr, BSc, Dc, HIDc, HIDc, HIDc, Dc, 0,
       1.f, down_b, p_t3, Dc, nullptr, 1, 0, nullptr, 0);
}

// round 12
// speedup vs baseline: 1.8577x; 1.0013x over previous
#include <cuda_runtime.h>
#include <cuda_bf16.h>
#include <cuda_fp16.h>
#include <math.h>

// Problem constants: B=4, S=1024, L=1024, D=1024, H=16, HD=64, HIDDEN=4096
#define Bc 4
#define Sc 1024
#define Lc 1024
#define Dc 1024
#define Hc 16
#define HDc 64
#define HIDc 4096
#define BSc (Bc*Sc)
#define BLc (Bc*Lc)

// ---------------- scratch (static device globals) ----------------
__device__ float g_t2 [BSc*Dc];
__device__ float g_upd[BSc*Dc];
__device__ float g_t3 [BSc*Dc];
__device__ float g_ss [Bc*2*Dc];
__device__ int   g_valid [BSc];
__device__ int   g_svalid[BLc];
__device__ float g_vrow  [Bc];
__device__ int   g_layout[2];
__device__ __half h_x   [BSc*Dc];
__device__ __half h_qkv [BSc*3*Dc];
__device__ __half h_ctx [BSc*Dc];
__device__ __half h_qn  [BSc*Dc];
__device__ __half h_sn  [BLc*Dc];
__device__ __half h_cq  [BSc*Dc];
__device__ __half h_ckv [BLc*2*Dc];
__device__ __half h_gcat[BSc*2*Dc];
__device__ __half h_h   [BSc*Dc];
__device__ __half h_g   [(size_t)BSc*HIDc];
__device__ __half h_act [(size_t)BSc*HIDc];
__device__ __half h_qkvw  [3*Dc*Dc];
__device__ __half h_outw  [Dc*Dc];
__device__ __half h_mhainw[3*Dc*Dc];
__device__ __half h_mhaoutw[Dc*Dc];
__device__ __half h_gatew [Dc*2*Dc];
__device__ __half h_guw   [2*HIDc*Dc];
__device__ __half h_downw [Dc*HIDc];

// ---------------- reductions ----------------
__device__ __forceinline__ float warp_sum(float v){
    #pragma unroll
    for (int o=16;o>0;o>>=1) v += __shfl_xor_sync(0xffffffffu, v, o);
    return v;
}
__device__ float block_sum(float v){
    __shared__ float red[33];
    __syncthreads();
    int lane = threadIdx.x & 31, wid = threadIdx.x >> 5;
    v = warp_sum(v);
    if (lane==0) red[wid] = v;
    __syncthreads();
    int nw = blockDim.x >> 5;
    float r = (threadIdx.x < nw) ? red[threadIdx.x] : 0.f;
    if (wid==0){ r = warp_sum(r); if (lane==0) red[32] = r; }
    __syncthreads();
    return red[32];
}

// ---------------- mask layout detection + decode ----------------
__global__ void detect_mask_layout(const unsigned char* __restrict__ p, int n, int slot){
    int i = blockIdx.x*blockDim.x + threadIdx.x;
    if (i >= n) return;
    unsigned char v = p[i];
    if (v != 0 && v != 1) atomicOr(&g_layout[slot], 2);
    else if (v == 1 && (i & 3) != 0) atomicOr(&g_layout[slot], 1);
}
__global__ void decode_mask(const void* __restrict__ p, int cols, int slot,
                            int* __restrict__ valid, float* __restrict__ vrow){
    int b = blockIdx.x;
    int layout = g_layout[slot];
    int mode = (layout & 2) ? 2 : ((layout & 1) ? 1 : 0);
    __shared__ int s_anyzero;
    if (threadIdx.x==0) s_anyzero = 0;
    __syncthreads();
    int local_any = 0;
    for (int j = threadIdx.x; j < cols; j += blockDim.x){
        long idx = (long)b*cols + j;
        int m;
        if (mode==1)      m = ((const unsigned char*)p)[idx] != 0;
        else if (mode==2) m = ((const float*)p)[idx] != 0.f;
        else              m = ((const int*)p)[idx] != 0;
        valid[idx] = m;
        if (!m) local_any = 1;
    }
    if (local_any) atomicOr(&s_anyzero, 1);
    __syncthreads();
    int anyz = s_anyzero;
    for (int j = threadIdx.x; j < cols; j += blockDim.x){
        long idx = (long)b*cols + j;
        valid[idx] = anyz ? (1 - valid[idx]) : 1;
    }
    if (vrow && threadIdx.x==0) vrow[b] = anyz ? 1.f : 0.f;
}

// ---------------- helpers ----------------
__device__ __forceinline__ void mma_f16(float* c, const unsigned* a, const unsigned* b){
    asm volatile("mma.sync.aligned.m16n8k16.row.col.f32.f16.f16.f32 "
        "{%0,%1,%2,%3}, {%4,%5,%6,%7}, {%8,%9}, {%0,%1,%2,%3};"
        : "+f"(c[0]),"+f"(c[1]),"+f"(c[2]),"+f"(c[3])
        : "r"(a[0]),"r"(a[1]),"r"(a[2]),"r"(a[3]), "r"(b[0]),"r"(b[1]));
}
__device__ __forceinline__ unsigned pack_h2(float x, float y){
    __half2 h = __floats2half2_rn(x, y);
    return *(unsigned*)&h;
}
__device__ __forceinline__ unsigned smem_u32(const void* p){
    return (unsigned)__cvta_generic_to_shared(p);
}
__device__ __forceinline__ void cp16(unsigned dst, const void* src){
    asm volatile("cp.async.cg.shared.global [%0], [%1], 16;" :: "r"(dst), "l"(src) : "memory");
}
__device__ __forceinline__ void ldsm4(unsigned* r, unsigned addr){
    asm volatile("ldmatrix.sync.aligned.m8n8.x4.shared.b16 {%0,%1,%2,%3}, [%4];"
        : "=r"(r[0]),"=r"(r[1]),"=r"(r[2]),"=r"(r[3]) : "r"(addr));
}

// ---------------- fp16 cp.async double-buffered NT GEMM (ldmatrix mainloop) ----------------
// A [M,K] fp16 row-major, B [N,K] fp16 row-major. M%128==0, N%128==0, K%32==0.
// epi=0: v=alpha*acc(+bias)(*rowscale)(+residual); store C32/C16
// epi=1 (gate): v=acc+bias; out = residual + sigmoid(v)*aux32
// epi=2 (silu): v=acc+bias; g=aux16; out = silu(g)*v
template<int NWM,int NWN>
__global__ __launch_bounds__(256)
void gemm_h16p(const __half* __restrict__ A, const __half* __restrict__ B,
               float* __restrict__ C32, __half* __restrict__ C16,
               int M,int N,int K,int lda,int ldb,int ldc32,int ldc16,
               float alpha,
               const float* __restrict__ bias,
               const float* __restrict__ residual,int ldres,
               const float* __restrict__ rowscale,int rsDiv,
               int epi, const void* __restrict__ aux, int ldaux)
{
    constexpr int BM=128, BN=128, BK=32, STAGES=2;
    constexpr int WM=BM/NWM, WN=BN/NWN;
    constexpr int MI=WM/16, NI=WN/8;
    constexpr int LDS=BK+8;   // 40 halves per row (80B stride: conflict-free ldmatrix)

    __shared__ __align__(16) __half As[STAGES][BM*LDS];
    __shared__ __align__(16) __half Bs[STAGES][BN*LDS];

    const int tid=threadIdx.x, lane=tid&31, warp=tid>>5;
    const int m0=blockIdx.y*BM, n0=blockIdx.x*BN;
    const int wm0=(warp/NWN)*WM, wn0=(warp%NWN)*WN;
    const int qr=lane>>2, qc=lane&3;
    const int lr=lane&15, koff=(lane>>4)<<3;   // ldmatrix lane addressing

    float acc[MI][NI][4];
    #pragma unroll
    for (int i=0;i<MI;i++)
        #pragma unroll
        for (int j=0;j<NI;j++)
            #pragma unroll
            for (int r=0;r<4;r++) acc[i][j][r]=0.f;

    const int nk = K/BK;

    auto issue = [&](int s, int kt){
        int k0 = kt*BK;
        #pragma unroll
        for (int h2=0; h2<2; ++h2){
            int c = tid + h2*256;
            int r = c>>2, col = c&3;
            cp16(smem_u32(&As[s][r*LDS + col*8]),
                 A + (long long)(m0+r)*lda + k0 + col*8);
            cp16(smem_u32(&Bs[s][r*LDS + col*8]),
                 B + (long long)(n0+r)*ldb + k0 + col*8);
        }
    };

    issue(0, 0);
    asm volatile("cp.async.commit_group;" ::: "memory");

    for (int kt=0; kt<nk; ++kt){
        asm volatile("cp.async.wait_group 0;" ::: "memory");
        __syncthreads();
        if (kt+1 < nk) issue((kt+1)&1, kt+1);
        asm volatile("cp.async.commit_group;" ::: "memory");

        const __half* as = As[kt&1];
        const __half* bs = Bs[kt&1];
        #pragma unroll
        for (int ks=0; ks<BK; ks+=16){
            unsigned af[MI][4], bf[NI][2];
            #pragma unroll
            for (int mi=0; mi<MI; ++mi)
                ldsm4(af[mi], smem_u32(&as[(wm0+mi*16+lr)*LDS + ks + koff]));
            #pragma unroll
            for (int nj=0; nj<NI/2; ++nj){
                unsigned r[4];
                ldsm4(r, smem_u32(&bs[(wn0+nj*16+lr)*LDS + ks + koff]));
                bf[2*nj][0]=r[0]; bf[2*nj+1][0]=r[1];
                bf[2*nj][1]=r[2]; bf[2*nj+1][1]=r[3];
            }
            #pragma unroll
            for (int mi=0; mi<MI; ++mi)
                #pragma unroll
                for (int ni=0; ni<NI; ++ni)
                    mma_f16(acc[mi][ni], af[mi], bf[ni]);
        }
        __syncthreads();
    }

    // epilogue
    #pragma unroll
    for (int mi=0; mi<MI; ++mi){
        #pragma unroll
        for (int hf=0; hf<2; ++hf){
            int gm = m0 + wm0 + mi*16 + qr + hf*8;
            float rs = rowscale ? rowscale[gm/rsDiv] : 1.f;
            #pragma unroll
            for (int ni=0; ni<NI; ++ni){
                int gn = n0 + wn0 + ni*8 + qc*2;
                float v0 = alpha*acc[mi][ni][hf*2+0];
                float v1 = alpha*acc[mi][ni][hf*2+1];
                if (bias){ v0 += bias[gn]; v1 += bias[gn+1]; }
                if (epi==1){
                    const float* upd = (const float*)aux;
                    float2 r = *(const float2*)(residual + (long long)gm*ldres + gn);
                    float2 u = *(const float2*)(upd + (long long)gm*ldaux + gn);
                    v0 = r.x + u.x/(1.f+__expf(-v0));
                    v1 = r.y + u.y/(1.f+__expf(-v1));
                } else if (epi==2){
                    const __half* gh = (const __half*)aux;
                    __half2 gg = *(const __half2*)(gh + (long long)gm*ldaux + gn);
                    float g0 = __low2float(gg), g1 = __high2float(gg);
                    v0 *= g0/(1.f+__expf(-g0));
                    v1 *= g1/(1.f+__expf(-g1));
                } else {
                    v0 *= rs; v1 *= rs;
                    if (residual){
                        float2 r = *(const float2*)(residual + (long long)gm*ldres + gn);
                        v0 += r.x; v1 += r.y;
                    }
                }
                if (C32)
                    *(float2*)(C32 + (long long)gm*ldc32 + gn) = make_float2(v0, v1);
                if (C16)
                    *(__half2*)(C16 + (long long)gm*ldc16 + gn) = __floats2half2_rn(v0, v1);
            }
        }
    }
}

// ---------------- fused flash attention (fp16 in/out, ldmatrix + hoisted Q frags) ----------------
__global__ __launch_bounds__(256)
void flash_attn(const __half* __restrict__ q, const __half* __restrict__ k,
                const __half* __restrict__ v, __half* __restrict__ o,
                const int* __restrict__ valid,
                int ldq, int ldk, int ldv, int ldo,
                int qrows, int krows)
{
    constexpr int BQ = 128, BKT = 64;
    constexpr int LQ = HDc + 8;      // 72 halves (144B stride: conflict-free ldmatrix)
    constexpr int LV = BKT + 8;
    __shared__ __align__(16) __half Qs[BQ*LQ];
    __shared__ __align__(16) __half Ks[BKT*LQ];
    __shared__ __align__(16) __half Vt[HDc*LV];
    __shared__ float  mk[BKT];

    const int z = blockIdx.y;
    const int b = z / Hc, h = z % Hc;
    const __half* qb = q + (long long)b*qrows*ldq + h*HDc;
    const __half* kb = k + (long long)b*krows*ldk + h*HDc;
    const __half* vb = v + (long long)b*krows*ldv + h*HDc;
    __half*       ob = o + (long long)b*qrows*ldo + h*HDc;
    const int*    vl = valid + (long)b*krows;

    const int tid = threadIdx.x, lane = tid & 31, warp = tid >> 5;
    const int qr = lane >> 2, qc = lane & 3;
    const int lr = lane & 15, koff = (lane>>4)<<3;
    const int m0 = blockIdx.x*BQ;
    const int wm = warp*16;
    const __half2 sc2 = __float2half2_rn(0.125f);

    // Q tile, scaled by 1/8
    for (int i = tid; i < BQ*(HDc/8); i += 256){
        int r = i>>3, c8 = i&7;
        uint4 u = *(const uint4*)(qb + (long long)(m0+r)*ldq + c8*8);
        __half2* hp = (__half2*)&u;
        hp[0]=__hmul2(hp[0],sc2); hp[1]=__hmul2(hp[1],sc2);
        hp[2]=__hmul2(hp[2],sc2); hp[3]=__hmul2(hp[3],sc2);
        *(uint4*)&Qs[r*LQ + c8*8] = u;
    }
    __syncthreads();
    // hoist Q fragments (loop-invariant)
    unsigned qf[4][4];
    #pragma unroll
    for (int ks4=0; ks4<4; ++ks4)
        ldsm4(qf[ks4], smem_u32(&Qs[(wm+lr)*LQ + ks4*16 + koff]));

    float mr0 = -3.4e38f, mr1 = -3.4e38f, lr0 = 0.f, lr1 = 0.f;
    float O[8][4];
    #pragma unroll
    for (int i=0;i<8;i++){ O[i][0]=0.f; O[i][1]=0.f; O[i][2]=0.f; O[i][3]=0.f; }

    const int nkt = krows / BKT;
    for (int kt=0; kt<nkt; ++kt){
        __syncthreads();
        for (int i = tid; i < BKT*(HDc/8); i += 256){
            int r = i>>3, c8 = i&7;
            *(uint4*)&Ks[r*LQ + c8*8] =
                *(const uint4*)(kb + (long long)(kt*BKT+r)*ldk + c8*8);
        }
        for (int i = tid; i < BKT*(HDc/8); i += 256){
            int r = i>>3, c8 = i&7;
            uint4 u = *(const uint4*)(vb + (long long)(kt*BKT+r)*ldv + c8*8);
            const __half* hv = (const __half*)&u;
            #pragma unroll
            for (int j=0;j<8;j++) Vt[(c8*8+j)*LV + r] = hv[j];
        }
        if (tid < BKT) mk[tid] = vl[kt*BKT + tid] ? 0.f : -1e30f;
        __syncthreads();

        // S = Q K^T via ldmatrix
        float S[8][4];
        #pragma unroll
        for (int i=0;i<8;i++){ S[i][0]=0.f; S[i][1]=0.f; S[i][2]=0.f; S[i][3]=0.f; }
        #pragma unroll
        for (int ks4=0; ks4<4; ++ks4){
            unsigned kf[8][2];
            #pragma unroll
            for (int nj=0; nj<4; ++nj){
                unsigned r[4];
                ldsm4(r, smem_u32(&Ks[(nj*16+lr)*LQ + ks4*16 + koff]));
                kf[2*nj][0]=r[0]; kf[2*nj+1][0]=r[1];
                kf[2*nj][1]=r[2]; kf[2*nj+1][1]=r[3];
            }
            #pragma unroll
            for (int ni=0; ni<8; ++ni)
                mma_f16(S[ni], qf[ks4], kf[ni]);
        }
        // mask + online softmax
        float mn0 = -3.4e38f, mn1 = -3.4e38f;
        #pragma unroll
        for (int ni=0; ni<8; ++ni){
            float a0 = mk[ni*8 + 2*qc], a1 = mk[ni*8 + 2*qc + 1];
            S[ni][0] += a0; S[ni][1] += a1; S[ni][2] += a0; S[ni][3] += a1;
            mn0 = fmaxf(mn0, fmaxf(S[ni][0], S[ni][1]));
            mn1 = fmaxf(mn1, fmaxf(S[ni][2], S[ni][3]));
        }
        mn0 = fmaxf(mn0, __shfl_xor_sync(0xffffffffu, mn0, 1));
        mn0 = fmaxf(mn0, __shfl_xor_sync(0xffffffffu, mn0, 2));
        mn1 = fmaxf(mn1, __shfl_xor_sync(0xffffffffu, mn1, 1));
        mn1 = fmaxf(mn1, __shfl_xor_sync(0xffffffffu, mn1, 2));
        float mN0 = fmaxf(mr0, mn0), mN1 = fmaxf(mr1, mn1);
        float f0 = __expf(mr0 - mN0), f1 = __expf(mr1 - mN1);
        lr0 *= f0; lr1 *= f1;
        #pragma unroll
        for (int no=0; no<8; ++no){
            O[no][0]*=f0; O[no][1]*=f0; O[no][2]*=f1; O[no][3]*=f1;
        }
        mr0 = mN0; mr1 = mN1;
        unsigned ph[8][2];
        #pragma unroll
        for (int ni=0; ni<8; ++ni){
            float p0 = __expf(S[ni][0]-mr0), p1 = __expf(S[ni][1]-mr0);
            float p2 = __expf(S[ni][2]-mr1), p3 = __expf(S[ni][3]-mr1);
            lr0 += p0+p1; lr1 += p2+p3;
            ph[ni][0] = pack_h2(p0, p1);
            ph[ni][1] = pack_h2(p2, p3);
        }
        // O += P V via ldmatrix on Vt
        #pragma unroll
        for (int st=0; st<4; ++st){
            unsigned af[4] = { ph[2*st][0], ph[2*st][1], ph[2*st+1][0], ph[2*st+1][1] };
            unsigned vf[8][2];
            #pragma unroll
            for (int nj=0; nj<4; ++nj){
                unsigned r[4];
                ldsm4(r, smem_u32(&Vt[(nj*16+lr)*LV + st*16 + koff]));
                vf[2*nj][0]=r[0]; vf[2*nj+1][0]=r[1];
                vf[2*nj][1]=r[2]; vf[2*nj+1][1]=r[3];
            }
            #pragma unroll
            for (int no=0; no<8; ++no)
                mma_f16(O[no], af, vf[no]);
        }
    }

    lr0 += __shfl_xor_sync(0xffffffffu, lr0, 1);
    lr0 += __shfl_xor_sync(0xffffffffu, lr0, 2);
    lr1 += __shfl_xor_sync(0xffffffffu, lr1, 1);
    lr1 += __shfl_xor_sync(0xffffffffu, lr1, 2);
    float i0 = 1.f/lr0, i1 = 1.f/lr1;
    #pragma unroll
    for (int no=0; no<8; ++no){
        int gm0 = m0 + wm + qr, gn = no*8 + 2*qc;
        *(__half2*)(ob + (long long)gm0*ldo + gn)     = __floats2half2_rn(O[no][0]*i0, O[no][1]*i0);
        *(__half2*)(ob + (long long)(gm0+8)*ldo + gn) = __floats2half2_rn(O[no][2]*i1, O[no][3]*i1);
    }
}

// ---------------- small kernels ----------------
__global__ void cvt_f2h(const float* __restrict__ x, __half* __restrict__ y, long n){
    long i = ((long)blockIdx.x*blockDim.x + threadIdx.x)*4;
    if (i >= n) return;
    float4 f = *(const float4*)(x + i);
    *(__half2*)(y+i)   = __floats2half2_rn(f.x, f.y);
    *(__half2*)(y+i+2) = __floats2half2_rn(f.z, f.w);
}

__global__ void film_gemv(const float* __restrict__ mod, const float* __restrict__ W,
                          const float* __restrict__ bias, float* __restrict__ out,
                          int Bn, int N2, int K){
    int warp = (blockIdx.x*blockDim.x + threadIdx.x) >> 5;
    int lane = threadIdx.x & 31;
    if (warp >= Bn*N2) return;
    int b = warp / N2, n = warp % N2;
    const float* a = mod + (long)b*K;
    const float* w = W   + (long)n*K;
    float acc=0.f;
    for (int k=lane; k<K; k+=32) acc = fmaf(a[k], w[k], acc);
    acc = warp_sum(acc);
    if (lane==0) out[warp] = acc + bias[n];
}

__global__ void rmsnorm_h(const float* __restrict__ x, const float* __restrict__ w,
                          __half* __restrict__ y, int Dd,
                          const float* __restrict__ filmss, int S){
    long row = blockIdx.x;
    const float* xr = x + row*Dd;
    float ss = 0.f;
    for (int j = threadIdx.x; j < Dd; j += blockDim.x){ float v = xr[j]; ss = fmaf(v,v,ss); }
    ss = block_sum(ss);
    float r = rsqrtf(ss/(float)Dd + 1e-6f);
    if (filmss){
        int b = (int)(row / S);
        const float* sc = filmss + (long)b*2*Dd;
        for (int j = threadIdx.x; j < Dd; j += blockDim.x){
            float v = xr[j]*r*w[j];
            y[row*Dd + j] = __float2half(v*(1.f + 0.1f*tanhf(sc[j])) + sc[Dd + j]);
        }
    } else {
        for (int j = threadIdx.x; j < Dd; j += blockDim.x)
            y[row*Dd + j] = __float2half(xr[j]*r*w[j]);
    }
}

__global__ void rope_h(__half* __restrict__ qkv){
    long idx = (long)blockIdx.x*blockDim.x + threadIdx.x;
    const long total = (long)BSc * Hc * (HDc/2);
    if (idx >= total) return;
    int i = idx % (HDc/2);
    int h = (idx / (HDc/2)) % Hc;
    long row = idx / ((HDc/2)*Hc);
    int s = (int)(row % Sc);
    float freq = expf(-logf(10000.f) * (float)(2*i) / (float)HDc);
    float ang = (float)s * freq;
    float c = cosf(ang), sn = sinf(ang);
    __half2* qb = (__half2*)(qkv + row*(3*Dc) + h*HDc);
    float2 qv = __half22float2(qb[i]);
    qb[i] = __floats2half2_rn(qv.x*c - qv.y*sn, qv.x*sn + qv.y*c);
    __half2* kb = qb + Dc/2;
    float2 kv = __half22float2(kb[i]);
    kb[i] = __floats2half2_rn(kv.x*c - kv.y*sn, kv.x*sn + kv.y*c);
}

// ---------------- host helper ----------------
static inline void tc(const __half* A,const __half* B,float* C32,__half* C16,
    int M,int N,int K,int lda,int ldb,int ldc32,int ldc16,
    float alpha,const float* bias,const float* res,int ldres,
    const float* rs,int rsdiv,int epi,const void* aux,int ldaux)
{
    dim3 g(N/128, M/128);
    gemm_h16p<2,4><<<g,256>>>(A,B,C32,C16,M,N,K,lda,ldb,ldc32,ldc16,
        alpha,bias,res,ldres,rs,rsdiv,epi,aux,ldaux);
}

extern "C" void kernel_launch(void* const* d_in, const int* in_sizes, int n_in,
                              void* d_out, int out_size)
{
    const float* tokens     = (const float*)d_in[0];
    const float* seq_tokens = (const float*)d_in[1];
    const float* modulation = (const float*)d_in[2];
    const float* attn_norm_w= (const float*)d_in[3];
    const float* qkv_w      = (const float*)d_in[4];
    const float* qkv_b      = (const float*)d_in[5];
    const float* out_w      = (const float*)d_in[6];
    const float* out_b      = (const float*)d_in[7];
    const float* film_w     = (const float*)d_in[8];
    const float* film_b     = (const float*)d_in[9];
    const float* sq_norm_w  = (const float*)d_in[10];
    const float* s_norm_w   = (const float*)d_in[11];
    const float* mha_in_w   = (const float*)d_in[12];
    const float* mha_in_b   = (const float*)d_in[13];
    const float* mha_out_w  = (const float*)d_in[14];
    const float* mha_out_b  = (const float*)d_in[15];
    const float* gate_w     = (const float*)d_in[16];
    const float* gate_b     = (const float*)d_in[17];
    const float* ffn_norm_w = (const float*)d_in[18];
    const float* gu_w       = (const float*)d_in[19];
    const float* gu_b       = (const float*)d_in[20];
    const float* down_w     = (const float*)d_in[21];
    const float* down_b     = (const float*)d_in[22];
    const void*  padding_mask = d_in[23];
    const void*  seq_mask     = d_in[24];
    float* out = (float*)d_out;

    float *p_t2,*p_upd,*p_t3,*p_ss,*p_vrow;
    int *p_valid,*p_svalid;
    __half *p_x,*p_qkv,*p_ctx,*p_qn,*p_sn,*p_cq,*p_ckv,*p_gcat,*p_h,*p_g,*p_act;
    __half *p_qkvw,*p_outw,*p_mhainw,*p_mhaoutw,*p_gatew,*p_guw,*p_downw;
    cudaGetSymbolAddress((void**)&p_t2, g_t2);
    cudaGetSymbolAddress((void**)&p_upd, g_upd);
    cudaGetSymbolAddress((void**)&p_t3, g_t3);
    cudaGetSymbolAddress((void**)&p_ss, g_ss);
    cudaGetSymbolAddress((void**)&p_vrow, g_vrow);
    cudaGetSymbolAddress((void**)&p_valid, g_valid);
    cudaGetSymbolAddress((void**)&p_svalid, g_svalid);
    cudaGetSymbolAddress((void**)&p_x, h_x);
    cudaGetSymbolAddress((void**)&p_qkv, h_qkv);
    cudaGetSymbolAddress((void**)&p_ctx, h_ctx);
    cudaGetSymbolAddress((void**)&p_qn, h_qn);
    cudaGetSymbolAddress((void**)&p_sn, h_sn);
    cudaGetSymbolAddress((void**)&p_cq, h_cq);
    cudaGetSymbolAddress((void**)&p_ckv, h_ckv);
    cudaGetSymbolAddress((void**)&p_gcat, h_gcat);
    cudaGetSymbolAddress((void**)&p_h, h_h);
    cudaGetSymbolAddress((void**)&p_g, h_g);
    cudaGetSymbolAddress((void**)&p_act, h_act);
    cudaGetSymbolAddress((void**)&p_qkvw, h_qkvw);
    cudaGetSymbolAddress((void**)&p_outw, h_outw);
    cudaGetSymbolAddress((void**)&p_mhainw, h_mhainw);
    cudaGetSymbolAddress((void**)&p_mhaoutw, h_mhaoutw);
    cudaGetSymbolAddress((void**)&p_gatew, h_gatew);
    cudaGetSymbolAddress((void**)&p_guw, h_guw);
    cudaGetSymbolAddress((void**)&p_downw, h_downw);

    // 1) masks
    detect_mask_layout<<<(Bc*Sc+255)/256,256>>>((const unsigned char*)padding_mask, Bc*Sc, 0);
    detect_mask_layout<<<(Bc*Lc+255)/256,256>>>((const unsigned char*)seq_mask,     Bc*Lc, 1);
    decode_mask<<<Bc,256>>>(padding_mask, Sc, 0, p_valid,  nullptr);
    decode_mask<<<Bc,256>>>(seq_mask,     Lc, 1, p_svalid, p_vrow);

    // 2) weights -> fp16
    cvt_f2h<<<(3*Dc*Dc/4+255)/256,256>>>(qkv_w,     p_qkvw,    (long)3*Dc*Dc);
    cvt_f2h<<<(Dc*Dc/4+255)/256,256>>>(out_w,       p_outw,    (long)Dc*Dc);
    cvt_f2h<<<(3*Dc*Dc/4+255)/256,256>>>(mha_in_w,  p_mhainw,  (long)3*Dc*Dc);
    cvt_f2h<<<(Dc*Dc/4+255)/256,256>>>(mha_out_w,   p_mhaoutw, (long)Dc*Dc);
    cvt_f2h<<<(Dc*2*Dc/4+255)/256,256>>>(gate_w,    p_gatew,   (long)Dc*2*Dc);
    cvt_f2h<<<((long)2*HIDc*Dc/4+255)/256,256>>>(gu_w, p_guw,  (long)2*HIDc*Dc);
    cvt_f2h<<<((long)Dc*HIDc/4+255)/256,256>>>(down_w, p_downw,(long)Dc*HIDc);

    // 3) FiLM + first norm
    film_gemv<<<(Bc*2*Dc*32 + 255)/256, 256>>>(modulation, film_w, film_b, p_ss, Bc, 2*Dc, Dc);
    rmsnorm_h<<<BSc,256>>>(tokens, attn_norm_w, p_x, Dc, p_ss, Sc);

    // 4) qkv projection
    tc(p_x, p_qkvw, nullptr, p_qkv, BSc, 3*Dc, Dc, Dc, Dc, 0, 3*Dc,
       1.f, qkv_b, nullptr, 0, nullptr, 1, 0, nullptr, 0);

    // 5) RoPE
    rope_h<<<((long)BSc*Hc*(HDc/2) + 255)/256, 256>>>(p_qkv);

    // 6) self attention
    { dim3 g(Sc/128, Bc*Hc);
      flash_attn<<<g,256>>>(p_qkv, p_qkv + Dc, p_qkv + 2*Dc, p_ctx, p_valid,
                            3*Dc, 3*Dc, 3*Dc, Dc, Sc, Sc); }

    // 7) out-proj: t2 (fp32 + fp16 into gcat[:,0:D])
    tc(p_ctx, p_outw, p_t2, p_gcat, BSc, Dc, Dc, Dc, Dc, Dc, 2*Dc,
       1.f, out_b, tokens, Dc, nullptr, 1, 0, nullptr, 0);

    // 8) norms
    rmsnorm_h<<<BSc,256>>>(p_t2, sq_norm_w, p_qn, Dc, nullptr, Sc);
    rmsnorm_h<<<BLc,256>>>(seq_tokens, s_norm_w, p_sn, Dc, nullptr, Lc);

    // 9) cross projections
    tc(p_qn, p_mhainw, nullptr, p_cq, BSc, Dc, Dc, Dc, Dc, 0, Dc,
       1.f, mha_in_b, nullptr, 0, nullptr, 1, 0, nullptr, 0);
    tc(p_sn, p_mhainw + (long long)Dc*Dc, nullptr, p_ckv, BLc, 2*Dc, Dc, Dc, Dc, 0, 2*Dc,
       1.f, mha_in_b + Dc, nullptr, 0, nullptr, 1, 0, nullptr, 0);

    // 10) cross attention
    { dim3 g(Sc/128, Bc*Hc);
      flash_attn<<<g,256>>>(p_cq, p_ckv, p_ckv + Dc, p_ctx, p_svalid,
                            Dc, 2*Dc, 2*Dc, Dc, Sc, Lc); }

    // 11) mha-out: upd (fp32 + fp16 into gcat[:,D:2D])
    tc(p_ctx, p_mhaoutw, p_upd, p_gcat + Dc, BSc, Dc, Dc, Dc, Dc, Dc, 2*Dc,
       1.f, mha_out_b, nullptr, 0, p_vrow, Sc, 0, nullptr, 0);

    // 12) fused gate: t3 = t2 + sigmoid([t2|upd]@gate_w^T + gate_b) * upd
    tc(p_gcat, p_gatew, p_t3, nullptr, BSc, Dc, 2*Dc, 2*Dc, 2*Dc, Dc, 0,
       1.f, gate_b, p_t2, Dc, nullptr, 1, 1, p_upd, Dc);

    // 13) ffn norm
    rmsnorm_h<<<BSc,256>>>(p_t3, ffn_norm_w, p_h, Dc, nullptr, Sc);

    // 14) g = h@gu_w[0:HID]^T + b ; act = silu(g) * (h@gu_w[HID:]^T + b)
    tc(p_h, p_guw, nullptr, p_g, BSc, HIDc, Dc, Dc, Dc, 0, HIDc,
       1.f, gu_b, nullptr, 0, nullptr, 1, 0, nullptr, 0);
    tc(p_h, p_guw + (long long)HIDc*Dc, nullptr, p_act, BSc, HIDc, Dc, Dc, Dc, 0, HIDc,
       1.f, gu_b + HIDc, nullptr, 0, nullptr, 1, 2, p_g, HIDc);

    // 15) out = t3 + act@down_w^T + down_b
    tc(p_act, p_downw, out, nullptr, BSc, Dc, HIDc, HIDc, HIDc, Dc, 0,
       1.f, down_b, p_t3, Dc, nullptr, 1, 0, nullptr, 0);
}